// round 8
// baseline (speedup 1.0000x reference)
#include <cuda_runtime.h>
#include <cuda_bf16.h>
#include <math.h>

#define TT 64
#define BB 256
#define EMBD 1024
#define ADIM 6
#define STOCHD 64
#define HIDD 512
#define FEATD 512
#define STATED 576
#define TBD (TT*BB)
#define NBLK 128
#define LOG2PI_F 1.837877066409345483560659472811f

typedef __nv_bfloat16 bf16;

// ---------------- scratch ----------------
__device__ float g_carryA[BB*STATED];   // [s(64)|h(512)]
__device__ float g_carryB[BB*STATED];
__device__ float g_zeroc[BB*STATED];
__device__ float g_y1[BB*FEATD];
__device__ float g_y2[BB*FEATD];
__device__ float g_qmu[TBD*STOCHD];
__device__ float g_qstd[TBD*STOCHD];
__device__ float g_P[TBD*1536];
__device__ float g_PE[TBD*FEATD];
__device__ float g_E[TBD*EMBD];
__device__ float g_praw[TBD*2*STOCHD];
__device__ float g_e0[EMBD];
__device__ float g_e0l1[FEATD];
__device__ float g_b2p[128];
__device__ double g_acc[3];
__device__ unsigned g_bcount = 0;
__device__ unsigned g_bgen = 0;

__device__ bf16 g_states_bf[TBD*STATED];
__device__ bf16 g_emb_bf[TBD*EMBD];
__device__ bf16 g_E_bf[TBD*EMBD];
__device__ bf16 g_pcat_bf[TBD*1536];
__device__ bf16 g_big1_bf[TBD*FEATD];
__device__ bf16 g_big2_bf[TBD*FEATD];
__device__ bf16 g_e0_bf[EMBD];
__device__ bf16 g_stW0b[512*1536];
__device__ bf16 g_stW1b[512*512];
__device__ bf16 g_stW2b[128*512];
__device__ bf16 g_epW0b[512*576];
__device__ bf16 g_epW1b[512*512];
__device__ bf16 g_epW2b[1024*512];
__device__ bf16 g_rpW0b[512*576];
__device__ bf16 g_rpW1b[512*512];
// split hi/lo weights for the sequential path
__device__ bf16 g_WGh[2048*576];
__device__ bf16 g_WGl[2048*576];
__device__ bf16 g_W0hh[512*512];
__device__ bf16 g_W0hl[512*512];
__device__ bf16 g_W1h[512*512];
__device__ bf16 g_W1l[512*512];
__device__ bf16 g_W2h[128*512];
__device__ bf16 g_W2l[128*512];

// ---------------- math ----------------
__device__ __forceinline__ float softplusf(float x) {
    return fmaxf(x, 0.f) + log1pf(expf(-fabsf(x)));
}
__device__ __forceinline__ float sigmoidf_(float x) { return 1.f / (1.f + expf(-x)); }
__device__ __forceinline__ float eluf(float x) { return x > 0.f ? x : expm1f(x); }
template<int ACT> __device__ __forceinline__ float actf(float v) {
    if (ACT == 1) return eluf(v);
    return v;
}

__device__ __forceinline__ void mma_bf16(float* c, const unsigned* a, const unsigned* b) {
    asm volatile(
        "mma.sync.aligned.m16n8k16.row.col.f32.bf16.bf16.f32 "
        "{%0,%1,%2,%3},{%4,%5,%6,%7},{%8,%9},{%0,%1,%2,%3};"
        : "+f"(c[0]), "+f"(c[1]), "+f"(c[2]), "+f"(c[3])
        : "r"(a[0]), "r"(a[1]), "r"(a[2]), "r"(a[3]), "r"(b[0]), "r"(b[1]));
}

// split two f32 into packed bf16 hi-word and lo-word (k-consecutive pair)
__device__ __forceinline__ void split2(float x, float y, unsigned& h, unsigned& l) {
    bf16 hx = __float2bfloat16(x), hy = __float2bfloat16(y);
    bf16 lx = __float2bfloat16(x - __bfloat162float(hx));
    bf16 ly = __float2bfloat16(y - __bfloat162float(hy));
    h = ((unsigned)__bfloat16_as_ushort(hy) << 16) | __bfloat16_as_ushort(hx);
    l = ((unsigned)__bfloat16_as_ushort(ly) << 16) | __bfloat16_as_ushort(lx);
}

// ---------------- grid barrier: atomic arrival, volatile-load spin ----------------
__device__ __forceinline__ void gbar() {
    __syncthreads();
    if (threadIdx.x == 0) {
        __threadfence();
        unsigned gen = *((volatile unsigned*)&g_bgen);
        if (atomicAdd(&g_bcount, 1u) == NBLK - 1u) {
            g_bcount = 0u;
            __threadfence();
            atomicAdd(&g_bgen, 1u);
        } else {
            while (*((volatile unsigned*)&g_bgen) == gen) { }
        }
        __threadfence();
    }
    __syncthreads();
}

// ---------------- bf16 tensor-core GEMM (batched; proven) ----------------
template<int ACT, bool ROWSHIFT, bool WF32, bool WBF>
__global__ __launch_bounds__(256, 2) void mma_gemm(
    const bf16* __restrict__ A, int ldA,
    const bf16* __restrict__ W, int ldW,
    const float* __restrict__ bias,
    float* __restrict__ Cf, bf16* __restrict__ Cb, int ldC, int K)
{
    __shared__ __align__(16) unsigned As[2][128 * 20];
    __shared__ __align__(16) unsigned Ws[2][128 * 20];
    int tid = threadIdx.x, lane = tid & 31, wid = tid >> 5;
    int g = lane >> 2, tg = lane & 3;
    int wr = wid >> 2, wc = wid & 3;
    int row0 = blockIdx.y * 128, col0 = blockIdx.x * 128;

    float acc[4][4][4];
#pragma unroll
    for (int mt = 0; mt < 4; mt++)
#pragma unroll
        for (int nt = 0; nt < 4; nt++)
#pragma unroll
            for (int q = 0; q < 4; q++) acc[mt][nt][q] = 0.f;

    const int nc = K / 32;
    uint4 pa[2], pb[2];
#pragma unroll
    for (int i = 0; i < 2; i++) {
        int u = tid + i * 256, row = u >> 2, q = u & 3;
        int grow = row0 + row;
        if (ROWSHIFT && grow >= 256) grow -= 256;
        pa[i] = *reinterpret_cast<const uint4*>(A + (size_t)grow * ldA + q * 8);
        pb[i] = *reinterpret_cast<const uint4*>(W + (size_t)(col0 + row) * ldW + q * 8);
    }
#pragma unroll
    for (int i = 0; i < 2; i++) {
        int u = tid + i * 256, row = u >> 2, q = u & 3;
        *reinterpret_cast<uint4*>(&As[0][row * 20 + q * 4]) = pa[i];
        *reinterpret_cast<uint4*>(&Ws[0][row * 20 + q * 4]) = pb[i];
    }
    __syncthreads();

    int buf = 0;
    for (int c = 0; c < nc; c++) {
        bool nxt = (c + 1 < nc);
        if (nxt) {
            int k0 = (c + 1) * 32;
#pragma unroll
            for (int i = 0; i < 2; i++) {
                int u = tid + i * 256, row = u >> 2, q = u & 3;
                int grow = row0 + row;
                if (ROWSHIFT && grow >= 256) grow -= 256;
                pa[i] = *reinterpret_cast<const uint4*>(A + (size_t)grow * ldA + k0 + q * 8);
                pb[i] = *reinterpret_cast<const uint4*>(W + (size_t)(col0 + row) * ldW + k0 + q * 8);
            }
        }
        const unsigned* as = As[buf];
        const unsigned* ws = Ws[buf];
#pragma unroll
        for (int ks = 0; ks < 2; ks++) {
            unsigned af[4][4], bfr[4][2];
#pragma unroll
            for (int mt = 0; mt < 4; mt++) {
                int r = wr * 64 + mt * 16 + g;
                af[mt][0] = as[r * 20 + ks * 8 + tg];
                af[mt][1] = as[(r + 8) * 20 + ks * 8 + tg];
                af[mt][2] = as[r * 20 + ks * 8 + tg + 4];
                af[mt][3] = as[(r + 8) * 20 + ks * 8 + tg + 4];
            }
#pragma unroll
            for (int nt = 0; nt < 4; nt++) {
                int n = wc * 32 + nt * 8 + g;
                bfr[nt][0] = ws[n * 20 + ks * 8 + tg];
                bfr[nt][1] = ws[n * 20 + ks * 8 + tg + 4];
            }
#pragma unroll
            for (int mt = 0; mt < 4; mt++)
#pragma unroll
                for (int nt = 0; nt < 4; nt++)
                    mma_bf16(acc[mt][nt], af[mt], bfr[nt]);
        }
        if (nxt) {
            int nb = buf ^ 1;
#pragma unroll
            for (int i = 0; i < 2; i++) {
                int u = tid + i * 256, row = u >> 2, q = u & 3;
                *reinterpret_cast<uint4*>(&As[nb][row * 20 + q * 4]) = pa[i];
                *reinterpret_cast<uint4*>(&Ws[nb][row * 20 + q * 4]) = pb[i];
            }
        }
        __syncthreads();
        buf ^= 1;
    }

#pragma unroll
    for (int mt = 0; mt < 4; mt++) {
        int r = row0 + wr * 64 + mt * 16 + g;
#pragma unroll
        for (int nt = 0; nt < 4; nt++) {
            int cc = col0 + wc * 32 + nt * 8 + tg * 2;
            float b0v = bias[cc], b1v = bias[cc + 1];
            float v00 = actf<ACT>(acc[mt][nt][0] + b0v);
            float v01 = actf<ACT>(acc[mt][nt][1] + b1v);
            float v10 = actf<ACT>(acc[mt][nt][2] + b0v);
            float v11 = actf<ACT>(acc[mt][nt][3] + b1v);
            if (WF32) {
                Cf[(size_t)r * ldC + cc]           = v00;
                Cf[(size_t)r * ldC + cc + 1]       = v01;
                Cf[(size_t)(r + 8) * ldC + cc]     = v10;
                Cf[(size_t)(r + 8) * ldC + cc + 1] = v11;
            }
            if (WBF) {
                Cb[(size_t)r * ldC + cc]           = __float2bfloat16(v00);
                Cb[(size_t)r * ldC + cc + 1]       = __float2bfloat16(v01);
                Cb[(size_t)(r + 8) * ldC + cc]     = __float2bfloat16(v10);
                Cb[(size_t)(r + 8) * ldC + cc + 1] = __float2bfloat16(v11);
            }
        }
    }
}

// ---------------- prep ----------------
__global__ void cvt_bf_k(const float* __restrict__ s, bf16* __restrict__ d, long n) {
    for (long i = blockIdx.x * (long)blockDim.x + threadIdx.x; i < n;
         i += (long)gridDim.x * blockDim.x)
        d[i] = __float2bfloat16(s[i]);
}

__global__ void prep_P(const float* __restrict__ action, const float* __restrict__ Wih,
                       const float* __restrict__ bih, const float* __restrict__ bhh,
                       float* __restrict__ P)
{
    int r = blockIdx.x;
    __shared__ float a[ADIM];
    if (threadIdx.x < ADIM) a[threadIdx.x] = action[(size_t)r * ADIM + threadIdx.x];
    __syncthreads();
    for (int j = threadIdx.x; j < 1536; j += 256) {
        float v = bih[j];
#pragma unroll
        for (int k = 0; k < ADIM; k++) v = fmaf(a[k], Wih[j * 70 + 64 + k], v);
        if (j < 1024) v += bhh[j];
        P[(size_t)r * 1536 + j] = v;
    }
}

// gate-interleaved packed GRU weights, split hi/lo.
__global__ void prep_WG(const float* __restrict__ Wih, const float* __restrict__ Whh,
                        bf16* __restrict__ WGh, bf16* __restrict__ WGl)
{
    long total = 2048L * 576;
    for (long idx = blockIdx.x * (long)blockDim.x + threadIdx.x; idx < total;
         idx += (long)gridDim.x * blockDim.x) {
        int c = (int)(idx / 576), k = (int)(idx % 576);
        int jb = c >> 7, gs = (c >> 5) & 3, jl = c & 31, j = jb * 32 + jl;
        float v = 0.f;
        if (gs == 0)      v = (k < 64) ? Wih[j * 70 + k] : Whh[(size_t)j * 512 + k - 64];
        else if (gs == 1) v = (k < 64) ? Wih[(512 + j) * 70 + k] : Whh[(size_t)(512 + j) * 512 + k - 64];
        else if (gs == 2) v = (k < 64) ? Wih[(1024 + j) * 70 + k] : 0.f;
        else              v = (k < 64) ? 0.f : Whh[(size_t)(1024 + j) * 512 + k - 64];
        bf16 h = __float2bfloat16(v);
        WGh[idx] = h;
        WGl[idx] = __float2bfloat16(v - __bfloat162float(h));
    }
}

__global__ void prep_split(const float* __restrict__ src, int ld, int K,
                           bf16* __restrict__ hi, bf16* __restrict__ lo, long n)
{
    for (long idx = blockIdx.x * (long)blockDim.x + threadIdx.x; idx < n;
         idx += (long)gridDim.x * blockDim.x) {
        int row = (int)(idx / K), k = (int)(idx % K);
        float v = src[(size_t)row * ld + k];
        bf16 h = __float2bfloat16(v);
        hi[idx] = h;
        lo[idx] = __float2bfloat16(v - __bfloat162float(h));
    }
}

// W2 rows interleaved (mu_i, std_i) pairs + matching bias
__global__ void prep_W2p(const float* __restrict__ W2, const float* __restrict__ b2,
                         bf16* __restrict__ hi, bf16* __restrict__ lo, float* __restrict__ b2p)
{
    long total = 128L * 512;
    for (long idx = blockIdx.x * (long)blockDim.x + threadIdx.x; idx < total;
         idx += (long)gridDim.x * blockDim.x) {
        int c = (int)(idx / 512), k = (int)(idx % 512);
        int sr = (c & 1) ? (64 + (c >> 1)) : (c >> 1);
        float v = W2[(size_t)sr * 512 + k];
        bf16 h = __float2bfloat16(v);
        hi[idx] = h;
        lo[idx] = __float2bfloat16(v - __bfloat162float(h));
        if (k == 0) b2p[c] = b2[sr];
    }
}

// ---------------- 16x64-tile split-bf16 MMA (K=512), double-buffered ----------------
// per-buffer layout (unsigned): AsH 0..320, AsL 320..640, WsH 640..1920, WsL 1920..3200
__device__ __forceinline__ void gemm16(
    const float* __restrict__ A, int ldA,
    const bf16* __restrict__ Wh, const bf16* __restrict__ Wl,
    int r0, int c0, float* acc, unsigned* SM,
    int tid, int wid, int g, int tg)
{
    acc[0] = acc[1] = acc[2] = acc[3] = 0.f;
    int ar = tid >> 3, aq = tid & 7;
    int wrow = tid >> 2, wq = tid & 3;
    bool aact = tid < 128;
    float4 fa = make_float4(0.f, 0.f, 0.f, 0.f);
    uint4 vh, vl;
    if (aact) fa = *reinterpret_cast<const float4*>(A + (size_t)(r0 + ar) * ldA + aq * 4);
    vh = *reinterpret_cast<const uint4*>(Wh + (size_t)(c0 + wrow) * 512 + wq * 8);
    vl = *reinterpret_cast<const uint4*>(Wl + (size_t)(c0 + wrow) * 512 + wq * 8);
    // store chunk 0
    {
        unsigned* b0 = SM;
        if (aact) {
            unsigned h0, l0, h1, l1;
            split2(fa.x, fa.y, h0, l0); split2(fa.z, fa.w, h1, l1);
            b0[ar * 20 + aq * 2] = h0;        b0[ar * 20 + aq * 2 + 1] = h1;
            b0[320 + ar * 20 + aq * 2] = l0;  b0[320 + ar * 20 + aq * 2 + 1] = l1;
        }
        *reinterpret_cast<uint4*>(&b0[640 + wrow * 20 + wq * 4]) = vh;
        *reinterpret_cast<uint4*>(&b0[1920 + wrow * 20 + wq * 4]) = vl;
    }
    __syncthreads();
    for (int c = 0; c < 16; c++) {
        const unsigned* base = SM + (c & 1) * 3200;
        const unsigned* AsH = base;        const unsigned* AsL = base + 320;
        const unsigned* WsH = base + 640;  const unsigned* WsL = base + 1920;
        if (c < 15) {
            int k0 = (c + 1) * 32;
            if (aact) fa = *reinterpret_cast<const float4*>(A + (size_t)(r0 + ar) * ldA + k0 + aq * 4);
            vh = *reinterpret_cast<const uint4*>(Wh + (size_t)(c0 + wrow) * 512 + k0 + wq * 8);
            vl = *reinterpret_cast<const uint4*>(Wl + (size_t)(c0 + wrow) * 512 + k0 + wq * 8);
        }
#pragma unroll
        for (int ks = 0; ks < 2; ks++) {
            unsigned aH[4], aL[4], bH[2], bL[2];
            aH[0] = AsH[g * 20 + ks * 8 + tg];       aH[1] = AsH[(g + 8) * 20 + ks * 8 + tg];
            aH[2] = AsH[g * 20 + ks * 8 + tg + 4];   aH[3] = AsH[(g + 8) * 20 + ks * 8 + tg + 4];
            aL[0] = AsL[g * 20 + ks * 8 + tg];       aL[1] = AsL[(g + 8) * 20 + ks * 8 + tg];
            aL[2] = AsL[g * 20 + ks * 8 + tg + 4];   aL[3] = AsL[(g + 8) * 20 + ks * 8 + tg + 4];
            int n = wid * 8 + g;
            bH[0] = WsH[n * 20 + ks * 8 + tg]; bH[1] = WsH[n * 20 + ks * 8 + tg + 4];
            bL[0] = WsL[n * 20 + ks * 8 + tg]; bL[1] = WsL[n * 20 + ks * 8 + tg + 4];
            mma_bf16(acc, aH, bH);
            mma_bf16(acc, aL, bH);
            mma_bf16(acc, aH, bL);
        }
        if (c < 15) {
            unsigned* nb = SM + ((c + 1) & 1) * 3200;
            if (aact) {
                unsigned h0, l0, h1, l1;
                split2(fa.x, fa.y, h0, l0); split2(fa.z, fa.w, h1, l1);
                nb[ar * 20 + aq * 2] = h0;        nb[ar * 20 + aq * 2 + 1] = h1;
                nb[320 + ar * 20 + aq * 2] = l0;  nb[320 + ar * 20 + aq * 2 + 1] = l1;
            }
            *reinterpret_cast<uint4*>(&nb[640 + wrow * 20 + wq * 4]) = vh;
            *reinterpret_cast<uint4*>(&nb[1920 + wrow * 20 + wq * 4]) = vl;
        }
        __syncthreads();
    }
}

// ---------------- persistent sequential recurrence ----------------
// dynamic smem: 12800 unsigned (51.2KB). GRU per-buffer layout (unsigned):
// AsH 0..640, AsL 640..1280, WsH 1280..3840, WsL 3840..6400; buffers at 0 / 6400.
extern __shared__ unsigned SMd[];

__global__ __launch_bounds__(256, 1) void recur_k(
    const bf16* __restrict__ WGh, const bf16* __restrict__ WGl,
    const float* __restrict__ P, const float* __restrict__ bhh,
    const bf16* __restrict__ W0hh, const bf16* __restrict__ W0hl, const float* __restrict__ PE,
    const bf16* __restrict__ W1h, const bf16* __restrict__ W1l, const float* __restrict__ b1,
    const bf16* __restrict__ W2h, const bf16* __restrict__ W2l, const float* __restrict__ b2p,
    const float* __restrict__ eps, float* __restrict__ qmu, float* __restrict__ qstd,
    bf16* __restrict__ stbf, float* __restrict__ carryA, float* __restrict__ carryB,
    const float* __restrict__ zeroc, float* __restrict__ y1, float* __restrict__ y2)
{
    unsigned* SM = SMd;
    int b = blockIdx.x, tid = threadIdx.x, lane = tid & 31, wid = tid >> 5;
    int g = lane >> 2, tg = lane & 3;

    for (int t = 0; t < TT; t++) {
        const float* cin = (t == 0) ? zeroc : ((t & 1) ? carryB : carryA);
        float* cout = ((t + 1) & 1) ? carryB : carryA;
        bf16* st_t = stbf + (size_t)t * BB * STATED;
        const float* P_t = P + (size_t)t * BB * 1536;
        const float* PE_t = PE + (size_t)t * BB * FEATD;
        const float* eps_t = eps + (size_t)t * BB * STOCHD;

        // ===== GRU: [256 x 2048] gate GEMM, K=576, tile 32x128, double-buffered =====
        {
            int bx = b & 15, by = b >> 4;
            int r0 = by * 32, c0 = bx * 128;
            int wr = wid >> 2, wc = wid & 3;
            float acc[4][4];
#pragma unroll
            for (int nt = 0; nt < 4; nt++)
#pragma unroll
                for (int q = 0; q < 4; q++) acc[nt][q] = 0.f;

            int ar = tid >> 3, aq = tid & 7;
            float4 fa = *reinterpret_cast<const float4*>(cin + (size_t)(r0 + ar) * STATED + aq * 4);
            uint4 vh[2], vl[2];
#pragma unroll
            for (int i = 0; i < 2; i++) {
                int u = tid + i * 256, rw = u >> 2, q = u & 3;
                vh[i] = *reinterpret_cast<const uint4*>(WGh + (size_t)(c0 + rw) * 576 + q * 8);
                vl[i] = *reinterpret_cast<const uint4*>(WGl + (size_t)(c0 + rw) * 576 + q * 8);
            }
            // store chunk 0 into buffer 0
            {
                unsigned* b0 = SM;
                unsigned h0, l0, h1, l1;
                split2(fa.x, fa.y, h0, l0); split2(fa.z, fa.w, h1, l1);
                b0[ar * 20 + aq * 2] = h0;        b0[ar * 20 + aq * 2 + 1] = h1;
                b0[640 + ar * 20 + aq * 2] = l0;  b0[640 + ar * 20 + aq * 2 + 1] = l1;
#pragma unroll
                for (int i = 0; i < 2; i++) {
                    int u = tid + i * 256, rw = u >> 2, q = u & 3;
                    *reinterpret_cast<uint4*>(&b0[1280 + rw * 20 + q * 4]) = vh[i];
                    *reinterpret_cast<uint4*>(&b0[3840 + rw * 20 + q * 4]) = vl[i];
                }
            }
            __syncthreads();
            for (int c = 0; c < 18; c++) {
                const unsigned* base = SM + (c & 1) * 6400;
                const unsigned* AsH = base;         const unsigned* AsL = base + 640;
                const unsigned* WsH = base + 1280;  const unsigned* WsL = base + 3840;
                if (c < 17) {
                    int k0 = (c + 1) * 32;
                    fa = *reinterpret_cast<const float4*>(cin + (size_t)(r0 + ar) * STATED + k0 + aq * 4);
#pragma unroll
                    for (int i = 0; i < 2; i++) {
                        int u = tid + i * 256, rw = u >> 2, q = u & 3;
                        vh[i] = *reinterpret_cast<const uint4*>(WGh + (size_t)(c0 + rw) * 576 + k0 + q * 8);
                        vl[i] = *reinterpret_cast<const uint4*>(WGl + (size_t)(c0 + rw) * 576 + k0 + q * 8);
                    }
                }
#pragma unroll
                for (int ks = 0; ks < 2; ks++) {
                    unsigned aH[4], aL[4];
                    int r = wr * 16 + g;
                    aH[0] = AsH[r * 20 + ks * 8 + tg];     aH[1] = AsH[(r + 8) * 20 + ks * 8 + tg];
                    aH[2] = AsH[r * 20 + ks * 8 + tg + 4]; aH[3] = AsH[(r + 8) * 20 + ks * 8 + tg + 4];
                    aL[0] = AsL[r * 20 + ks * 8 + tg];     aL[1] = AsL[(r + 8) * 20 + ks * 8 + tg];
                    aL[2] = AsL[r * 20 + ks * 8 + tg + 4]; aL[3] = AsL[(r + 8) * 20 + ks * 8 + tg + 4];
#pragma unroll
                    for (int nt = 0; nt < 4; nt++) {
                        int n = wc * 32 + nt * 8 + g;
                        unsigned bH[2] = { WsH[n * 20 + ks * 8 + tg], WsH[n * 20 + ks * 8 + tg + 4] };
                        unsigned bL[2] = { WsL[n * 20 + ks * 8 + tg], WsL[n * 20 + ks * 8 + tg + 4] };
                        mma_bf16(acc[nt], aH, bH);
                        mma_bf16(acc[nt], aL, bH);
                        mma_bf16(acc[nt], aH, bL);
                    }
                }
                if (c < 17) {
                    unsigned* nb = SM + ((c + 1) & 1) * 6400;
                    unsigned h0, l0, h1, l1;
                    split2(fa.x, fa.y, h0, l0); split2(fa.z, fa.w, h1, l1);
                    nb[ar * 20 + aq * 2] = h0;        nb[ar * 20 + aq * 2 + 1] = h1;
                    nb[640 + ar * 20 + aq * 2] = l0;  nb[640 + ar * 20 + aq * 2 + 1] = l1;
#pragma unroll
                    for (int i = 0; i < 2; i++) {
                        int u = tid + i * 256, rw = u >> 2, q = u & 3;
                        *reinterpret_cast<uint4*>(&nb[1280 + rw * 20 + q * 4]) = vh[i];
                        *reinterpret_cast<uint4*>(&nb[3840 + rw * 20 + q * 4]) = vl[i];
                    }
                }
                __syncthreads();
            }
            // stage raw gates into smem, then block-local GRU epilogue
            float* Cst = (float*)SM;   // 32 x 132
#pragma unroll
            for (int nt = 0; nt < 4; nt++) {
                int cc = wc * 32 + nt * 8 + tg * 2;
                int rr = wr * 16 + g;
                Cst[rr * 132 + cc]           = acc[nt][0];
                Cst[rr * 132 + cc + 1]       = acc[nt][1];
                Cst[(rr + 8) * 132 + cc]     = acc[nt][2];
                Cst[(rr + 8) * 132 + cc + 1] = acc[nt][3];
            }
            __syncthreads();
#pragma unroll
            for (int i = 0; i < 4; i++) {
                int o = tid + i * 256;
                int row = o >> 5, jl = o & 31;
                int gr = r0 + row, j = bx * 32 + jl;
                float rv = Cst[row * 132 + jl];
                float zv = Cst[row * 132 + 32 + jl];
                float nsv = Cst[row * 132 + 64 + jl];
                float nhv = Cst[row * 132 + 96 + jl];
                float rr_ = sigmoidf_(rv + P_t[(size_t)gr * 1536 + j]);
                float zz = sigmoidf_(zv + P_t[(size_t)gr * 1536 + 512 + j]);
                float nn = tanhf(nsv + P_t[(size_t)gr * 1536 + 1024 + j] + rr_ * (nhv + bhh[1024 + j]));
                float hp = cin[(size_t)gr * STATED + 64 + j];
                float h = (1.f - zz) * nn + zz * hp;
                cout[(size_t)gr * STATED + 64 + j] = h;
                st_t[(size_t)gr * STATED + j] = __float2bfloat16(h);
            }
        }
        gbar();

        // ===== L0: y1 = elu(h @ W0h^T + PE_t)  [256x512], K=512 =====
        {
            int by = b >> 3, bx = b & 7;
            int r0 = by * 16, c0 = bx * 64;
            float acc[4];
            gemm16(cout + 64, STATED, W0hh, W0hl, r0, c0, acc, SM, tid, wid, g, tg);
            int cc = c0 + wid * 8 + tg * 2;
            int gr = r0 + g;
            y1[(size_t)gr * 512 + cc]           = eluf(acc[0] + PE_t[(size_t)gr * 512 + cc]);
            y1[(size_t)gr * 512 + cc + 1]       = eluf(acc[1] + PE_t[(size_t)gr * 512 + cc + 1]);
            y1[(size_t)(gr + 8) * 512 + cc]     = eluf(acc[2] + PE_t[(size_t)(gr + 8) * 512 + cc]);
            y1[(size_t)(gr + 8) * 512 + cc + 1] = eluf(acc[3] + PE_t[(size_t)(gr + 8) * 512 + cc + 1]);
        }
        gbar();

        // ===== L1: y2 = elu(y1 @ W1^T + b1) =====
        {
            int by = b >> 3, bx = b & 7;
            int r0 = by * 16, c0 = bx * 64;
            float acc[4];
            gemm16(y1, 512, W1h, W1l, r0, c0, acc, SM, tid, wid, g, tg);
            int cc = c0 + wid * 8 + tg * 2;
            int gr = r0 + g;
            y2[(size_t)gr * 512 + cc]           = eluf(acc[0] + b1[cc]);
            y2[(size_t)gr * 512 + cc + 1]       = eluf(acc[1] + b1[cc + 1]);
            y2[(size_t)(gr + 8) * 512 + cc]     = eluf(acc[2] + b1[cc]);
            y2[(size_t)(gr + 8) * 512 + cc + 1] = eluf(acc[3] + b1[cc + 1]);
        }
        gbar();

        // ===== L2 + sample: qraw[256x128] (interleaved mu/std), K=512 =====
        if (b < 32) {
            int by = b >> 1, bx = b & 1;
            int r0 = by * 16, c0 = bx * 64;
            float acc[4];
            gemm16(y2, 512, W2h, W2l, r0, c0, acc, SM, tid, wid, g, tg);
            int cc = c0 + wid * 8 + tg * 2;
            int i_ = cc >> 1;
#pragma unroll
            for (int rr = 0; rr < 2; rr++) {
                int gr = r0 + g + rr * 8;
                float mu = acc[rr * 2] + b2p[cc];
                float sd = softplusf(acc[rr * 2 + 1] + b2p[cc + 1]) + 1e-4f;
                float s = fmaf(sd, eps_t[(size_t)gr * 64 + i_], mu);
                qmu[(size_t)(t * BB + gr) * 64 + i_] = mu;
                qstd[(size_t)(t * BB + gr) * 64 + i_] = sd;
                cout[(size_t)gr * STATED + i_] = s;
                st_t[(size_t)gr * STATED + 512 + i_] = __float2bfloat16(s);
            }
        }
        gbar();
    }
}

// ---------------- misc ----------------
__global__ void e0_l1(const float* __restrict__ ep_b0, const float* __restrict__ ep_W1,
                      const float* __restrict__ ep_b1, float* __restrict__ l1)
{
    __shared__ float x0[512];
    for (int k = threadIdx.x; k < 512; k += 256) x0[k] = eluf(ep_b0[k]);
    __syncthreads();
    for (int o = threadIdx.x; o < 512; o += 256) {
        float v = ep_b1[o];
        for (int k = 0; k < 512; k++) v = fmaf(x0[k], ep_W1[(size_t)o * 512 + k], v);
        l1[o] = eluf(v);
    }
}

__global__ void e0_head(const float* __restrict__ l1, const float* __restrict__ ep_W2,
                        const float* __restrict__ ep_b2, float* __restrict__ e0)
{
    int o = blockIdx.x * 256 + threadIdx.x;
    float v = ep_b2[o];
    for (int k = 0; k < 512; k++) v = fmaf(l1[k], ep_W2[(size_t)o * 512 + k], v);
    e0[o] = v;
}

__global__ void build_pcat(const bf16* __restrict__ stbf, const bf16* __restrict__ Ebf,
                           const bf16* __restrict__ e0bf, bf16* __restrict__ out)
{
    int r = blockIdx.x;
    const bf16* src = (r < 256) ? e0bf : (Ebf + (size_t)(r - 256) * EMBD);
    bf16* o = out + (size_t)r * 1536;
    const bf16* st = stbf + (size_t)r * STATED;
    for (int c = threadIdx.x; c < 1536; c += 256)
        o[c] = (c < 512) ? st[c] : src[c - 512];
}

// ---------------- reductions ----------------
__global__ void zero_acc_k(double* acc) { if (threadIdx.x < 3) acc[threadIdx.x] = 0.0; }

__global__ void kl_reduce_k(const float* __restrict__ praw, const float* __restrict__ qmu,
                            const float* __restrict__ qstd, double* __restrict__ acc)
{
    __shared__ double sh[256];
    double s = 0.0;
    long total = (long)TBD * STOCHD;
    for (long idx = blockIdx.x * (long)blockDim.x + threadIdx.x; idx < total;
         idx += (long)gridDim.x * blockDim.x) {
        int r = (int)(idx >> 6), i = (int)(idx & 63);
        float pmu = praw[(size_t)r * 128 + i];
        float psd = softplusf(praw[(size_t)r * 128 + 64 + i]) + 1e-4f;
        float qm = qmu[idx], qs = qstd[idx];
        float d = qm - pmu;
        s += (double)(logf(psd / qs) + (qs * qs + d * d) / (2.f * psd * psd) - 0.5f);
    }
    sh[threadIdx.x] = s; __syncthreads();
    for (int o = 128; o > 0; o >>= 1) {
        if (threadIdx.x < o) sh[threadIdx.x] += sh[threadIdx.x + o];
        __syncthreads();
    }
    if (threadIdx.x == 0) atomicAdd(acc, sh[0]);
}

__global__ void emb_reduce_k(const float* __restrict__ emb, const float* __restrict__ embmu,
                             double* __restrict__ acc)
{
    __shared__ double sh[256];
    double s = 0.0;
    long total = (long)TBD * EMBD;
    for (long idx = blockIdx.x * (long)blockDim.x + threadIdx.x; idx < total;
         idx += (long)gridDim.x * blockDim.x) {
        float d = emb[idx] - embmu[idx];
        s += (double)(0.5f * d * d + 0.5f * LOG2PI_F);
    }
    sh[threadIdx.x] = s; __syncthreads();
    for (int o = 128; o > 0; o >>= 1) {
        if (threadIdx.x < o) sh[threadIdx.x] += sh[threadIdx.x + o];
        __syncthreads();
    }
    if (threadIdx.x == 0) atomicAdd(acc, sh[0]);
}

__global__ void reward_reduce_k(const bf16* __restrict__ big2, const float* __restrict__ W,
                                const float* __restrict__ bias, const float* __restrict__ reward,
                                double* __restrict__ acc)
{
    __shared__ double sh[8];
    int lane = threadIdx.x & 31, wib = threadIdx.x >> 5;
    int gwarp = (blockIdx.x * blockDim.x + threadIdx.x) >> 5;
    int nwarps = (gridDim.x * blockDim.x) >> 5;
    double local = 0.0;
    for (int r = gwarp; r < TBD; r += nwarps) {
        float sum = 0.f;
        const bf16* row = big2 + (size_t)r * FEATD;
        for (int k = lane; k < FEATD; k += 32)
            sum = fmaf(__bfloat162float(row[k]), W[k], sum);
#pragma unroll
        for (int o = 16; o > 0; o >>= 1) sum += __shfl_xor_sync(0xffffffffu, sum, o);
        if (lane == 0) {
            float d = reward[r] - (sum + bias[0]);
            local += (double)(0.5f * d * d + 0.5f * LOG2PI_F);
        }
    }
    if (lane == 0) sh[wib] = local;
    __syncthreads();
    if (threadIdx.x == 0) {
        double t = 0.0;
        for (int i = 0; i < 8; i++) t += sh[i];
        atomicAdd(acc, t);
    }
}

__global__ void finalize_k(const double* __restrict__ acc, float* __restrict__ out, int n) {
    double inv = 1.0 / (double)(TT * BB);
    float loss = (float)((acc[0] + acc[1] + acc[2]) * inv);
    for (int i = 0; i < n; i++) out[i] = loss;
}

// ---------------- host ----------------
static void* symaddr(const void* sym) {
    void* p = nullptr;
    cudaGetSymbolAddress(&p, sym);
    return p;
}

extern "C" void kernel_launch(void* const* d_in, const int* in_sizes, int n_in,
                              void* d_out, int out_size)
{
    const float* emb     = (const float*)d_in[0];
    const float* action  = (const float*)d_in[1];
    const float* reward  = (const float*)d_in[2];
    const float* eps     = (const float*)d_in[3];
    const float* gru_Wih = (const float*)d_in[4];
    const float* gru_bih = (const float*)d_in[5];
    const float* gru_Whh = (const float*)d_in[6];
    const float* gru_bhh = (const float*)d_in[7];
    const float* st_W0 = (const float*)d_in[8];  const float* st_b0 = (const float*)d_in[9];
    const float* st_W1 = (const float*)d_in[10]; const float* st_b1 = (const float*)d_in[11];
    const float* st_W2 = (const float*)d_in[12]; const float* st_b2 = (const float*)d_in[13];
    const float* ep_W0 = (const float*)d_in[14]; const float* ep_b0 = (const float*)d_in[15];
    const float* ep_W1 = (const float*)d_in[16]; const float* ep_b1 = (const float*)d_in[17];
    const float* ep_W2 = (const float*)d_in[18]; const float* ep_b2 = (const float*)d_in[19];
    const float* rp_W0 = (const float*)d_in[20]; const float* rp_b0 = (const float*)d_in[21];
    const float* rp_W1 = (const float*)d_in[22]; const float* rp_b1 = (const float*)d_in[23];
    const float* rp_W2 = (const float*)d_in[24]; const float* rp_b2 = (const float*)d_in[25];

    float* carryA = (float*)symaddr(g_carryA);
    float* carryB = (float*)symaddr(g_carryB);
    float* zeroc  = (float*)symaddr(g_zeroc);
    float* y1     = (float*)symaddr(g_y1);
    float* y2     = (float*)symaddr(g_y2);
    float* qmu    = (float*)symaddr(g_qmu);
    float* qstd   = (float*)symaddr(g_qstd);
    float* P      = (float*)symaddr(g_P);
    float* PE     = (float*)symaddr(g_PE);
    float* E      = (float*)symaddr(g_E);
    float* praw   = (float*)symaddr(g_praw);
    float* e0     = (float*)symaddr(g_e0);
    float* e0l1   = (float*)symaddr(g_e0l1);
    float* b2p    = (float*)symaddr(g_b2p);
    double* acc   = (double*)symaddr(g_acc);
    bf16* stbf   = (bf16*)symaddr(g_states_bf);
    bf16* embbf  = (bf16*)symaddr(g_emb_bf);
    bf16* Ebf    = (bf16*)symaddr(g_E_bf);
    bf16* pcatbf = (bf16*)symaddr(g_pcat_bf);
    bf16* big1bf = (bf16*)symaddr(g_big1_bf);
    bf16* big2bf = (bf16*)symaddr(g_big2_bf);
    bf16* e0bf   = (bf16*)symaddr(g_e0_bf);
    bf16* stW0b  = (bf16*)symaddr(g_stW0b);
    bf16* stW1b  = (bf16*)symaddr(g_stW1b);
    bf16* stW2b  = (bf16*)symaddr(g_stW2b);
    bf16* epW0b  = (bf16*)symaddr(g_epW0b);
    bf16* epW1b  = (bf16*)symaddr(g_epW1b);
    bf16* epW2b  = (bf16*)symaddr(g_epW2b);
    bf16* rpW0b  = (bf16*)symaddr(g_rpW0b);
    bf16* rpW1b  = (bf16*)symaddr(g_rpW1b);
    bf16* WGh  = (bf16*)symaddr(g_WGh);   bf16* WGl  = (bf16*)symaddr(g_WGl);
    bf16* W0hh = (bf16*)symaddr(g_W0hh);  bf16* W0hl = (bf16*)symaddr(g_W0hl);
    bf16* W1h  = (bf16*)symaddr(g_W1h);   bf16* W1l  = (bf16*)symaddr(g_W1l);
    bf16* W2h  = (bf16*)symaddr(g_W2h);   bf16* W2l  = (bf16*)symaddr(g_W2l);

    static bool attr_set = false;
    if (!attr_set) {
        cudaFuncSetAttribute(recur_k, cudaFuncAttributeMaxDynamicSharedMemorySize, 64 * 1024);
        attr_set = true;
    }

    zero_acc_k<<<1, 32>>>(acc);

    // conversions + prep
    cvt_bf_k<<<2048, 256>>>(emb,   embbf, (long)TBD * EMBD);
    cvt_bf_k<<<512, 256>>>(st_W0, stW0b, 512L * 1536);
    cvt_bf_k<<<256, 256>>>(st_W1, stW1b, 512L * 512);
    cvt_bf_k<<<64,  256>>>(st_W2, stW2b, 128L * 512);
    cvt_bf_k<<<256, 256>>>(ep_W0, epW0b, 512L * 576);
    cvt_bf_k<<<256, 256>>>(ep_W1, epW1b, 512L * 512);
    cvt_bf_k<<<512, 256>>>(ep_W2, epW2b, 1024L * 512);
    cvt_bf_k<<<256, 256>>>(rp_W0, rpW0b, 512L * 576);
    cvt_bf_k<<<256, 256>>>(rp_W1, rpW1b, 512L * 512);
    prep_P<<<TBD, 256>>>(action, gru_Wih, gru_bih, gru_bhh, P);
    prep_WG<<<1024, 256>>>(gru_Wih, gru_Whh, WGh, WGl);
    prep_split<<<256, 256>>>(st_W0, 1536, 512, W0hh, W0hl, 512L * 512);
    prep_split<<<256, 256>>>(st_W1, 512, 512, W1h, W1l, 512L * 512);
    prep_W2p<<<64, 256>>>(st_W2, st_b2, W2h, W2l, b2p);
    e0_l1<<<1, 256>>>(ep_b0, ep_W1, ep_b1, e0l1);
    e0_head<<<4, 256>>>(e0l1, ep_W2, ep_b2, e0);
    cvt_bf_k<<<4, 256>>>(e0, e0bf, EMBD);

    // PE = emb_prev @ st_W0[:,512:1536]^T + st_b0   (tensor core, rowShift)
    mma_gemm<0, true, true, false><<<dim3(4, 128), 256>>>(
        embbf, EMBD, stW0b + 512, 1536, st_b0, PE, nullptr, FEATD, EMBD);

    // sequential recurrence: persistent, split-bf16 tensor-core stages (dynamic smem)
    recur_k<<<NBLK, 256, 51200>>>(WGh, WGl, P, gru_bhh, W0hh, W0hl, PE,
                                  W1h, W1l, st_b1, W2h, W2l, b2p,
                                  eps, qmu, qstd, stbf, carryA, carryB, zeroc, y1, y2);

    // shared ep-MLP: E = ep_mlp(states) = emb_mu; row-shifted = pre_emb
    mma_gemm<1, false, false, true><<<dim3(4, 128), 256>>>(
        stbf, STATED, epW0b, STATED, ep_b0, nullptr, big1bf, FEATD, STATED);
    mma_gemm<1, false, false, true><<<dim3(4, 128), 256>>>(
        big1bf, FEATD, epW1b, FEATD, ep_b1, nullptr, big2bf, FEATD, FEATD);
    mma_gemm<0, false, true, true><<<dim3(8, 128), 256>>>(
        big2bf, FEATD, epW2b, FEATD, ep_b2, E, Ebf, EMBD, FEATD);

    // prior path
    build_pcat<<<TBD, 256>>>(stbf, Ebf, e0bf, pcatbf);
    mma_gemm<1, false, false, true><<<dim3(4, 128), 256>>>(
        pcatbf, 1536, stW0b, 1536, st_b0, nullptr, big1bf, FEATD, 1536);
    mma_gemm<1, false, false, true><<<dim3(4, 128), 256>>>(
        big1bf, FEATD, stW1b, FEATD, st_b1, nullptr, big2bf, FEATD, FEATD);
    mma_gemm<0, false, true, false><<<dim3(1, 128), 256>>>(
        big2bf, FEATD, stW2b, FEATD, st_b2, praw, nullptr, 128, FEATD);
    kl_reduce_k<<<1024, 256>>>(praw, qmu, qstd, acc + 0);

    // emb loss
    emb_reduce_k<<<2048, 256>>>(emb, E, acc + 1);

    // reward loss
    mma_gemm<1, false, false, true><<<dim3(4, 128), 256>>>(
        stbf, STATED, rpW0b, STATED, rp_b0, nullptr, big1bf, FEATD, STATED);
    mma_gemm<1, false, false, true><<<dim3(4, 128), 256>>>(
        big1bf, FEATD, rpW1b, FEATD, rp_b1, nullptr, big2bf, FEATD, FEATD);
    reward_reduce_k<<<512, 256>>>(big2bf, rp_W2, rp_b2, reward, acc + 2);

    finalize_k<<<1, 1>>>(acc, (float*)d_out, out_size);
}

// round 9
// speedup vs baseline: 1.2488x; 1.2488x over previous
#include <cuda_runtime.h>
#include <cuda_bf16.h>
#include <math.h>

#define TT 64
#define BB 256
#define EMBD 1024
#define ADIM 6
#define STOCHD 64
#define HIDD 512
#define FEATD 512
#define STATED 576
#define TBD (TT*BB)
#define NBLK 128
#define LOG2PI_F 1.837877066409345483560659472811f

typedef __nv_bfloat16 bf16;

// ---------------- scratch ----------------
__device__ float g_qmu[TBD*STOCHD];
__device__ float g_qstd[TBD*STOCHD];
__device__ float g_P[TBD*1536];
__device__ float g_PE[TBD*FEATD];
__device__ float g_E[TBD*EMBD];
__device__ float g_praw[TBD*2*STOCHD];
__device__ float g_e0[EMBD];
__device__ float g_e0l1[FEATD];
__device__ float g_b2p[128];
__device__ double g_acc[3];
__device__ unsigned g_bcount = 0;
__device__ unsigned g_bgen = 0;

// hi/lo carry + intermediates (bf16 pairs)
__device__ bf16 g_cAH[BB*STATED];
__device__ bf16 g_cAL[BB*STATED];
__device__ bf16 g_cBH[BB*STATED];
__device__ bf16 g_cBL[BB*STATED];
__device__ bf16 g_zcH[BB*STATED];   // zero, never written
__device__ bf16 g_zcL[BB*STATED];   // zero, never written
__device__ bf16 g_y1H[BB*FEATD];
__device__ bf16 g_y1L[BB*FEATD];
__device__ bf16 g_y2H[BB*FEATD];
__device__ bf16 g_y2L[BB*FEATD];

__device__ bf16 g_states_bf[TBD*STATED];
__device__ bf16 g_emb_bf[TBD*EMBD];
__device__ bf16 g_E_bf[TBD*EMBD];
__device__ bf16 g_pcat_bf[TBD*1536];
__device__ bf16 g_big1_bf[TBD*FEATD];
__device__ bf16 g_big2_bf[TBD*FEATD];
__device__ bf16 g_e0_bf[EMBD];
__device__ bf16 g_stW0b[512*1536];
__device__ bf16 g_stW1b[512*512];
__device__ bf16 g_stW2b[128*512];
__device__ bf16 g_epW0b[512*576];
__device__ bf16 g_epW1b[512*512];
__device__ bf16 g_epW2b[1024*512];
__device__ bf16 g_rpW0b[512*576];
__device__ bf16 g_rpW1b[512*512];
// split hi/lo weights for the sequential path
__device__ bf16 g_WGh[2048*576];
__device__ bf16 g_WGl[2048*576];
__device__ bf16 g_W0hh[512*512];
__device__ bf16 g_W0hl[512*512];
__device__ bf16 g_W1h[512*512];
__device__ bf16 g_W1l[512*512];
__device__ bf16 g_W2h[128*512];
__device__ bf16 g_W2l[128*512];

// ---------------- math ----------------
__device__ __forceinline__ float softplusf(float x) {
    return fmaxf(x, 0.f) + log1pf(expf(-fabsf(x)));
}
__device__ __forceinline__ float sigmoidf_(float x) { return 1.f / (1.f + expf(-x)); }
__device__ __forceinline__ float eluf(float x) { return x > 0.f ? x : expm1f(x); }
template<int ACT> __device__ __forceinline__ float actf(float v) {
    if (ACT == 1) return eluf(v);
    return v;
}

__device__ __forceinline__ void mma_bf16(float* c, const unsigned* a, const unsigned* b) {
    asm volatile(
        "mma.sync.aligned.m16n8k16.row.col.f32.bf16.bf16.f32 "
        "{%0,%1,%2,%3},{%4,%5,%6,%7},{%8,%9},{%0,%1,%2,%3};"
        : "+f"(c[0]), "+f"(c[1]), "+f"(c[2]), "+f"(c[3])
        : "r"(a[0]), "r"(a[1]), "r"(a[2]), "r"(a[3]), "r"(b[0]), "r"(b[1]));
}

__device__ __forceinline__ void splitw(float v, bf16& h, bf16& l) {
    h = __float2bfloat16(v);
    l = __float2bfloat16(v - __bfloat162float(h));
}

// ---------------- grid barrier (R7 proven) ----------------
__device__ __forceinline__ void gbar() {
    __syncthreads();
    if (threadIdx.x == 0) {
        __threadfence();
        unsigned gen = atomicAdd(&g_bgen, 0u);
        if (atomicAdd(&g_bcount, 1u) == NBLK - 1u) {
            g_bcount = 0u;
            __threadfence();
            atomicAdd(&g_bgen, 1u);
        } else {
            while (atomicAdd(&g_bgen, 0u) == gen) { __nanosleep(64); }
        }
        __threadfence();
    }
    __syncthreads();
}

// ---------------- bf16 tensor-core GEMM (batched; proven) ----------------
template<int ACT, bool ROWSHIFT, bool WF32, bool WBF>
__global__ __launch_bounds__(256, 2) void mma_gemm(
    const bf16* __restrict__ A, int ldA,
    const bf16* __restrict__ W, int ldW,
    const float* __restrict__ bias,
    float* __restrict__ Cf, bf16* __restrict__ Cb, int ldC, int K)
{
    __shared__ __align__(16) unsigned As[2][128 * 20];
    __shared__ __align__(16) unsigned Ws[2][128 * 20];
    int tid = threadIdx.x, lane = tid & 31, wid = tid >> 5;
    int g = lane >> 2, tg = lane & 3;
    int wr = wid >> 2, wc = wid & 3;
    int row0 = blockIdx.y * 128, col0 = blockIdx.x * 128;

    float acc[4][4][4];
#pragma unroll
    for (int mt = 0; mt < 4; mt++)
#pragma unroll
        for (int nt = 0; nt < 4; nt++)
#pragma unroll
            for (int q = 0; q < 4; q++) acc[mt][nt][q] = 0.f;

    const int nc = K / 32;
    uint4 pa[2], pb[2];
#pragma unroll
    for (int i = 0; i < 2; i++) {
        int u = tid + i * 256, row = u >> 2, q = u & 3;
        int grow = row0 + row;
        if (ROWSHIFT && grow >= 256) grow -= 256;
        pa[i] = *reinterpret_cast<const uint4*>(A + (size_t)grow * ldA + q * 8);
        pb[i] = *reinterpret_cast<const uint4*>(W + (size_t)(col0 + row) * ldW + q * 8);
    }
#pragma unroll
    for (int i = 0; i < 2; i++) {
        int u = tid + i * 256, row = u >> 2, q = u & 3;
        *reinterpret_cast<uint4*>(&As[0][row * 20 + q * 4]) = pa[i];
        *reinterpret_cast<uint4*>(&Ws[0][row * 20 + q * 4]) = pb[i];
    }
    __syncthreads();

    int buf = 0;
    for (int c = 0; c < nc; c++) {
        bool nxt = (c + 1 < nc);
        if (nxt) {
            int k0 = (c + 1) * 32;
#pragma unroll
            for (int i = 0; i < 2; i++) {
                int u = tid + i * 256, row = u >> 2, q = u & 3;
                int grow = row0 + row;
                if (ROWSHIFT && grow >= 256) grow -= 256;
                pa[i] = *reinterpret_cast<const uint4*>(A + (size_t)grow * ldA + k0 + q * 8);
                pb[i] = *reinterpret_cast<const uint4*>(W + (size_t)(col0 + row) * ldW + k0 + q * 8);
            }
        }
        const unsigned* as = As[buf];
        const unsigned* ws = Ws[buf];
#pragma unroll
        for (int ks = 0; ks < 2; ks++) {
            unsigned af[4][4], bfr[4][2];
#pragma unroll
            for (int mt = 0; mt < 4; mt++) {
                int r = wr * 64 + mt * 16 + g;
                af[mt][0] = as[r * 20 + ks * 8 + tg];
                af[mt][1] = as[(r + 8) * 20 + ks * 8 + tg];
                af[mt][2] = as[r * 20 + ks * 8 + tg + 4];
                af[mt][3] = as[(r + 8) * 20 + ks * 8 + tg + 4];
            }
#pragma unroll
            for (int nt = 0; nt < 4; nt++) {
                int n = wc * 32 + nt * 8 + g;
                bfr[nt][0] = ws[n * 20 + ks * 8 + tg];
                bfr[nt][1] = ws[n * 20 + ks * 8 + tg + 4];
            }
#pragma unroll
            for (int mt = 0; mt < 4; mt++)
#pragma unroll
                for (int nt = 0; nt < 4; nt++)
                    mma_bf16(acc[mt][nt], af[mt], bfr[nt]);
        }
        if (nxt) {
            int nb = buf ^ 1;
#pragma unroll
            for (int i = 0; i < 2; i++) {
                int u = tid + i * 256, row = u >> 2, q = u & 3;
                *reinterpret_cast<uint4*>(&As[nb][row * 20 + q * 4]) = pa[i];
                *reinterpret_cast<uint4*>(&Ws[nb][row * 20 + q * 4]) = pb[i];
            }
        }
        __syncthreads();
        buf ^= 1;
    }

#pragma unroll
    for (int mt = 0; mt < 4; mt++) {
        int r = row0 + wr * 64 + mt * 16 + g;
#pragma unroll
        for (int nt = 0; nt < 4; nt++) {
            int cc = col0 + wc * 32 + nt * 8 + tg * 2;
            float b0v = bias[cc], b1v = bias[cc + 1];
            float v00 = actf<ACT>(acc[mt][nt][0] + b0v);
            float v01 = actf<ACT>(acc[mt][nt][1] + b1v);
            float v10 = actf<ACT>(acc[mt][nt][2] + b0v);
            float v11 = actf<ACT>(acc[mt][nt][3] + b1v);
            if (WF32) {
                Cf[(size_t)r * ldC + cc]           = v00;
                Cf[(size_t)r * ldC + cc + 1]       = v01;
                Cf[(size_t)(r + 8) * ldC + cc]     = v10;
                Cf[(size_t)(r + 8) * ldC + cc + 1] = v11;
            }
            if (WBF) {
                Cb[(size_t)r * ldC + cc]           = __float2bfloat16(v00);
                Cb[(size_t)r * ldC + cc + 1]       = __float2bfloat16(v01);
                Cb[(size_t)(r + 8) * ldC + cc]     = __float2bfloat16(v10);
                Cb[(size_t)(r + 8) * ldC + cc + 1] = __float2bfloat16(v11);
            }
        }
    }
}

// ---------------- prep ----------------
__global__ void cvt_bf_k(const float* __restrict__ s, bf16* __restrict__ d, long n) {
    for (long i = blockIdx.x * (long)blockDim.x + threadIdx.x; i < n;
         i += (long)gridDim.x * blockDim.x)
        d[i] = __float2bfloat16(s[i]);
}

__global__ void prep_P(const float* __restrict__ action, const float* __restrict__ Wih,
                       const float* __restrict__ bih, const float* __restrict__ bhh,
                       float* __restrict__ P)
{
    int r = blockIdx.x;
    __shared__ float a[ADIM];
    if (threadIdx.x < ADIM) a[threadIdx.x] = action[(size_t)r * ADIM + threadIdx.x];
    __syncthreads();
    for (int j = threadIdx.x; j < 1536; j += 256) {
        float v = bih[j];
#pragma unroll
        for (int k = 0; k < ADIM; k++) v = fmaf(a[k], Wih[j * 70 + 64 + k], v);
        if (j < 1024) v += bhh[j];
        P[(size_t)r * 1536 + j] = v;
    }
}

// gate-interleaved packed GRU weights, split hi/lo.
__global__ void prep_WG(const float* __restrict__ Wih, const float* __restrict__ Whh,
                        bf16* __restrict__ WGh, bf16* __restrict__ WGl)
{
    long total = 2048L * 576;
    for (long idx = blockIdx.x * (long)blockDim.x + threadIdx.x; idx < total;
         idx += (long)gridDim.x * blockDim.x) {
        int c = (int)(idx / 576), k = (int)(idx % 576);
        int jb = c >> 7, gs = (c >> 5) & 3, jl = c & 31, j = jb * 32 + jl;
        float v = 0.f;
        if (gs == 0)      v = (k < 64) ? Wih[j * 70 + k] : Whh[(size_t)j * 512 + k - 64];
        else if (gs == 1) v = (k < 64) ? Wih[(512 + j) * 70 + k] : Whh[(size_t)(512 + j) * 512 + k - 64];
        else if (gs == 2) v = (k < 64) ? Wih[(1024 + j) * 70 + k] : 0.f;
        else              v = (k < 64) ? 0.f : Whh[(size_t)(1024 + j) * 512 + k - 64];
        bf16 h, l; splitw(v, h, l);
        WGh[idx] = h; WGl[idx] = l;
    }
}

__global__ void prep_split(const float* __restrict__ src, int ld, int K,
                           bf16* __restrict__ hi, bf16* __restrict__ lo, long n)
{
    for (long idx = blockIdx.x * (long)blockDim.x + threadIdx.x; idx < n;
         idx += (long)gridDim.x * blockDim.x) {
        int row = (int)(idx / K), k = (int)(idx % K);
        float v = src[(size_t)row * ld + k];
        bf16 h, l; splitw(v, h, l);
        hi[idx] = h; lo[idx] = l;
    }
}

// W2 rows interleaved (mu_i, std_i) pairs + matching bias
__global__ void prep_W2p(const float* __restrict__ W2, const float* __restrict__ b2,
                         bf16* __restrict__ hi, bf16* __restrict__ lo, float* __restrict__ b2p)
{
    long total = 128L * 512;
    for (long idx = blockIdx.x * (long)blockDim.x + threadIdx.x; idx < total;
         idx += (long)gridDim.x * blockDim.x) {
        int c = (int)(idx / 512), k = (int)(idx % 512);
        int sr = (c & 1) ? (64 + (c >> 1)) : (c >> 1);
        float v = W2[(size_t)sr * 512 + k];
        bf16 h, l; splitw(v, h, l);
        hi[idx] = h; lo[idx] = l;
        if (k == 0) b2p[c] = b2[sr];
    }
}

// ---------------- 16x64-tile split-bf16 MMA, K=512, k64 chunks, dbl-buffered ----------------
// buffer (u32): AsH 0..576, AsL 576..1152, WsH 1152..3456, WsL 3456..5760; buffers at 0/5760
__device__ __forceinline__ void gemm16v(
    const bf16* __restrict__ AH, const bf16* __restrict__ AL, int ldA,
    const bf16* __restrict__ WH, const bf16* __restrict__ WL,
    int r0, int c0, float* acc, unsigned* SM,
    int tid, int wid, int g, int tg)
{
    acc[0] = acc[1] = acc[2] = acc[3] = 0.f;
    int arow = (tid & 127) >> 3, aq = tid & 7;
    const bf16* Asrc = (tid < 128) ? AH : AL;
    int adst = (tid < 128) ? 0 : 576;
    uint4 va, vw[2][2];
    va = *reinterpret_cast<const uint4*>(Asrc + (size_t)(r0 + arow) * ldA + aq * 8);
#pragma unroll
    for (int i = 0; i < 2; i++) {
        int u = tid + i * 256, wcol = u >> 3, wq = u & 7;
        vw[i][0] = *reinterpret_cast<const uint4*>(WH + (size_t)(c0 + wcol) * 512 + wq * 8);
        vw[i][1] = *reinterpret_cast<const uint4*>(WL + (size_t)(c0 + wcol) * 512 + wq * 8);
    }
    {
        unsigned* b0 = SM;
        *reinterpret_cast<uint4*>(&b0[adst + arow * 36 + aq * 4]) = va;
#pragma unroll
        for (int i = 0; i < 2; i++) {
            int u = tid + i * 256, wcol = u >> 3, wq = u & 7;
            *reinterpret_cast<uint4*>(&b0[1152 + wcol * 36 + wq * 4]) = vw[i][0];
            *reinterpret_cast<uint4*>(&b0[3456 + wcol * 36 + wq * 4]) = vw[i][1];
        }
    }
    __syncthreads();
    for (int c = 0; c < 8; c++) {
        const unsigned* base = SM + (c & 1) * 5760;
        if (c < 7) {
            int k0 = (c + 1) * 64;
            va = *reinterpret_cast<const uint4*>(Asrc + (size_t)(r0 + arow) * ldA + k0 + aq * 8);
#pragma unroll
            for (int i = 0; i < 2; i++) {
                int u = tid + i * 256, wcol = u >> 3, wq = u & 7;
                vw[i][0] = *reinterpret_cast<const uint4*>(WH + (size_t)(c0 + wcol) * 512 + k0 + wq * 8);
                vw[i][1] = *reinterpret_cast<const uint4*>(WL + (size_t)(c0 + wcol) * 512 + k0 + wq * 8);
            }
        }
#pragma unroll
        for (int ks = 0; ks < 4; ks++) {
            unsigned aH[4], aL[4], bH[2], bL[2];
            aH[0] = base[g * 36 + ks * 8 + tg];       aH[1] = base[(g + 8) * 36 + ks * 8 + tg];
            aH[2] = base[g * 36 + ks * 8 + tg + 4];   aH[3] = base[(g + 8) * 36 + ks * 8 + tg + 4];
            aL[0] = base[576 + g * 36 + ks * 8 + tg];     aL[1] = base[576 + (g + 8) * 36 + ks * 8 + tg];
            aL[2] = base[576 + g * 36 + ks * 8 + tg + 4]; aL[3] = base[576 + (g + 8) * 36 + ks * 8 + tg + 4];
            int n = wid * 8 + g;
            bH[0] = base[1152 + n * 36 + ks * 8 + tg]; bH[1] = base[1152 + n * 36 + ks * 8 + tg + 4];
            bL[0] = base[3456 + n * 36 + ks * 8 + tg]; bL[1] = base[3456 + n * 36 + ks * 8 + tg + 4];
            mma_bf16(acc, aH, bH);
            mma_bf16(acc, aL, bH);
            mma_bf16(acc, aH, bL);
        }
        if (c < 7) {
            unsigned* nb = SM + ((c + 1) & 1) * 5760;
            *reinterpret_cast<uint4*>(&nb[adst + arow * 36 + aq * 4]) = va;
#pragma unroll
            for (int i = 0; i < 2; i++) {
                int u = tid + i * 256, wcol = u >> 3, wq = u & 7;
                *reinterpret_cast<uint4*>(&nb[1152 + wcol * 36 + wq * 4]) = vw[i][0];
                *reinterpret_cast<uint4*>(&nb[3456 + wcol * 36 + wq * 4]) = vw[i][1];
            }
        }
        __syncthreads();
    }
}

// ---------------- persistent sequential recurrence ----------------
// dynamic smem arena: 23040 u32 (92160B).
// GRU buffer (u32): AsH 0..1152, AsL 1152..2304, WsH 2304..6912, WsL 6912..11520; buffers 0/11520.
extern __shared__ unsigned SMd[];

__global__ __launch_bounds__(256, 1) void recur_k(
    const bf16* __restrict__ WGh, const bf16* __restrict__ WGl,
    const float* __restrict__ P, const float* __restrict__ bhh,
    const bf16* __restrict__ W0hh, const bf16* __restrict__ W0hl, const float* __restrict__ PE,
    const bf16* __restrict__ W1h, const bf16* __restrict__ W1l, const float* __restrict__ b1,
    const bf16* __restrict__ W2h, const bf16* __restrict__ W2l, const float* __restrict__ b2p,
    const float* __restrict__ eps, float* __restrict__ qmu, float* __restrict__ qstd,
    bf16* __restrict__ stbf,
    bf16* __restrict__ cAH, bf16* __restrict__ cAL,
    bf16* __restrict__ cBH, bf16* __restrict__ cBL,
    const bf16* __restrict__ zcH, const bf16* __restrict__ zcL,
    bf16* __restrict__ y1H, bf16* __restrict__ y1L,
    bf16* __restrict__ y2H, bf16* __restrict__ y2L)
{
    unsigned* SM = SMd;
    int b = blockIdx.x, tid = threadIdx.x, lane = tid & 31, wid = tid >> 5;
    int g = lane >> 2, tg = lane & 3;

    for (int t = 0; t < TT; t++) {
        const bf16* cinH = (t == 0) ? zcH : ((t & 1) ? cBH : cAH);
        const bf16* cinL = (t == 0) ? zcL : ((t & 1) ? cBL : cAL);
        bf16* coutH = ((t + 1) & 1) ? cBH : cAH;
        bf16* coutL = ((t + 1) & 1) ? cBL : cAL;
        bf16* st_t = stbf + (size_t)t * BB * STATED;
        const float* P_t = P + (size_t)t * BB * 1536;
        const float* PE_t = PE + (size_t)t * BB * FEATD;
        const float* eps_t = eps + (size_t)t * BB * STOCHD;

        // ===== GRU: [256 x 2048], K=576, 9 chunks of k64, tile 32x128 =====
        {
            int bx = b & 15, by = b >> 4;
            int r0 = by * 32, c0 = bx * 128;
            int wr = wid >> 2, wc = wid & 3;
            float acc[4][4];
#pragma unroll
            for (int nt = 0; nt < 4; nt++)
#pragma unroll
                for (int q = 0; q < 4; q++) acc[nt][q] = 0.f;

            int arow = tid >> 3, aq = tid & 7;  // 32 rows x 8 q
            uint4 vah, valo, vwh[4], vwl[4];
            vah  = *reinterpret_cast<const uint4*>(cinH + (size_t)(r0 + arow) * STATED + aq * 8);
            valo = *reinterpret_cast<const uint4*>(cinL + (size_t)(r0 + arow) * STATED + aq * 8);
#pragma unroll
            for (int i = 0; i < 4; i++) {
                int u = tid + i * 256, wcol = u >> 3, wq = u & 7;
                vwh[i] = *reinterpret_cast<const uint4*>(WGh + (size_t)(c0 + wcol) * 576 + wq * 8);
                vwl[i] = *reinterpret_cast<const uint4*>(WGl + (size_t)(c0 + wcol) * 576 + wq * 8);
            }
            {
                unsigned* b0 = SM;
                *reinterpret_cast<uint4*>(&b0[arow * 36 + aq * 4]) = vah;
                *reinterpret_cast<uint4*>(&b0[1152 + arow * 36 + aq * 4]) = valo;
#pragma unroll
                for (int i = 0; i < 4; i++) {
                    int u = tid + i * 256, wcol = u >> 3, wq = u & 7;
                    *reinterpret_cast<uint4*>(&b0[2304 + wcol * 36 + wq * 4]) = vwh[i];
                    *reinterpret_cast<uint4*>(&b0[6912 + wcol * 36 + wq * 4]) = vwl[i];
                }
            }
            __syncthreads();
            for (int c = 0; c < 9; c++) {
                const unsigned* base = SM + (c & 1) * 11520;
                if (c < 8) {
                    int k0 = (c + 1) * 64;
                    vah  = *reinterpret_cast<const uint4*>(cinH + (size_t)(r0 + arow) * STATED + k0 + aq * 8);
                    valo = *reinterpret_cast<const uint4*>(cinL + (size_t)(r0 + arow) * STATED + k0 + aq * 8);
#pragma unroll
                    for (int i = 0; i < 4; i++) {
                        int u = tid + i * 256, wcol = u >> 3, wq = u & 7;
                        vwh[i] = *reinterpret_cast<const uint4*>(WGh + (size_t)(c0 + wcol) * 576 + k0 + wq * 8);
                        vwl[i] = *reinterpret_cast<const uint4*>(WGl + (size_t)(c0 + wcol) * 576 + k0 + wq * 8);
                    }
                }
#pragma unroll
                for (int ks = 0; ks < 4; ks++) {
                    unsigned aH[4], aL[4];
                    int r = wr * 16 + g;
                    aH[0] = base[r * 36 + ks * 8 + tg];     aH[1] = base[(r + 8) * 36 + ks * 8 + tg];
                    aH[2] = base[r * 36 + ks * 8 + tg + 4]; aH[3] = base[(r + 8) * 36 + ks * 8 + tg + 4];
                    aL[0] = base[1152 + r * 36 + ks * 8 + tg];     aL[1] = base[1152 + (r + 8) * 36 + ks * 8 + tg];
                    aL[2] = base[1152 + r * 36 + ks * 8 + tg + 4]; aL[3] = base[1152 + (r + 8) * 36 + ks * 8 + tg + 4];
#pragma unroll
                    for (int nt = 0; nt < 4; nt++) {
                        int n = wc * 32 + nt * 8 + g;
                        unsigned bH[2] = { base[2304 + n * 36 + ks * 8 + tg], base[2304 + n * 36 + ks * 8 + tg + 4] };
                        unsigned bL[2] = { base[6912 + n * 36 + ks * 8 + tg], base[6912 + n * 36 + ks * 8 + tg + 4] };
                        mma_bf16(acc[nt], aH, bH);
                        mma_bf16(acc[nt], aL, bH);
                        mma_bf16(acc[nt], aH, bL);
                    }
                }
                if (c < 8) {
                    unsigned* nb = SM + ((c + 1) & 1) * 11520;
                    *reinterpret_cast<uint4*>(&nb[arow * 36 + aq * 4]) = vah;
                    *reinterpret_cast<uint4*>(&nb[1152 + arow * 36 + aq * 4]) = valo;
#pragma unroll
                    for (int i = 0; i < 4; i++) {
                        int u = tid + i * 256, wcol = u >> 3, wq = u & 7;
                        *reinterpret_cast<uint4*>(&nb[2304 + wcol * 36 + wq * 4]) = vwh[i];
                        *reinterpret_cast<uint4*>(&nb[6912 + wcol * 36 + wq * 4]) = vwl[i];
                    }
                }
                __syncthreads();
            }
            // stage raw gates into smem, then block-local GRU epilogue
            float* Cst = (float*)SM;   // 32 x 132
#pragma unroll
            for (int nt = 0; nt < 4; nt++) {
                int cc = wc * 32 + nt * 8 + tg * 2;
                int rr = wr * 16 + g;
                Cst[rr * 132 + cc]           = acc[nt][0];
                Cst[rr * 132 + cc + 1]       = acc[nt][1];
                Cst[(rr + 8) * 132 + cc]     = acc[nt][2];
                Cst[(rr + 8) * 132 + cc + 1] = acc[nt][3];
            }
            __syncthreads();
#pragma unroll
            for (int i = 0; i < 4; i++) {
                int o = tid + i * 256;
                int row = o >> 5, jl = o & 31;
                int gr = r0 + row, j = bx * 32 + jl;
                float rv = Cst[row * 132 + jl];
                float zv = Cst[row * 132 + 32 + jl];
                float nsv = Cst[row * 132 + 64 + jl];
                float nhv = Cst[row * 132 + 96 + jl];
                float rr_ = sigmoidf_(rv + P_t[(size_t)gr * 1536 + j]);
                float zz = sigmoidf_(zv + P_t[(size_t)gr * 1536 + 512 + j]);
                float nn = tanhf(nsv + P_t[(size_t)gr * 1536 + 1024 + j] + rr_ * (nhv + bhh[1024 + j]));
                float hp = __bfloat162float(cinH[(size_t)gr * STATED + 64 + j])
                         + __bfloat162float(cinL[(size_t)gr * STATED + 64 + j]);
                float h = (1.f - zz) * nn + zz * hp;
                bf16 hh, hl; splitw(h, hh, hl);
                coutH[(size_t)gr * STATED + 64 + j] = hh;
                coutL[(size_t)gr * STATED + 64 + j] = hl;
                st_t[(size_t)gr * STATED + j] = __float2bfloat16(h);
            }
        }
        gbar();

        // ===== L0: y1 = elu(h @ W0h^T + PE_t) =====
        {
            int by = b >> 3, bx = b & 7;
            int r0 = by * 16, c0 = bx * 64;
            float acc[4];
            gemm16v(coutH + 64, coutL + 64, STATED, W0hh, W0hl, r0, c0, acc, SM, tid, wid, g, tg);
            int cc = c0 + wid * 8 + tg * 2;
#pragma unroll
            for (int rr = 0; rr < 2; rr++) {
                int gr = r0 + g + rr * 8;
#pragma unroll
                for (int q = 0; q < 2; q++) {
                    float v = eluf(acc[rr * 2 + q] + PE_t[(size_t)gr * 512 + cc + q]);
                    bf16 vh, vl; splitw(v, vh, vl);
                    y1H[(size_t)gr * 512 + cc + q] = vh;
                    y1L[(size_t)gr * 512 + cc + q] = vl;
                }
            }
        }
        gbar();

        // ===== L1: y2 = elu(y1 @ W1^T + b1) =====
        {
            int by = b >> 3, bx = b & 7;
            int r0 = by * 16, c0 = bx * 64;
            float acc[4];
            gemm16v(y1H, y1L, 512, W1h, W1l, r0, c0, acc, SM, tid, wid, g, tg);
            int cc = c0 + wid * 8 + tg * 2;
#pragma unroll
            for (int rr = 0; rr < 2; rr++) {
                int gr = r0 + g + rr * 8;
#pragma unroll
                for (int q = 0; q < 2; q++) {
                    float v = eluf(acc[rr * 2 + q] + b1[cc + q]);
                    bf16 vh, vl; splitw(v, vh, vl);
                    y2H[(size_t)gr * 512 + cc + q] = vh;
                    y2L[(size_t)gr * 512 + cc + q] = vl;
                }
            }
        }
        gbar();

        // ===== L2 + sample =====
        if (b < 32) {
            int by = b >> 1, bx = b & 1;
            int r0 = by * 16, c0 = bx * 64;
            float acc[4];
            gemm16v(y2H, y2L, 512, W2h, W2l, r0, c0, acc, SM, tid, wid, g, tg);
            int cc = c0 + wid * 8 + tg * 2;
            int i_ = cc >> 1;
#pragma unroll
            for (int rr = 0; rr < 2; rr++) {
                int gr = r0 + g + rr * 8;
                float mu = acc[rr * 2] + b2p[cc];
                float sd = softplusf(acc[rr * 2 + 1] + b2p[cc + 1]) + 1e-4f;
                float s = fmaf(sd, eps_t[(size_t)gr * 64 + i_], mu);
                qmu[(size_t)(t * BB + gr) * 64 + i_] = mu;
                qstd[(size_t)(t * BB + gr) * 64 + i_] = sd;
                bf16 sh, sl; splitw(s, sh, sl);
                coutH[(size_t)gr * STATED + i_] = sh;
                coutL[(size_t)gr * STATED + i_] = sl;
                st_t[(size_t)gr * STATED + 512 + i_] = __float2bfloat16(s);
            }
        }
        gbar();
    }
}

// ---------------- misc ----------------
__global__ void e0_l1(const float* __restrict__ ep_b0, const float* __restrict__ ep_W1,
                      const float* __restrict__ ep_b1, float* __restrict__ l1)
{
    __shared__ float x0[512];
    for (int k = threadIdx.x; k < 512; k += 256) x0[k] = eluf(ep_b0[k]);
    __syncthreads();
    for (int o = threadIdx.x; o < 512; o += 256) {
        float v = ep_b1[o];
        for (int k = 0; k < 512; k++) v = fmaf(x0[k], ep_W1[(size_t)o * 512 + k], v);
        l1[o] = eluf(v);
    }
}

__global__ void e0_head(const float* __restrict__ l1, const float* __restrict__ ep_W2,
                        const float* __restrict__ ep_b2, float* __restrict__ e0)
{
    int o = blockIdx.x * 256 + threadIdx.x;
    float v = ep_b2[o];
    for (int k = 0; k < 512; k++) v = fmaf(l1[k], ep_W2[(size_t)o * 512 + k], v);
    e0[o] = v;
}

__global__ void build_pcat(const bf16* __restrict__ stbf, const bf16* __restrict__ Ebf,
                           const bf16* __restrict__ e0bf, bf16* __restrict__ out)
{
    int r = blockIdx.x;
    const bf16* src = (r < 256) ? e0bf : (Ebf + (size_t)(r - 256) * EMBD);
    bf16* o = out + (size_t)r * 1536;
    const bf16* st = stbf + (size_t)r * STATED;
    for (int c = threadIdx.x; c < 1536; c += 256)
        o[c] = (c < 512) ? st[c] : src[c - 512];
}

// ---------------- reductions ----------------
__global__ void zero_acc_k(double* acc) { if (threadIdx.x < 3) acc[threadIdx.x] = 0.0; }

__global__ void kl_reduce_k(const float* __restrict__ praw, const float* __restrict__ qmu,
                            const float* __restrict__ qstd, double* __restrict__ acc)
{
    __shared__ double sh[256];
    double s = 0.0;
    long total = (long)TBD * STOCHD;
    for (long idx = blockIdx.x * (long)blockDim.x + threadIdx.x; idx < total;
         idx += (long)gridDim.x * blockDim.x) {
        int r = (int)(idx >> 6), i = (int)(idx & 63);
        float pmu = praw[(size_t)r * 128 + i];
        float psd = softplusf(praw[(size_t)r * 128 + 64 + i]) + 1e-4f;
        float qm = qmu[idx], qs = qstd[idx];
        float d = qm - pmu;
        s += (double)(logf(psd / qs) + (qs * qs + d * d) / (2.f * psd * psd) - 0.5f);
    }
    sh[threadIdx.x] = s; __syncthreads();
    for (int o = 128; o > 0; o >>= 1) {
        if (threadIdx.x < o) sh[threadIdx.x] += sh[threadIdx.x + o];
        __syncthreads();
    }
    if (threadIdx.x == 0) atomicAdd(acc, sh[0]);
}

__global__ void emb_reduce_k(const float* __restrict__ emb, const float* __restrict__ embmu,
                             double* __restrict__ acc)
{
    __shared__ double sh[256];
    double s = 0.0;
    long total = (long)TBD * EMBD;
    for (long idx = blockIdx.x * (long)blockDim.x + threadIdx.x; idx < total;
         idx += (long)gridDim.x * blockDim.x) {
        float d = emb[idx] - embmu[idx];
        s += (double)(0.5f * d * d + 0.5f * LOG2PI_F);
    }
    sh[threadIdx.x] = s; __syncthreads();
    for (int o = 128; o > 0; o >>= 1) {
        if (threadIdx.x < o) sh[threadIdx.x] += sh[threadIdx.x + o];
        __syncthreads();
    }
    if (threadIdx.x == 0) atomicAdd(acc, sh[0]);
}

__global__ void reward_reduce_k(const bf16* __restrict__ big2, const float* __restrict__ W,
                                const float* __restrict__ bias, const float* __restrict__ reward,
                                double* __restrict__ acc)
{
    __shared__ double sh[8];
    int lane = threadIdx.x & 31, wib = threadIdx.x >> 5;
    int gwarp = (blockIdx.x * blockDim.x + threadIdx.x) >> 5;
    int nwarps = (gridDim.x * blockDim.x) >> 5;
    double local = 0.0;
    for (int r = gwarp; r < TBD; r += nwarps) {
        float sum = 0.f;
        const bf16* row = big2 + (size_t)r * FEATD;
        for (int k = lane; k < FEATD; k += 32)
            sum = fmaf(__bfloat162float(row[k]), W[k], sum);
#pragma unroll
        for (int o = 16; o > 0; o >>= 1) sum += __shfl_xor_sync(0xffffffffu, sum, o);
        if (lane == 0) {
            float d = reward[r] - (sum + bias[0]);
            local += (double)(0.5f * d * d + 0.5f * LOG2PI_F);
        }
    }
    if (lane == 0) sh[wib] = local;
    __syncthreads();
    if (threadIdx.x == 0) {
        double t = 0.0;
        for (int i = 0; i < 8; i++) t += sh[i];
        atomicAdd(acc, t);
    }
}

__global__ void finalize_k(const double* __restrict__ acc, float* __restrict__ out, int n) {
    double inv = 1.0 / (double)(TT * BB);
    float loss = (float)((acc[0] + acc[1] + acc[2]) * inv);
    for (int i = 0; i < n; i++) out[i] = loss;
}

// ---------------- host ----------------
static void* symaddr(const void* sym) {
    void* p = nullptr;
    cudaGetSymbolAddress(&p, sym);
    return p;
}

extern "C" void kernel_launch(void* const* d_in, const int* in_sizes, int n_in,
                              void* d_out, int out_size)
{
    const float* emb     = (const float*)d_in[0];
    const float* action  = (const float*)d_in[1];
    const float* reward  = (const float*)d_in[2];
    const float* eps     = (const float*)d_in[3];
    const float* gru_Wih = (const float*)d_in[4];
    const float* gru_bih = (const float*)d_in[5];
    const float* gru_Whh = (const float*)d_in[6];
    const float* gru_bhh = (const float*)d_in[7];
    const float* st_W0 = (const float*)d_in[8];  const float* st_b0 = (const float*)d_in[9];
    const float* st_W1 = (const float*)d_in[10]; const float* st_b1 = (const float*)d_in[11];
    const float* st_W2 = (const float*)d_in[12]; const float* st_b2 = (const float*)d_in[13];
    const float* ep_W0 = (const float*)d_in[14]; const float* ep_b0 = (const float*)d_in[15];
    const float* ep_W1 = (const float*)d_in[16]; const float* ep_b1 = (const float*)d_in[17];
    const float* ep_W2 = (const float*)d_in[18]; const float* ep_b2 = (const float*)d_in[19];
    const float* rp_W0 = (const float*)d_in[20]; const float* rp_b0 = (const float*)d_in[21];
    const float* rp_W1 = (const float*)d_in[22]; const float* rp_b1 = (const float*)d_in[23];
    const float* rp_W2 = (const float*)d_in[24]; const float* rp_b2 = (const float*)d_in[25];

    float* qmu    = (float*)symaddr(g_qmu);
    float* qstd   = (float*)symaddr(g_qstd);
    float* P      = (float*)symaddr(g_P);
    float* PE     = (float*)symaddr(g_PE);
    float* E      = (float*)symaddr(g_E);
    float* praw   = (float*)symaddr(g_praw);
    float* e0     = (float*)symaddr(g_e0);
    float* e0l1   = (float*)symaddr(g_e0l1);
    float* b2p    = (float*)symaddr(g_b2p);
    double* acc   = (double*)symaddr(g_acc);
    bf16* stbf   = (bf16*)symaddr(g_states_bf);
    bf16* embbf  = (bf16*)symaddr(g_emb_bf);
    bf16* Ebf    = (bf16*)symaddr(g_E_bf);
    bf16* pcatbf = (bf16*)symaddr(g_pcat_bf);
    bf16* big1bf = (bf16*)symaddr(g_big1_bf);
    bf16* big2bf = (bf16*)symaddr(g_big2_bf);
    bf16* e0bf   = (bf16*)symaddr(g_e0_bf);
    bf16* stW0b  = (bf16*)symaddr(g_stW0b);
    bf16* stW1b  = (bf16*)symaddr(g_stW1b);
    bf16* stW2b  = (bf16*)symaddr(g_stW2b);
    bf16* epW0b  = (bf16*)symaddr(g_epW0b);
    bf16* epW1b  = (bf16*)symaddr(g_epW1b);
    bf16* epW2b  = (bf16*)symaddr(g_epW2b);
    bf16* rpW0b  = (bf16*)symaddr(g_rpW0b);
    bf16* rpW1b  = (bf16*)symaddr(g_rpW1b);
    bf16* WGh  = (bf16*)symaddr(g_WGh);   bf16* WGl  = (bf16*)symaddr(g_WGl);
    bf16* W0hh = (bf16*)symaddr(g_W0hh);  bf16* W0hl = (bf16*)symaddr(g_W0hl);
    bf16* W1h  = (bf16*)symaddr(g_W1h);   bf16* W1l  = (bf16*)symaddr(g_W1l);
    bf16* W2h  = (bf16*)symaddr(g_W2h);   bf16* W2l  = (bf16*)symaddr(g_W2l);
    bf16* cAH = (bf16*)symaddr(g_cAH);    bf16* cAL = (bf16*)symaddr(g_cAL);
    bf16* cBH = (bf16*)symaddr(g_cBH);    bf16* cBL = (bf16*)symaddr(g_cBL);
    bf16* zcH = (bf16*)symaddr(g_zcH);    bf16* zcL = (bf16*)symaddr(g_zcL);
    bf16* y1H = (bf16*)symaddr(g_y1H);    bf16* y1L = (bf16*)symaddr(g_y1L);
    bf16* y2H = (bf16*)symaddr(g_y2H);    bf16* y2L = (bf16*)symaddr(g_y2L);

    static bool attr_set = false;
    if (!attr_set) {
        cudaFuncSetAttribute(recur_k, cudaFuncAttributeMaxDynamicSharedMemorySize, 96 * 1024);
        attr_set = true;
    }

    zero_acc_k<<<1, 32>>>(acc);

    // conversions + prep
    cvt_bf_k<<<2048, 256>>>(emb,   embbf, (long)TBD * EMBD);
    cvt_bf_k<<<512, 256>>>(st_W0, stW0b, 512L * 1536);
    cvt_bf_k<<<256, 256>>>(st_W1, stW1b, 512L * 512);
    cvt_bf_k<<<64,  256>>>(st_W2, stW2b, 128L * 512);
    cvt_bf_k<<<256, 256>>>(ep_W0, epW0b, 512L * 576);
    cvt_bf_k<<<256, 256>>>(ep_W1, epW1b, 512L * 512);
    cvt_bf_k<<<512, 256>>>(ep_W2, epW2b, 1024L * 512);
    cvt_bf_k<<<256, 256>>>(rp_W0, rpW0b, 512L * 576);
    cvt_bf_k<<<256, 256>>>(rp_W1, rpW1b, 512L * 512);
    prep_P<<<TBD, 256>>>(action, gru_Wih, gru_bih, gru_bhh, P);
    prep_WG<<<1024, 256>>>(gru_Wih, gru_Whh, WGh, WGl);
    prep_split<<<256, 256>>>(st_W0, 1536, 512, W0hh, W0hl, 512L * 512);
    prep_split<<<256, 256>>>(st_W1, 512, 512, W1h, W1l, 512L * 512);
    prep_W2p<<<64, 256>>>(st_W2, st_b2, W2h, W2l, b2p);
    e0_l1<<<1, 256>>>(ep_b0, ep_W1, ep_b1, e0l1);
    e0_head<<<4, 256>>>(e0l1, ep_W2, ep_b2, e0);
    cvt_bf_k<<<4, 256>>>(e0, e0bf, EMBD);

    // PE = emb_prev @ st_W0[:,512:1536]^T + st_b0   (tensor core, rowShift)
    mma_gemm<0, true, true, false><<<dim3(4, 128), 256>>>(
        embbf, EMBD, stW0b + 512, 1536, st_b0, PE, nullptr, FEATD, EMBD);

    // sequential recurrence: persistent, split-bf16 tensor-core stages
    recur_k<<<NBLK, 256, 92160>>>(WGh, WGl, P, gru_bhh, W0hh, W0hl, PE,
                                  W1h, W1l, st_b1, W2h, W2l, b2p,
                                  eps, qmu, qstd, stbf,
                                  cAH, cAL, cBH, cBL, zcH, zcL,
                                  y1H, y1L, y2H, y2L);

    // shared ep-MLP: E = ep_mlp(states) = emb_mu; row-shifted = pre_emb
    mma_gemm<1, false, false, true><<<dim3(4, 128), 256>>>(
        stbf, STATED, epW0b, STATED, ep_b0, nullptr, big1bf, FEATD, STATED);
    mma_gemm<1, false, false, true><<<dim3(4, 128), 256>>>(
        big1bf, FEATD, epW1b, FEATD, ep_b1, nullptr, big2bf, FEATD, FEATD);
    mma_gemm<0, false, true, true><<<dim3(8, 128), 256>>>(
        big2bf, FEATD, epW2b, FEATD, ep_b2, E, Ebf, EMBD, FEATD);

    // prior path
    build_pcat<<<TBD, 256>>>(stbf, Ebf, e0bf, pcatbf);
    mma_gemm<1, false, false, true><<<dim3(4, 128), 256>>>(
        pcatbf, 1536, stW0b, 1536, st_b0, nullptr, big1bf, FEATD, 1536);
    mma_gemm<1, false, false, true><<<dim3(4, 128), 256>>>(
        big1bf, FEATD, stW1b, FEATD, st_b1, nullptr, big2bf, FEATD, FEATD);
    mma_gemm<0, false, true, false><<<dim3(1, 128), 256>>>(
        big2bf, FEATD, stW2b, FEATD, st_b2, praw, nullptr, 128, FEATD);
    kl_reduce_k<<<1024, 256>>>(praw, qmu, qstd, acc + 0);

    // emb loss
    emb_reduce_k<<<2048, 256>>>(emb, E, acc + 1);

    // reward loss
    mma_gemm<1, false, false, true><<<dim3(4, 128), 256>>>(
        stbf, STATED, rpW0b, STATED, rp_b0, nullptr, big1bf, FEATD, STATED);
    mma_gemm<1, false, false, true><<<dim3(4, 128), 256>>>(
        big1bf, FEATD, rpW1b, FEATD, rp_b1, nullptr, big2bf, FEATD, FEATD);
    reward_reduce_k<<<512, 256>>>(big2bf, rp_W2, rp_b2, reward, acc + 2);

    finalize_k<<<1, 1>>>(acc, (float*)d_out, out_size);
}

// round 10
// speedup vs baseline: 1.3672x; 1.0948x over previous
#include <cuda_runtime.h>
#include <cuda_bf16.h>
#include <math.h>

#define TT 64
#define BB 256
#define EMBD 1024
#define ADIM 6
#define STOCHD 64
#define HIDD 512
#define FEATD 512
#define STATED 576
#define TBD (TT*BB)
#define NBLK 128
#define LOG2PI_F 1.837877066409345483560659472811f
#define LOG2PI_D 1.837877066409345483560659472811

typedef __nv_bfloat16 bf16;

// ---------------- scratch ----------------
__device__ float g_qmu[TBD*STOCHD];
__device__ float g_qstd[TBD*STOCHD];
__device__ float g_PE[TBD*FEATD];
__device__ float g_praw[TBD*2*STOCHD];
__device__ float g_e0[EMBD];
__device__ float g_e0l1[FEATD];
__device__ float g_b2p[128];
__device__ double g_acc[3];
// tree barrier state
__device__ unsigned g_leaf[8*32];
__device__ unsigned g_root2 = 0;
__device__ volatile unsigned g_rel = 0;

// hi/lo carry + intermediates (bf16 pairs)
__device__ bf16 g_cAH[BB*STATED];
__device__ bf16 g_cAL[BB*STATED];
__device__ bf16 g_cBH[BB*STATED];
__device__ bf16 g_cBL[BB*STATED];
__device__ bf16 g_zcH[BB*STATED];   // zero, never written
__device__ bf16 g_zcL[BB*STATED];   // zero, never written
__device__ bf16 g_y1H[BB*FEATD];
__device__ bf16 g_y1L[BB*FEATD];
__device__ bf16 g_y2H[BB*FEATD];
__device__ bf16 g_y2L[BB*FEATD];

__device__ bf16 g_states_bf[TBD*STATED];
__device__ bf16 g_emb_bf[TBD*EMBD];
__device__ bf16 g_E_bf[TBD*EMBD];
__device__ bf16 g_pcat_bf[TBD*1536];
__device__ bf16 g_big1_bf[TBD*FEATD];
__device__ bf16 g_big2_bf[TBD*FEATD];
__device__ bf16 g_e0_bf[EMBD];
__device__ bf16 g_stW0b[512*1536];
__device__ bf16 g_stW1b[512*512];
__device__ bf16 g_stW2b[128*512];
__device__ bf16 g_epW0b[512*576];
__device__ bf16 g_epW1b[512*512];
__device__ bf16 g_epW2b[1024*512];
__device__ bf16 g_rpW0b[512*576];
__device__ bf16 g_rpW1b[512*512];
// split hi/lo weights for the sequential path
__device__ bf16 g_WGh[2048*576];
__device__ bf16 g_WGl[2048*576];
__device__ bf16 g_W0hh[512*512];
__device__ bf16 g_W0hl[512*512];
__device__ bf16 g_W1h[512*512];
__device__ bf16 g_W1l[512*512];
__device__ bf16 g_W2h[128*512];
__device__ bf16 g_W2l[128*512];

// ---------------- math ----------------
__device__ __forceinline__ float softplusf(float x) {
    return fmaxf(x, 0.f) + log1pf(expf(-fabsf(x)));
}
__device__ __forceinline__ float sigmoidf_(float x) { return 1.f / (1.f + expf(-x)); }
__device__ __forceinline__ float eluf(float x) { return x > 0.f ? x : expm1f(x); }
template<int ACT> __device__ __forceinline__ float actf(float v) {
    if (ACT == 1) return eluf(v);
    return v;
}

__device__ __forceinline__ void mma_bf16(float* c, const unsigned* a, const unsigned* b) {
    asm volatile(
        "mma.sync.aligned.m16n8k16.row.col.f32.bf16.bf16.f32 "
        "{%0,%1,%2,%3},{%4,%5,%6,%7},{%8,%9},{%0,%1,%2,%3};"
        : "+f"(c[0]), "+f"(c[1]), "+f"(c[2]), "+f"(c[3])
        : "r"(a[0]), "r"(a[1]), "r"(a[2]), "r"(a[3]), "r"(b[0]), "r"(b[1]));
}

__device__ __forceinline__ void splitw(float v, bf16& h, bf16& l) {
    h = __float2bfloat16(v);
    l = __float2bfloat16(v - __bfloat162float(h));
}

// ---------------- two-level tree grid barrier ----------------
__device__ __forceinline__ void gbar() {
    __syncthreads();
    if (threadIdx.x == 0) {
        unsigned gen = g_rel;          // read BEFORE arrival
        __threadfence();
        int grp = (blockIdx.x >> 4) * 32;   // 8 groups x 16 blocks, 128B-strided counters
        if (atomicAdd(&g_leaf[grp], 1u) == 15u) {
            if (atomicAdd(&g_root2, 1u) == 7u) {
#pragma unroll
                for (int i = 0; i < 8; i++) g_leaf[i * 32] = 0u;
                g_root2 = 0u;
                __threadfence();
                g_rel = gen + 1u;
            }
        }
        while (g_rel == gen) { __nanosleep(32); }
        __threadfence();
    }
    __syncthreads();
}

// ---------------- bf16 tensor-core GEMM (batched; proven) ----------------
// REDUCE: fused emb squared-error reduction against Ef (f32), into racc.
template<int ACT, bool ROWSHIFT, bool WF32, bool WBF, bool REDUCE>
__global__ __launch_bounds__(256, 2) void mma_gemm(
    const bf16* __restrict__ A, int ldA,
    const bf16* __restrict__ W, int ldW,
    const float* __restrict__ bias,
    float* __restrict__ Cf, bf16* __restrict__ Cb, int ldC, int K,
    const float* __restrict__ Ef, double* __restrict__ racc)
{
    __shared__ __align__(16) unsigned As[2][128 * 20];
    __shared__ __align__(16) unsigned Ws[2][128 * 20];
    __shared__ double redsm[256];
    int tid = threadIdx.x, lane = tid & 31, wid = tid >> 5;
    int g = lane >> 2, tg = lane & 3;
    int wr = wid >> 2, wc = wid & 3;
    int row0 = blockIdx.y * 128, col0 = blockIdx.x * 128;

    float acc[4][4][4];
#pragma unroll
    for (int mt = 0; mt < 4; mt++)
#pragma unroll
        for (int nt = 0; nt < 4; nt++)
#pragma unroll
            for (int q = 0; q < 4; q++) acc[mt][nt][q] = 0.f;

    const int nc = K / 32;
    uint4 pa[2], pb[2];
#pragma unroll
    for (int i = 0; i < 2; i++) {
        int u = tid + i * 256, row = u >> 2, q = u & 3;
        int grow = row0 + row;
        if (ROWSHIFT && grow >= 256) grow -= 256;
        pa[i] = *reinterpret_cast<const uint4*>(A + (size_t)grow * ldA + q * 8);
        pb[i] = *reinterpret_cast<const uint4*>(W + (size_t)(col0 + row) * ldW + q * 8);
    }
#pragma unroll
    for (int i = 0; i < 2; i++) {
        int u = tid + i * 256, row = u >> 2, q = u & 3;
        *reinterpret_cast<uint4*>(&As[0][row * 20 + q * 4]) = pa[i];
        *reinterpret_cast<uint4*>(&Ws[0][row * 20 + q * 4]) = pb[i];
    }
    __syncthreads();

    int buf = 0;
    for (int c = 0; c < nc; c++) {
        bool nxt = (c + 1 < nc);
        if (nxt) {
            int k0 = (c + 1) * 32;
#pragma unroll
            for (int i = 0; i < 2; i++) {
                int u = tid + i * 256, row = u >> 2, q = u & 3;
                int grow = row0 + row;
                if (ROWSHIFT && grow >= 256) grow -= 256;
                pa[i] = *reinterpret_cast<const uint4*>(A + (size_t)grow * ldA + k0 + q * 8);
                pb[i] = *reinterpret_cast<const uint4*>(W + (size_t)(col0 + row) * ldW + k0 + q * 8);
            }
        }
        const unsigned* as = As[buf];
        const unsigned* ws = Ws[buf];
#pragma unroll
        for (int ks = 0; ks < 2; ks++) {
            unsigned af[4][4], bfr[4][2];
#pragma unroll
            for (int mt = 0; mt < 4; mt++) {
                int r = wr * 64 + mt * 16 + g;
                af[mt][0] = as[r * 20 + ks * 8 + tg];
                af[mt][1] = as[(r + 8) * 20 + ks * 8 + tg];
                af[mt][2] = as[r * 20 + ks * 8 + tg + 4];
                af[mt][3] = as[(r + 8) * 20 + ks * 8 + tg + 4];
            }
#pragma unroll
            for (int nt = 0; nt < 4; nt++) {
                int n = wc * 32 + nt * 8 + g;
                bfr[nt][0] = ws[n * 20 + ks * 8 + tg];
                bfr[nt][1] = ws[n * 20 + ks * 8 + tg + 4];
            }
#pragma unroll
            for (int mt = 0; mt < 4; mt++)
#pragma unroll
                for (int nt = 0; nt < 4; nt++)
                    mma_bf16(acc[mt][nt], af[mt], bfr[nt]);
        }
        if (nxt) {
            int nb = buf ^ 1;
#pragma unroll
            for (int i = 0; i < 2; i++) {
                int u = tid + i * 256, row = u >> 2, q = u & 3;
                *reinterpret_cast<uint4*>(&As[nb][row * 20 + q * 4]) = pa[i];
                *reinterpret_cast<uint4*>(&Ws[nb][row * 20 + q * 4]) = pb[i];
            }
        }
        __syncthreads();
        buf ^= 1;
    }

    double rsum = 0.0;
#pragma unroll
    for (int mt = 0; mt < 4; mt++) {
        int r = row0 + wr * 64 + mt * 16 + g;
#pragma unroll
        for (int nt = 0; nt < 4; nt++) {
            int cc = col0 + wc * 32 + nt * 8 + tg * 2;
            float b0v = bias[cc], b1v = bias[cc + 1];
            float v00 = actf<ACT>(acc[mt][nt][0] + b0v);
            float v01 = actf<ACT>(acc[mt][nt][1] + b1v);
            float v10 = actf<ACT>(acc[mt][nt][2] + b0v);
            float v11 = actf<ACT>(acc[mt][nt][3] + b1v);
            if (WF32) {
                Cf[(size_t)r * ldC + cc]           = v00;
                Cf[(size_t)r * ldC + cc + 1]       = v01;
                Cf[(size_t)(r + 8) * ldC + cc]     = v10;
                Cf[(size_t)(r + 8) * ldC + cc + 1] = v11;
            }
            if (WBF) {
                Cb[(size_t)r * ldC + cc]           = __float2bfloat16(v00);
                Cb[(size_t)r * ldC + cc + 1]       = __float2bfloat16(v01);
                Cb[(size_t)(r + 8) * ldC + cc]     = __float2bfloat16(v10);
                Cb[(size_t)(r + 8) * ldC + cc + 1] = __float2bfloat16(v11);
            }
            if (REDUCE) {
                float d0 = Ef[(size_t)r * ldC + cc]           - v00;
                float d1 = Ef[(size_t)r * ldC + cc + 1]       - v01;
                float d2 = Ef[(size_t)(r + 8) * ldC + cc]     - v10;
                float d3 = Ef[(size_t)(r + 8) * ldC + cc + 1] - v11;
                rsum += (double)(0.5f * d0 * d0) + (double)(0.5f * d1 * d1)
                      + (double)(0.5f * d2 * d2) + (double)(0.5f * d3 * d3);
            }
        }
    }
    if (REDUCE) {
        redsm[tid] = rsum;
        __syncthreads();
        for (int o = 128; o > 0; o >>= 1) {
            if (tid < o) redsm[tid] += redsm[tid + o];
            __syncthreads();
        }
        if (tid == 0) atomicAdd(racc, redsm[0]);
    }
}

// ---------------- prep ----------------
__global__ void cvt_bf_k(const float* __restrict__ s, bf16* __restrict__ d, long n) {
    for (long i = blockIdx.x * (long)blockDim.x + threadIdx.x; i < n;
         i += (long)gridDim.x * blockDim.x)
        d[i] = __float2bfloat16(s[i]);
}

// gate-interleaved packed GRU weights, split hi/lo.
__global__ void prep_WG(const float* __restrict__ Wih, const float* __restrict__ Whh,
                        bf16* __restrict__ WGh, bf16* __restrict__ WGl)
{
    long total = 2048L * 576;
    for (long idx = blockIdx.x * (long)blockDim.x + threadIdx.x; idx < total;
         idx += (long)gridDim.x * blockDim.x) {
        int c = (int)(idx / 576), k = (int)(idx % 576);
        int jb = c >> 7, gs = (c >> 5) & 3, jl = c & 31, j = jb * 32 + jl;
        float v = 0.f;
        if (gs == 0)      v = (k < 64) ? Wih[j * 70 + k] : Whh[(size_t)j * 512 + k - 64];
        else if (gs == 1) v = (k < 64) ? Wih[(512 + j) * 70 + k] : Whh[(size_t)(512 + j) * 512 + k - 64];
        else if (gs == 2) v = (k < 64) ? Wih[(1024 + j) * 70 + k] : 0.f;
        else              v = (k < 64) ? 0.f : Whh[(size_t)(1024 + j) * 512 + k - 64];
        bf16 h, l; splitw(v, h, l);
        WGh[idx] = h; WGl[idx] = l;
    }
}

__global__ void prep_split(const float* __restrict__ src, int ld, int K,
                           bf16* __restrict__ hi, bf16* __restrict__ lo, long n)
{
    for (long idx = blockIdx.x * (long)blockDim.x + threadIdx.x; idx < n;
         idx += (long)gridDim.x * blockDim.x) {
        int row = (int)(idx / K), k = (int)(idx % K);
        float v = src[(size_t)row * ld + k];
        bf16 h, l; splitw(v, h, l);
        hi[idx] = h; lo[idx] = l;
    }
}

// W2 rows interleaved (mu_i, std_i) pairs + matching bias
__global__ void prep_W2p(const float* __restrict__ W2, const float* __restrict__ b2,
                         bf16* __restrict__ hi, bf16* __restrict__ lo, float* __restrict__ b2p)
{
    long total = 128L * 512;
    for (long idx = blockIdx.x * (long)blockDim.x + threadIdx.x; idx < total;
         idx += (long)gridDim.x * blockDim.x) {
        int c = (int)(idx / 512), k = (int)(idx % 512);
        int sr = (c & 1) ? (64 + (c >> 1)) : (c >> 1);
        float v = W2[(size_t)sr * 512 + k];
        bf16 h, l; splitw(v, h, l);
        hi[idx] = h; lo[idx] = l;
        if (k == 0) b2p[c] = b2[sr];
    }
}

// ---------------- 16x64-tile split-bf16 MMA, K=512, k64 chunks, dbl-buffered ----------------
__device__ __forceinline__ void gemm16v(
    const bf16* __restrict__ AH, const bf16* __restrict__ AL, int ldA,
    const bf16* __restrict__ WH, const bf16* __restrict__ WL,
    int r0, int c0, float* acc, unsigned* SM,
    int tid, int wid, int g, int tg)
{
    acc[0] = acc[1] = acc[2] = acc[3] = 0.f;
    int arow = (tid & 127) >> 3, aq = tid & 7;
    const bf16* Asrc = (tid < 128) ? AH : AL;
    int adst = (tid < 128) ? 0 : 576;
    uint4 va, vw[2][2];
    va = *reinterpret_cast<const uint4*>(Asrc + (size_t)(r0 + arow) * ldA + aq * 8);
#pragma unroll
    for (int i = 0; i < 2; i++) {
        int u = tid + i * 256, wcol = u >> 3, wq = u & 7;
        vw[i][0] = *reinterpret_cast<const uint4*>(WH + (size_t)(c0 + wcol) * 512 + wq * 8);
        vw[i][1] = *reinterpret_cast<const uint4*>(WL + (size_t)(c0 + wcol) * 512 + wq * 8);
    }
    {
        unsigned* b0 = SM;
        *reinterpret_cast<uint4*>(&b0[adst + arow * 36 + aq * 4]) = va;
#pragma unroll
        for (int i = 0; i < 2; i++) {
            int u = tid + i * 256, wcol = u >> 3, wq = u & 7;
            *reinterpret_cast<uint4*>(&b0[1152 + wcol * 36 + wq * 4]) = vw[i][0];
            *reinterpret_cast<uint4*>(&b0[3456 + wcol * 36 + wq * 4]) = vw[i][1];
        }
    }
    __syncthreads();
    for (int c = 0; c < 8; c++) {
        const unsigned* base = SM + (c & 1) * 5760;
        if (c < 7) {
            int k0 = (c + 1) * 64;
            va = *reinterpret_cast<const uint4*>(Asrc + (size_t)(r0 + arow) * ldA + k0 + aq * 8);
#pragma unroll
            for (int i = 0; i < 2; i++) {
                int u = tid + i * 256, wcol = u >> 3, wq = u & 7;
                vw[i][0] = *reinterpret_cast<const uint4*>(WH + (size_t)(c0 + wcol) * 512 + k0 + wq * 8);
                vw[i][1] = *reinterpret_cast<const uint4*>(WL + (size_t)(c0 + wcol) * 512 + k0 + wq * 8);
            }
        }
#pragma unroll
        for (int ks = 0; ks < 4; ks++) {
            unsigned aH[4], aL[4], bH[2], bL[2];
            aH[0] = base[g * 36 + ks * 8 + tg];       aH[1] = base[(g + 8) * 36 + ks * 8 + tg];
            aH[2] = base[g * 36 + ks * 8 + tg + 4];   aH[3] = base[(g + 8) * 36 + ks * 8 + tg + 4];
            aL[0] = base[576 + g * 36 + ks * 8 + tg];     aL[1] = base[576 + (g + 8) * 36 + ks * 8 + tg];
            aL[2] = base[576 + g * 36 + ks * 8 + tg + 4]; aL[3] = base[576 + (g + 8) * 36 + ks * 8 + tg + 4];
            int n = wid * 8 + g;
            bH[0] = base[1152 + n * 36 + ks * 8 + tg]; bH[1] = base[1152 + n * 36 + ks * 8 + tg + 4];
            bL[0] = base[3456 + n * 36 + ks * 8 + tg]; bL[1] = base[3456 + n * 36 + ks * 8 + tg + 4];
            mma_bf16(acc, aH, bH);
            mma_bf16(acc, aL, bH);
            mma_bf16(acc, aH, bL);
        }
        if (c < 7) {
            unsigned* nb = SM + ((c + 1) & 1) * 5760;
            *reinterpret_cast<uint4*>(&nb[adst + arow * 36 + aq * 4]) = va;
#pragma unroll
            for (int i = 0; i < 2; i++) {
                int u = tid + i * 256, wcol = u >> 3, wq = u & 7;
                *reinterpret_cast<uint4*>(&nb[1152 + wcol * 36 + wq * 4]) = vw[i][0];
                *reinterpret_cast<uint4*>(&nb[3456 + wcol * 36 + wq * 4]) = vw[i][1];
            }
        }
        __syncthreads();
    }
}

// ---------------- persistent sequential recurrence ----------------
extern __shared__ unsigned SMd[];

__global__ __launch_bounds__(256, 1) void recur_k(
    const bf16* __restrict__ WGh, const bf16* __restrict__ WGl,
    const float* __restrict__ action, const float* __restrict__ Wih,
    const float* __restrict__ bih, const float* __restrict__ bhh,
    const bf16* __restrict__ W0hh, const bf16* __restrict__ W0hl, const float* __restrict__ PE,
    const bf16* __restrict__ W1h, const bf16* __restrict__ W1l, const float* __restrict__ b1,
    const bf16* __restrict__ W2h, const bf16* __restrict__ W2l, const float* __restrict__ b2p,
    const float* __restrict__ eps, float* __restrict__ qmu, float* __restrict__ qstd,
    bf16* __restrict__ stbf,
    bf16* __restrict__ cAH, bf16* __restrict__ cAL,
    bf16* __restrict__ cBH, bf16* __restrict__ cBL,
    const bf16* __restrict__ zcH, const bf16* __restrict__ zcL,
    bf16* __restrict__ y1H, bf16* __restrict__ y1L,
    bf16* __restrict__ y2H, bf16* __restrict__ y2L)
{
    unsigned* SM = SMd;
    int b = blockIdx.x, tid = threadIdx.x, lane = tid & 31, wid = tid >> 5;
    int g = lane >> 2, tg = lane & 3;

    for (int t = 0; t < TT; t++) {
        const bf16* cinH = (t == 0) ? zcH : ((t & 1) ? cBH : cAH);
        const bf16* cinL = (t == 0) ? zcL : ((t & 1) ? cBL : cAL);
        bf16* coutH = ((t + 1) & 1) ? cBH : cAH;
        bf16* coutL = ((t + 1) & 1) ? cBL : cAL;
        bf16* st_t = stbf + (size_t)t * BB * STATED;
        const float* a_t = action + (size_t)t * BB * ADIM;
        const float* PE_t = PE + (size_t)t * BB * FEATD;
        const float* eps_t = eps + (size_t)t * BB * STOCHD;

        // ===== GRU: [256 x 2048], K=576, 9 chunks of k64, tile 32x128 =====
        {
            int bx = b & 15, by = b >> 4;
            int r0 = by * 32, c0 = bx * 128;
            int wr = wid >> 2, wc = wid & 3;
            float acc[4][4];
#pragma unroll
            for (int nt = 0; nt < 4; nt++)
#pragma unroll
                for (int q = 0; q < 4; q++) acc[nt][q] = 0.f;

            int arow = tid >> 3, aq = tid & 7;  // 32 rows x 8 q
            uint4 vah, valo, vwh[4], vwl[4];
            vah  = *reinterpret_cast<const uint4*>(cinH + (size_t)(r0 + arow) * STATED + aq * 8);
            valo = *reinterpret_cast<const uint4*>(cinL + (size_t)(r0 + arow) * STATED + aq * 8);
#pragma unroll
            for (int i = 0; i < 4; i++) {
                int u = tid + i * 256, wcol = u >> 3, wq = u & 7;
                vwh[i] = *reinterpret_cast<const uint4*>(WGh + (size_t)(c0 + wcol) * 576 + wq * 8);
                vwl[i] = *reinterpret_cast<const uint4*>(WGl + (size_t)(c0 + wcol) * 576 + wq * 8);
            }
            {
                unsigned* b0 = SM;
                *reinterpret_cast<uint4*>(&b0[arow * 36 + aq * 4]) = vah;
                *reinterpret_cast<uint4*>(&b0[1152 + arow * 36 + aq * 4]) = valo;
#pragma unroll
                for (int i = 0; i < 4; i++) {
                    int u = tid + i * 256, wcol = u >> 3, wq = u & 7;
                    *reinterpret_cast<uint4*>(&b0[2304 + wcol * 36 + wq * 4]) = vwh[i];
                    *reinterpret_cast<uint4*>(&b0[6912 + wcol * 36 + wq * 4]) = vwl[i];
                }
            }
            __syncthreads();
            for (int c = 0; c < 9; c++) {
                const unsigned* base = SM + (c & 1) * 11520;
                if (c < 8) {
                    int k0 = (c + 1) * 64;
                    vah  = *reinterpret_cast<const uint4*>(cinH + (size_t)(r0 + arow) * STATED + k0 + aq * 8);
                    valo = *reinterpret_cast<const uint4*>(cinL + (size_t)(r0 + arow) * STATED + k0 + aq * 8);
#pragma unroll
                    for (int i = 0; i < 4; i++) {
                        int u = tid + i * 256, wcol = u >> 3, wq = u & 7;
                        vwh[i] = *reinterpret_cast<const uint4*>(WGh + (size_t)(c0 + wcol) * 576 + k0 + wq * 8);
                        vwl[i] = *reinterpret_cast<const uint4*>(WGl + (size_t)(c0 + wcol) * 576 + k0 + wq * 8);
                    }
                }
#pragma unroll
                for (int ks = 0; ks < 4; ks++) {
                    unsigned aH[4], aL[4];
                    int r = wr * 16 + g;
                    aH[0] = base[r * 36 + ks * 8 + tg];     aH[1] = base[(r + 8) * 36 + ks * 8 + tg];
                    aH[2] = base[r * 36 + ks * 8 + tg + 4]; aH[3] = base[(r + 8) * 36 + ks * 8 + tg + 4];
                    aL[0] = base[1152 + r * 36 + ks * 8 + tg];     aL[1] = base[1152 + (r + 8) * 36 + ks * 8 + tg];
                    aL[2] = base[1152 + r * 36 + ks * 8 + tg + 4]; aL[3] = base[1152 + (r + 8) * 36 + ks * 8 + tg + 4];
#pragma unroll
                    for (int nt = 0; nt < 4; nt++) {
                        int n = wc * 32 + nt * 8 + g;
                        unsigned bH[2] = { base[2304 + n * 36 + ks * 8 + tg], base[2304 + n * 36 + ks * 8 + tg + 4] };
                        unsigned bL[2] = { base[6912 + n * 36 + ks * 8 + tg], base[6912 + n * 36 + ks * 8 + tg + 4] };
                        mma_bf16(acc[nt], aH, bH);
                        mma_bf16(acc[nt], aL, bH);
                        mma_bf16(acc[nt], aH, bL);
                    }
                }
                if (c < 8) {
                    unsigned* nb = SM + ((c + 1) & 1) * 11520;
                    *reinterpret_cast<uint4*>(&nb[arow * 36 + aq * 4]) = vah;
                    *reinterpret_cast<uint4*>(&nb[1152 + arow * 36 + aq * 4]) = valo;
#pragma unroll
                    for (int i = 0; i < 4; i++) {
                        int u = tid + i * 256, wcol = u >> 3, wq = u & 7;
                        *reinterpret_cast<uint4*>(&nb[2304 + wcol * 36 + wq * 4]) = vwh[i];
                        *reinterpret_cast<uint4*>(&nb[6912 + wcol * 36 + wq * 4]) = vwl[i];
                    }
                }
                __syncthreads();
            }
            // stage raw gates into smem, then block-local GRU epilogue (P on-the-fly)
            float* Cst = (float*)SM;   // 32 x 132
#pragma unroll
            for (int nt = 0; nt < 4; nt++) {
                int cc = wc * 32 + nt * 8 + tg * 2;
                int rr = wr * 16 + g;
                Cst[rr * 132 + cc]           = acc[nt][0];
                Cst[rr * 132 + cc + 1]       = acc[nt][1];
                Cst[(rr + 8) * 132 + cc]     = acc[nt][2];
                Cst[(rr + 8) * 132 + cc + 1] = acc[nt][3];
            }
            __syncthreads();
#pragma unroll
            for (int i = 0; i < 4; i++) {
                int o = tid + i * 256;
                int row = o >> 5, jl = o & 31;
                int gr = r0 + row, j = bx * 32 + jl;
                float rv = Cst[row * 132 + jl];
                float zv = Cst[row * 132 + 32 + jl];
                float nsv = Cst[row * 132 + 64 + jl];
                float nhv = Cst[row * 132 + 96 + jl];
                float a0 = a_t[gr * ADIM], a1 = a_t[gr * ADIM + 1], a2 = a_t[gr * ADIM + 2];
                float a3 = a_t[gr * ADIM + 3], a4 = a_t[gr * ADIM + 4], a5 = a_t[gr * ADIM + 5];
                // pr: bih[j] + a·Wih[j,64:70] + bhh[j]   (same fp order as old prep_P)
                const float* wr0 = Wih + (size_t)j * 70 + 64;
                float pr = bih[j];
                pr = fmaf(a0, wr0[0], pr); pr = fmaf(a1, wr0[1], pr); pr = fmaf(a2, wr0[2], pr);
                pr = fmaf(a3, wr0[3], pr); pr = fmaf(a4, wr0[4], pr); pr = fmaf(a5, wr0[5], pr);
                pr += bhh[j];
                const float* wz0 = Wih + (size_t)(512 + j) * 70 + 64;
                float pz = bih[512 + j];
                pz = fmaf(a0, wz0[0], pz); pz = fmaf(a1, wz0[1], pz); pz = fmaf(a2, wz0[2], pz);
                pz = fmaf(a3, wz0[3], pz); pz = fmaf(a4, wz0[4], pz); pz = fmaf(a5, wz0[5], pz);
                pz += bhh[512 + j];
                const float* wn0 = Wih + (size_t)(1024 + j) * 70 + 64;
                float pn = bih[1024 + j];
                pn = fmaf(a0, wn0[0], pn); pn = fmaf(a1, wn0[1], pn); pn = fmaf(a2, wn0[2], pn);
                pn = fmaf(a3, wn0[3], pn); pn = fmaf(a4, wn0[4], pn); pn = fmaf(a5, wn0[5], pn);
                float rr_ = sigmoidf_(rv + pr);
                float zz = sigmoidf_(zv + pz);
                float nn = tanhf(nsv + pn + rr_ * (nhv + bhh[1024 + j]));
                float hp = __bfloat162float(cinH[(size_t)gr * STATED + 64 + j])
                         + __bfloat162float(cinL[(size_t)gr * STATED + 64 + j]);
                float h = (1.f - zz) * nn + zz * hp;
                bf16 hh, hl; splitw(h, hh, hl);
                coutH[(size_t)gr * STATED + 64 + j] = hh;
                coutL[(size_t)gr * STATED + 64 + j] = hl;
                st_t[(size_t)gr * STATED + j] = __float2bfloat16(h);
            }
        }
        gbar();

        // ===== L0: y1 = elu(h @ W0h^T + PE_t) =====
        {
            int by = b >> 3, bx = b & 7;
            int r0 = by * 16, c0 = bx * 64;
            float acc[4];
            gemm16v(coutH + 64, coutL + 64, STATED, W0hh, W0hl, r0, c0, acc, SM, tid, wid, g, tg);
            int cc = c0 + wid * 8 + tg * 2;
#pragma unroll
            for (int rr = 0; rr < 2; rr++) {
                int gr = r0 + g + rr * 8;
#pragma unroll
                for (int q = 0; q < 2; q++) {
                    float v = eluf(acc[rr * 2 + q] + PE_t[(size_t)gr * 512 + cc + q]);
                    bf16 vh, vl; splitw(v, vh, vl);
                    y1H[(size_t)gr * 512 + cc + q] = vh;
                    y1L[(size_t)gr * 512 + cc + q] = vl;
                }
            }
        }
        gbar();

        // ===== L1: y2 = elu(y1 @ W1^T + b1) =====
        {
            int by = b >> 3, bx = b & 7;
            int r0 = by * 16, c0 = bx * 64;
            float acc[4];
            gemm16v(y1H, y1L, 512, W1h, W1l, r0, c0, acc, SM, tid, wid, g, tg);
            int cc = c0 + wid * 8 + tg * 2;
#pragma unroll
            for (int rr = 0; rr < 2; rr++) {
                int gr = r0 + g + rr * 8;
#pragma unroll
                for (int q = 0; q < 2; q++) {
                    float v = eluf(acc[rr * 2 + q] + b1[cc + q]);
                    bf16 vh, vl; splitw(v, vh, vl);
                    y2H[(size_t)gr * 512 + cc + q] = vh;
                    y2L[(size_t)gr * 512 + cc + q] = vl;
                }
            }
        }
        gbar();

        // ===== L2 + sample =====
        if (b < 32) {
            int by = b >> 1, bx = b & 1;
            int r0 = by * 16, c0 = bx * 64;
            float acc[4];
            gemm16v(y2H, y2L, 512, W2h, W2l, r0, c0, acc, SM, tid, wid, g, tg);
            int cc = c0 + wid * 8 + tg * 2;
            int i_ = cc >> 1;
#pragma unroll
            for (int rr = 0; rr < 2; rr++) {
                int gr = r0 + g + rr * 8;
                float mu = acc[rr * 2] + b2p[cc];
                float sd = softplusf(acc[rr * 2 + 1] + b2p[cc + 1]) + 1e-4f;
                float s = fmaf(sd, eps_t[(size_t)gr * 64 + i_], mu);
                qmu[(size_t)(t * BB + gr) * 64 + i_] = mu;
                qstd[(size_t)(t * BB + gr) * 64 + i_] = sd;
                bf16 sh, sl; splitw(s, sh, sl);
                coutH[(size_t)gr * STATED + i_] = sh;
                coutL[(size_t)gr * STATED + i_] = sl;
                st_t[(size_t)gr * STATED + 512 + i_] = __float2bfloat16(s);
            }
        }
        gbar();
    }
}

// ---------------- misc ----------------
__global__ void e0_l1(const float* __restrict__ ep_b0, const float* __restrict__ ep_W1,
                      const float* __restrict__ ep_b1, float* __restrict__ l1)
{
    __shared__ float x0[512];
    for (int k = threadIdx.x; k < 512; k += 256) x0[k] = eluf(ep_b0[k]);
    __syncthreads();
    for (int o = threadIdx.x; o < 512; o += 256) {
        float v = ep_b1[o];
        for (int k = 0; k < 512; k++) v = fmaf(x0[k], ep_W1[(size_t)o * 512 + k], v);
        l1[o] = eluf(v);
    }
}

__global__ void e0_head(const float* __restrict__ l1, const float* __restrict__ ep_W2,
                        const float* __restrict__ ep_b2, float* __restrict__ e0)
{
    int o = blockIdx.x * 256 + threadIdx.x;
    float v = ep_b2[o];
    for (int k = 0; k < 512; k++) v = fmaf(l1[k], ep_W2[(size_t)o * 512 + k], v);
    e0[o] = v;
}

__global__ void build_pcat(const bf16* __restrict__ stbf, const bf16* __restrict__ Ebf,
                           const bf16* __restrict__ e0bf, bf16* __restrict__ out)
{
    int r = blockIdx.x;
    const bf16* src = (r < 256) ? e0bf : (Ebf + (size_t)(r - 256) * EMBD);
    bf16* o = out + (size_t)r * 1536;
    const bf16* st = stbf + (size_t)r * STATED;
    for (int c = threadIdx.x; c < 1536; c += 256)
        o[c] = (c < 512) ? st[c] : src[c - 512];
}

// ---------------- reductions ----------------
__global__ void zero_acc_k(double* acc) {
    if (threadIdx.x < 3) acc[threadIdx.x] = 0.0;
    if (threadIdx.x < 8) g_leaf[threadIdx.x * 32] = 0u;
    if (threadIdx.x == 0) { g_root2 = 0u; g_rel = 0u; }
}

__global__ void kl_reduce_k(const float* __restrict__ praw, const float* __restrict__ qmu,
                            const float* __restrict__ qstd, double* __restrict__ acc)
{
    __shared__ double sh[256];
    double s = 0.0;
    long total = (long)TBD * STOCHD;
    for (long idx = blockIdx.x * (long)blockDim.x + threadIdx.x; idx < total;
         idx += (long)gridDim.x * blockDim.x) {
        int r = (int)(idx >> 6), i = (int)(idx & 63);
        float pmu = praw[(size_t)r * 128 + i];
        float psd = softplusf(praw[(size_t)r * 128 + 64 + i]) + 1e-4f;
        float qm = qmu[idx], qs = qstd[idx];
        float d = qm - pmu;
        s += (double)(logf(psd / qs) + (qs * qs + d * d) / (2.f * psd * psd) - 0.5f);
    }
    sh[threadIdx.x] = s; __syncthreads();
    for (int o = 128; o > 0; o >>= 1) {
        if (threadIdx.x < o) sh[threadIdx.x] += sh[threadIdx.x + o];
        __syncthreads();
    }
    if (threadIdx.x == 0) atomicAdd(acc, sh[0]);
}

__global__ void reward_reduce_k(const bf16* __restrict__ big2, const float* __restrict__ W,
                                const float* __restrict__ bias, const float* __restrict__ reward,
                                double* __restrict__ acc)
{
    __shared__ double sh[8];
    int lane = threadIdx.x & 31, wib = threadIdx.x >> 5;
    int gwarp = (blockIdx.x * blockDim.x + threadIdx.x) >> 5;
    int nwarps = (gridDim.x * blockDim.x) >> 5;
    double local = 0.0;
    for (int r = gwarp; r < TBD; r += nwarps) {
        float sum = 0.f;
        const bf16* row = big2 + (size_t)r * FEATD;
        for (int k = lane; k < FEATD; k += 32)
            sum = fmaf(__bfloat162float(row[k]), W[k], sum);
#pragma unroll
        for (int o = 16; o > 0; o >>= 1) sum += __shfl_xor_sync(0xffffffffu, sum, o);
        if (lane == 0) {
            float d = reward[r] - (sum + bias[0]);
            local += (double)(0.5f * d * d + 0.5f * LOG2PI_F);
        }
    }
    if (lane == 0) sh[wib] = local;
    __syncthreads();
    if (threadIdx.x == 0) {
        double t = 0.0;
        for (int i = 0; i < 8; i++) t += sh[i];
        atomicAdd(acc, t);
    }
}

__global__ void finalize_k(const double* __restrict__ acc, float* __restrict__ out, int n) {
    double inv = 1.0 / (double)(TT * BB);
    // emb constant: TBD*EMBD elements of 0.5*log2pi, /(T*B) = EMBD*0.5*log2pi
    double loss = (acc[0] + acc[1] + acc[2]) * inv + (double)EMBD * 0.5 * LOG2PI_D;
    float lf = (float)loss;
    for (int i = 0; i < n; i++) out[i] = lf;
}

// ---------------- host ----------------
static void* symaddr(const void* sym) {
    void* p = nullptr;
    cudaGetSymbolAddress(&p, sym);
    return p;
}

extern "C" void kernel_launch(void* const* d_in, const int* in_sizes, int n_in,
                              void* d_out, int out_size)
{
    const float* emb     = (const float*)d_in[0];
    const float* action  = (const float*)d_in[1];
    const float* reward  = (const float*)d_in[2];
    const float* eps     = (const float*)d_in[3];
    const float* gru_Wih = (const float*)d_in[4];
    const float* gru_bih = (const float*)d_in[5];
    const float* gru_Whh = (const float*)d_in[6];
    const float* gru_bhh = (const float*)d_in[7];
    const float* st_W0 = (const float*)d_in[8];  const float* st_b0 = (const float*)d_in[9];
    const float* st_W1 = (const float*)d_in[10]; const float* st_b1 = (const float*)d_in[11];
    const float* st_W2 = (const float*)d_in[12]; const float* st_b2 = (const float*)d_in[13];
    const float* ep_W0 = (const float*)d_in[14]; const float* ep_b0 = (const float*)d_in[15];
    const float* ep_W1 = (const float*)d_in[16]; const float* ep_b1 = (const float*)d_in[17];
    const float* ep_W2 = (const float*)d_in[18]; const float* ep_b2 = (const float*)d_in[19];
    const float* rp_W0 = (const float*)d_in[20]; const float* rp_b0 = (const float*)d_in[21];
    const float* rp_W1 = (const float*)d_in[22]; const float* rp_b1 = (const float*)d_in[23];
    const float* rp_W2 = (const float*)d_in[24]; const float* rp_b2 = (const float*)d_in[25];

    float* qmu    = (float*)symaddr(g_qmu);
    float* qstd   = (float*)symaddr(g_qstd);
    float* PE     = (float*)symaddr(g_PE);
    float* praw   = (float*)symaddr(g_praw);
    float* e0     = (float*)symaddr(g_e0);
    float* e0l1   = (float*)symaddr(g_e0l1);
    float* b2p    = (float*)symaddr(g_b2p);
    double* acc   = (double*)symaddr(g_acc);
    bf16* stbf   = (bf16*)symaddr(g_states_bf);
    bf16* embbf  = (bf16*)symaddr(g_emb_bf);
    bf16* Ebf    = (bf16*)symaddr(g_E_bf);
    bf16* pcatbf = (bf16*)symaddr(g_pcat_bf);
    bf16* big1bf = (bf16*)symaddr(g_big1_bf);
    bf16* big2bf = (bf16*)symaddr(g_big2_bf);
    bf16* e0bf   = (bf16*)symaddr(g_e0_bf);
    bf16* stW0b  = (bf16*)symaddr(g_stW0b);
    bf16* stW1b  = (bf16*)symaddr(g_stW1b);
    bf16* stW2b  = (bf16*)symaddr(g_stW2b);
    bf16* epW0b  = (bf16*)symaddr(g_epW0b);
    bf16* epW1b  = (bf16*)symaddr(g_epW1b);
    bf16* epW2b  = (bf16*)symaddr(g_epW2b);
    bf16* rpW0b  = (bf16*)symaddr(g_rpW0b);
    bf16* rpW1b  = (bf16*)symaddr(g_rpW1b);
    bf16* WGh  = (bf16*)symaddr(g_WGh);   bf16* WGl  = (bf16*)symaddr(g_WGl);
    bf16* W0hh = (bf16*)symaddr(g_W0hh);  bf16* W0hl = (bf16*)symaddr(g_W0hl);
    bf16* W1h  = (bf16*)symaddr(g_W1h);   bf16* W1l  = (bf16*)symaddr(g_W1l);
    bf16* W2h  = (bf16*)symaddr(g_W2h);   bf16* W2l  = (bf16*)symaddr(g_W2l);
    bf16* cAH = (bf16*)symaddr(g_cAH);    bf16* cAL = (bf16*)symaddr(g_cAL);
    bf16* cBH = (bf16*)symaddr(g_cBH);    bf16* cBL = (bf16*)symaddr(g_cBL);
    bf16* zcH = (bf16*)symaddr(g_zcH);    bf16* zcL = (bf16*)symaddr(g_zcL);
    bf16* y1H = (bf16*)symaddr(g_y1H);    bf16* y1L = (bf16*)symaddr(g_y1L);
    bf16* y2H = (bf16*)symaddr(g_y2H);    bf16* y2L = (bf16*)symaddr(g_y2L);

    static bool attr_set = false;
    if (!attr_set) {
        cudaFuncSetAttribute(recur_k, cudaFuncAttributeMaxDynamicSharedMemorySize, 96 * 1024);
        attr_set = true;
    }

    zero_acc_k<<<1, 32>>>(acc);

    // conversions + prep
    cvt_bf_k<<<2048, 256>>>(emb,   embbf, (long)TBD * EMBD);
    cvt_bf_k<<<512, 256>>>(st_W0, stW0b, 512L * 1536);
    cvt_bf_k<<<256, 256>>>(st_W1, stW1b, 512L * 512);
    cvt_bf_k<<<64,  256>>>(st_W2, stW2b, 128L * 512);
    cvt_bf_k<<<256, 256>>>(ep_W0, epW0b, 512L * 576);
    cvt_bf_k<<<256, 256>>>(ep_W1, epW1b, 512L * 512);
    cvt_bf_k<<<512, 256>>>(ep_W2, epW2b, 1024L * 512);
    cvt_bf_k<<<256, 256>>>(rp_W0, rpW0b, 512L * 576);
    cvt_bf_k<<<256, 256>>>(rp_W1, rpW1b, 512L * 512);
    prep_WG<<<1024, 256>>>(gru_Wih, gru_Whh, WGh, WGl);
    prep_split<<<256, 256>>>(st_W0, 1536, 512, W0hh, W0hl, 512L * 512);
    prep_split<<<256, 256>>>(st_W1, 512, 512, W1h, W1l, 512L * 512);
    prep_W2p<<<64, 256>>>(st_W2, st_b2, W2h, W2l, b2p);
    e0_l1<<<1, 256>>>(ep_b0, ep_W1, ep_b1, e0l1);
    e0_head<<<4, 256>>>(e0l1, ep_W2, ep_b2, e0);
    cvt_bf_k<<<4, 256>>>(e0, e0bf, EMBD);

    // PE = emb_prev @ st_W0[:,512:1536]^T + st_b0   (tensor core, rowShift)
    mma_gemm<0, true, true, false, false><<<dim3(4, 128), 256>>>(
        embbf, EMBD, stW0b + 512, 1536, st_b0, PE, nullptr, FEATD, EMBD, nullptr, nullptr);

    // sequential recurrence: persistent, split-bf16 tensor-core stages
    recur_k<<<NBLK, 256, 92160>>>(WGh, WGl, action, gru_Wih, gru_bih, gru_bhh,
                                  W0hh, W0hl, PE,
                                  W1h, W1l, st_b1, W2h, W2l, b2p,
                                  eps, qmu, qstd, stbf,
                                  cAH, cAL, cBH, cBL, zcH, zcL,
                                  y1H, y1L, y2H, y2L);

    // shared ep-MLP: E = ep_mlp(states); head epilogue fuses emb loss (acc[1])
    mma_gemm<1, false, false, true, false><<<dim3(4, 128), 256>>>(
        stbf, STATED, epW0b, STATED, ep_b0, nullptr, big1bf, FEATD, STATED, nullptr, nullptr);
    mma_gemm<1, false, false, true, false><<<dim3(4, 128), 256>>>(
        big1bf, FEATD, epW1b, FEATD, ep_b1, nullptr, big2bf, FEATD, FEATD, nullptr, nullptr);
    mma_gemm<0, false, false, true, true><<<dim3(8, 128), 256>>>(
        big2bf, FEATD, epW2b, FEATD, ep_b2, nullptr, Ebf, EMBD, FEATD, emb, acc + 1);

    // prior path
    build_pcat<<<TBD, 256>>>(stbf, Ebf, e0bf, pcatbf);
    mma_gemm<1, false, false, true, false><<<dim3(4, 128), 256>>>(
        pcatbf, 1536, stW0b, 1536, st_b0, nullptr, big1bf, FEATD, 1536, nullptr, nullptr);
    mma_gemm<1, false, false, true, false><<<dim3(4, 128), 256>>>(
        big1bf, FEATD, stW1b, FEATD, st_b1, nullptr, big2bf, FEATD, FEATD, nullptr, nullptr);
    mma_gemm<0, false, true, false, false><<<dim3(1, 128), 256>>>(
        big2bf, FEATD, stW2b, FEATD, st_b2, praw, nullptr, 128, FEATD, nullptr, nullptr);
    kl_reduce_k<<<1024, 256>>>(praw, qmu, qstd, acc + 0);

    // reward loss
    mma_gemm<1, false, false, true, false><<<dim3(4, 128), 256>>>(
        stbf, STATED, rpW0b, STATED, rp_b0, nullptr, big1bf, FEATD, STATED, nullptr, nullptr);
    mma_gemm<1, false, false, true, false><<<dim3(4, 128), 256>>>(
        big1bf, FEATD, rpW1b, FEATD, rp_b1, nullptr, big2bf, FEATD, FEATD, nullptr, nullptr);
    reward_reduce_k<<<512, 256>>>(big2bf, rp_W2, rp_b2, reward, acc + 2);

    finalize_k<<<1, 1>>>(acc, (float*)d_out, out_size);
}

// round 11
// speedup vs baseline: 1.4300x; 1.0460x over previous
#include <cuda_runtime.h>
#include <cuda_bf16.h>
#include <math.h>

#define TT 64
#define BB 256
#define EMBD 1024
#define ADIM 6
#define STOCHD 64
#define HIDD 512
#define FEATD 512
#define STATED 576
#define TBD (TT*BB)
#define NBLK 128
#define LOG2PI_F 1.837877066409345483560659472811f
#define LOG2PI_D 1.837877066409345483560659472811

typedef __nv_bfloat16 bf16;

// ---------------- scratch ----------------
__device__ float g_qmu[TBD*STOCHD];
__device__ float g_qstd[TBD*STOCHD];
__device__ float g_PE[TBD*FEATD];
__device__ float g_praw[TBD*2*STOCHD];
__device__ float g_e0[EMBD];
__device__ float g_e0l1[FEATD];
__device__ float g_b2p[128];
__device__ double g_acc[3];
// tree barrier state
__device__ unsigned g_leaf[8*32];
__device__ unsigned g_root2 = 0;
__device__ volatile unsigned g_rel = 0;

// hi/lo carry + intermediates (bf16 pairs)
__device__ bf16 g_cAH[BB*STATED];
__device__ bf16 g_cAL[BB*STATED];
__device__ bf16 g_cBH[BB*STATED];
__device__ bf16 g_cBL[BB*STATED];
__device__ bf16 g_zcH[BB*STATED];   // zero, never written
__device__ bf16 g_zcL[BB*STATED];   // zero, never written
__device__ bf16 g_y1H[BB*FEATD];
__device__ bf16 g_y1L[BB*FEATD];
__device__ bf16 g_y2H[BB*FEATD];
__device__ bf16 g_y2L[BB*FEATD];

__device__ bf16 g_states_bf[TBD*STATED];
__device__ bf16 g_emb_bf[TBD*EMBD];
__device__ bf16 g_E_bf[TBD*EMBD];
__device__ bf16 g_pcat_bf[TBD*1536];
__device__ bf16 g_big1_bf[TBD*FEATD];
__device__ bf16 g_big2_bf[TBD*FEATD];
__device__ bf16 g_e0_bf[EMBD];
__device__ bf16 g_stW0b[512*1536];
__device__ bf16 g_stW1b[512*512];
__device__ bf16 g_stW2b[128*512];
__device__ bf16 g_epW0b[512*576];
__device__ bf16 g_epW1b[512*512];
__device__ bf16 g_epW2b[1024*512];
__device__ bf16 g_rpW0b[512*576];
__device__ bf16 g_rpW1b[512*512];
// split hi/lo weights for the sequential path
__device__ bf16 g_WGh[2048*576];
__device__ bf16 g_WGl[2048*576];
__device__ bf16 g_W0hh[512*512];
__device__ bf16 g_W0hl[512*512];
__device__ bf16 g_W1h[512*512];
__device__ bf16 g_W1l[512*512];
__device__ bf16 g_W2h[128*512];
__device__ bf16 g_W2l[128*512];

// ---------------- math ----------------
__device__ __forceinline__ float softplusf(float x) {
    return fmaxf(x, 0.f) + log1pf(expf(-fabsf(x)));
}
__device__ __forceinline__ float sigmoidf_(float x) { return 1.f / (1.f + expf(-x)); }
__device__ __forceinline__ float eluf(float x) { return x > 0.f ? x : expm1f(x); }
template<int ACT> __device__ __forceinline__ float actf(float v) {
    if (ACT == 1) return eluf(v);
    return v;
}

__device__ __forceinline__ void mma_bf16(float* c, const unsigned* a, const unsigned* b) {
    asm volatile(
        "mma.sync.aligned.m16n8k16.row.col.f32.bf16.bf16.f32 "
        "{%0,%1,%2,%3},{%4,%5,%6,%7},{%8,%9},{%0,%1,%2,%3};"
        : "+f"(c[0]), "+f"(c[1]), "+f"(c[2]), "+f"(c[3])
        : "r"(a[0]), "r"(a[1]), "r"(a[2]), "r"(a[3]), "r"(b[0]), "r"(b[1]));
}

__device__ __forceinline__ void splitw(float v, bf16& h, bf16& l) {
    h = __float2bfloat16(v);
    l = __float2bfloat16(v - __bfloat162float(h));
}

__device__ __forceinline__ unsigned s2u(const void* p) {
    return (unsigned)__cvta_generic_to_shared(p);
}
__device__ __forceinline__ void ldsm4(unsigned& r0, unsigned& r1, unsigned& r2, unsigned& r3,
                                      unsigned a) {
    asm volatile("ldmatrix.sync.aligned.m8n8.x4.shared.b16 {%0,%1,%2,%3}, [%4];"
                 : "=r"(r0), "=r"(r1), "=r"(r2), "=r"(r3) : "r"(a));
}

// ---------------- two-level tree grid barrier ----------------
__device__ __forceinline__ void gbar() {
    __syncthreads();
    if (threadIdx.x == 0) {
        unsigned gen = g_rel;
        __threadfence();
        int grp = (blockIdx.x >> 4) * 32;
        if (atomicAdd(&g_leaf[grp], 1u) == 15u) {
            if (atomicAdd(&g_root2, 1u) == 7u) {
#pragma unroll
                for (int i = 0; i < 8; i++) g_leaf[i * 32] = 0u;
                g_root2 = 0u;
                __threadfence();
                g_rel = gen + 1u;
            }
        }
        while (g_rel == gen) { __nanosleep(32); }
        __threadfence();
    }
    __syncthreads();
}

// ---------------- bf16 tensor-core GEMM (batched; ldmatrix fragments) ----------------
template<int ACT, bool ROWSHIFT, bool WF32, bool WBF, bool REDUCE>
__global__ __launch_bounds__(256, 2) void mma_gemm(
    const bf16* __restrict__ A, int ldA,
    const bf16* __restrict__ W, int ldW,
    const float* __restrict__ bias,
    float* __restrict__ Cf, bf16* __restrict__ Cb, int ldC, int K,
    const float* __restrict__ Ef, double* __restrict__ racc)
{
    __shared__ __align__(16) unsigned As[2][128 * 20];
    __shared__ __align__(16) unsigned Ws[2][128 * 20];
    __shared__ double redsm[256];
    int tid = threadIdx.x, lane = tid & 31, wid = tid >> 5;
    int g = lane >> 2, tg = lane & 3;
    int wr = wid >> 2, wc = wid & 3;
    int row0 = blockIdx.y * 128, col0 = blockIdx.x * 128;

    float acc[4][4][4];
#pragma unroll
    for (int mt = 0; mt < 4; mt++)
#pragma unroll
        for (int nt = 0; nt < 4; nt++)
#pragma unroll
            for (int q = 0; q < 4; q++) acc[mt][nt][q] = 0.f;

    // precomputed per-lane ldmatrix row/word offsets
    int a_r = (lane & 7) + ((lane >> 3) & 1) * 8;
    int a_w = ((lane >> 4) & 1) * 4;
    int b_r = (lane & 7) + ((lane >> 4) & 1) * 8;
    int b_w = ((lane >> 3) & 1) * 4;

    const int nc = K / 32;
    uint4 pa[2], pb[2];
#pragma unroll
    for (int i = 0; i < 2; i++) {
        int u = tid + i * 256, row = u >> 2, q = u & 3;
        int grow = row0 + row;
        if (ROWSHIFT && grow >= 256) grow -= 256;
        pa[i] = *reinterpret_cast<const uint4*>(A + (size_t)grow * ldA + q * 8);
        pb[i] = *reinterpret_cast<const uint4*>(W + (size_t)(col0 + row) * ldW + q * 8);
    }
#pragma unroll
    for (int i = 0; i < 2; i++) {
        int u = tid + i * 256, row = u >> 2, q = u & 3;
        *reinterpret_cast<uint4*>(&As[0][row * 20 + q * 4]) = pa[i];
        *reinterpret_cast<uint4*>(&Ws[0][row * 20 + q * 4]) = pb[i];
    }
    __syncthreads();

    int buf = 0;
    for (int c = 0; c < nc; c++) {
        bool nxt = (c + 1 < nc);
        if (nxt) {
            int k0 = (c + 1) * 32;
#pragma unroll
            for (int i = 0; i < 2; i++) {
                int u = tid + i * 256, row = u >> 2, q = u & 3;
                int grow = row0 + row;
                if (ROWSHIFT && grow >= 256) grow -= 256;
                pa[i] = *reinterpret_cast<const uint4*>(A + (size_t)grow * ldA + k0 + q * 8);
                pb[i] = *reinterpret_cast<const uint4*>(W + (size_t)(col0 + row) * ldW + k0 + q * 8);
            }
        }
        unsigned asb = s2u(&As[buf][0]);
        unsigned wsb = s2u(&Ws[buf][0]);
#pragma unroll
        for (int ks = 0; ks < 2; ks++) {
            unsigned af[4][4], bfr[4][2];
#pragma unroll
            for (int mt = 0; mt < 4; mt++) {
                int row = wr * 64 + mt * 16 + a_r;
                ldsm4(af[mt][0], af[mt][1], af[mt][2], af[mt][3],
                      asb + (unsigned)((row * 20 + ks * 8 + a_w) * 4));
            }
#pragma unroll
            for (int np = 0; np < 2; np++) {
                int row = wc * 32 + np * 16 + b_r;
                ldsm4(bfr[np * 2][0], bfr[np * 2][1], bfr[np * 2 + 1][0], bfr[np * 2 + 1][1],
                      wsb + (unsigned)((row * 20 + ks * 8 + b_w) * 4));
            }
#pragma unroll
            for (int mt = 0; mt < 4; mt++)
#pragma unroll
                for (int nt = 0; nt < 4; nt++)
                    mma_bf16(acc[mt][nt], af[mt], bfr[nt]);
        }
        if (nxt) {
            int nb = buf ^ 1;
#pragma unroll
            for (int i = 0; i < 2; i++) {
                int u = tid + i * 256, row = u >> 2, q = u & 3;
                *reinterpret_cast<uint4*>(&As[nb][row * 20 + q * 4]) = pa[i];
                *reinterpret_cast<uint4*>(&Ws[nb][row * 20 + q * 4]) = pb[i];
            }
        }
        __syncthreads();
        buf ^= 1;
    }

    double rsum = 0.0;
#pragma unroll
    for (int mt = 0; mt < 4; mt++) {
        int r = row0 + wr * 64 + mt * 16 + g;
#pragma unroll
        for (int nt = 0; nt < 4; nt++) {
            int cc = col0 + wc * 32 + nt * 8 + tg * 2;
            float b0v = bias[cc], b1v = bias[cc + 1];
            float v00 = actf<ACT>(acc[mt][nt][0] + b0v);
            float v01 = actf<ACT>(acc[mt][nt][1] + b1v);
            float v10 = actf<ACT>(acc[mt][nt][2] + b0v);
            float v11 = actf<ACT>(acc[mt][nt][3] + b1v);
            if (WF32) {
                Cf[(size_t)r * ldC + cc]           = v00;
                Cf[(size_t)r * ldC + cc + 1]       = v01;
                Cf[(size_t)(r + 8) * ldC + cc]     = v10;
                Cf[(size_t)(r + 8) * ldC + cc + 1] = v11;
            }
            if (WBF) {
                Cb[(size_t)r * ldC + cc]           = __float2bfloat16(v00);
                Cb[(size_t)r * ldC + cc + 1]       = __float2bfloat16(v01);
                Cb[(size_t)(r + 8) * ldC + cc]     = __float2bfloat16(v10);
                Cb[(size_t)(r + 8) * ldC + cc + 1] = __float2bfloat16(v11);
            }
            if (REDUCE) {
                float d0 = Ef[(size_t)r * ldC + cc]           - v00;
                float d1 = Ef[(size_t)r * ldC + cc + 1]       - v01;
                float d2 = Ef[(size_t)(r + 8) * ldC + cc]     - v10;
                float d3 = Ef[(size_t)(r + 8) * ldC + cc + 1] - v11;
                rsum += (double)(0.5f * d0 * d0) + (double)(0.5f * d1 * d1)
                      + (double)(0.5f * d2 * d2) + (double)(0.5f * d3 * d3);
            }
        }
    }
    if (REDUCE) {
        redsm[tid] = rsum;
        __syncthreads();
        for (int o = 128; o > 0; o >>= 1) {
            if (tid < o) redsm[tid] += redsm[tid + o];
            __syncthreads();
        }
        if (tid == 0) atomicAdd(racc, redsm[0]);
    }
}

// ---------------- prep ----------------
__global__ void cvt_bf_k(const float* __restrict__ s, bf16* __restrict__ d, long n) {
    for (long i = blockIdx.x * (long)blockDim.x + threadIdx.x; i < n;
         i += (long)gridDim.x * blockDim.x)
        d[i] = __float2bfloat16(s[i]);
}

// fused prep for everything recur_k needs: WG split, W0/W1 splits, W2p
__global__ void prep_all(const float* __restrict__ Wih, const float* __restrict__ Whh,
                         bf16* __restrict__ WGh, bf16* __restrict__ WGl,
                         const float* __restrict__ st_W0, bf16* __restrict__ W0hh, bf16* __restrict__ W0hl,
                         const float* __restrict__ st_W1, bf16* __restrict__ W1h, bf16* __restrict__ W1l,
                         const float* __restrict__ W2, const float* __restrict__ b2,
                         bf16* __restrict__ W2h, bf16* __restrict__ W2l, float* __restrict__ b2p)
{
    const long nWG = 2048L * 576;          // [0, nWG)
    const long nW0 = 512L * 512;
    const long nW1 = 512L * 512;
    const long nW2 = 128L * 512;
    const long total = nWG + nW0 + nW1 + nW2;
    for (long idx = blockIdx.x * (long)blockDim.x + threadIdx.x; idx < total;
         idx += (long)gridDim.x * blockDim.x) {
        if (idx < nWG) {
            int c = (int)(idx / 576), k = (int)(idx % 576);
            int jb = c >> 7, gs = (c >> 5) & 3, jl = c & 31, j = jb * 32 + jl;
            float v = 0.f;
            if (gs == 0)      v = (k < 64) ? Wih[j * 70 + k] : Whh[(size_t)j * 512 + k - 64];
            else if (gs == 1) v = (k < 64) ? Wih[(512 + j) * 70 + k] : Whh[(size_t)(512 + j) * 512 + k - 64];
            else if (gs == 2) v = (k < 64) ? Wih[(1024 + j) * 70 + k] : 0.f;
            else              v = (k < 64) ? 0.f : Whh[(size_t)(1024 + j) * 512 + k - 64];
            bf16 h, l; splitw(v, h, l);
            WGh[idx] = h; WGl[idx] = l;
        } else if (idx < nWG + nW0) {
            long i2 = idx - nWG;
            int row = (int)(i2 / 512), k = (int)(i2 % 512);
            float v = st_W0[(size_t)row * 1536 + k];
            bf16 h, l; splitw(v, h, l);
            W0hh[i2] = h; W0hl[i2] = l;
        } else if (idx < nWG + nW0 + nW1) {
            long i2 = idx - nWG - nW0;
            float v = st_W1[i2];
            bf16 h, l; splitw(v, h, l);
            W1h[i2] = h; W1l[i2] = l;
        } else {
            long i2 = idx - nWG - nW0 - nW1;
            int c = (int)(i2 / 512), k = (int)(i2 % 512);
            int sr = (c & 1) ? (64 + (c >> 1)) : (c >> 1);
            float v = W2[(size_t)sr * 512 + k];
            bf16 h, l; splitw(v, h, l);
            W2h[i2] = h; W2l[i2] = l;
            if (k == 0) b2p[c] = b2[sr];
        }
    }
}

// ---------------- 16x64-tile split-bf16 MMA, K=512, k64 chunks, ldmatrix ----------------
__device__ __forceinline__ void gemm16v(
    const bf16* __restrict__ AH, const bf16* __restrict__ AL, int ldA,
    const bf16* __restrict__ WH, const bf16* __restrict__ WL,
    int r0, int c0, float* acc, unsigned* SM,
    int tid, int wid, int g, int tg)
{
    int lane = tid & 31;
    acc[0] = acc[1] = acc[2] = acc[3] = 0.f;
    int arow = (tid & 127) >> 3, aq = tid & 7;
    const bf16* Asrc = (tid < 128) ? AH : AL;
    int adst = (tid < 128) ? 0 : 576;
    int a_r = (lane & 7) + ((lane >> 3) & 1) * 8;
    int a_w = ((lane >> 4) & 1) * 4;
    int b_r = wid * 8 + (lane & 7);
    int b_w = ((lane >> 3) & 1) * 4;
    unsigned b_roff = (lane < 16) ? 1152u : 3456u;
    unsigned smb = s2u(SM);

    uint4 va, vw[2][2];
    va = *reinterpret_cast<const uint4*>(Asrc + (size_t)(r0 + arow) * ldA + aq * 8);
#pragma unroll
    for (int i = 0; i < 2; i++) {
        int u = tid + i * 256, wcol = u >> 3, wq = u & 7;
        vw[i][0] = *reinterpret_cast<const uint4*>(WH + (size_t)(c0 + wcol) * 512 + wq * 8);
        vw[i][1] = *reinterpret_cast<const uint4*>(WL + (size_t)(c0 + wcol) * 512 + wq * 8);
    }
    {
        unsigned* b0 = SM;
        *reinterpret_cast<uint4*>(&b0[adst + arow * 36 + aq * 4]) = va;
#pragma unroll
        for (int i = 0; i < 2; i++) {
            int u = tid + i * 256, wcol = u >> 3, wq = u & 7;
            *reinterpret_cast<uint4*>(&b0[1152 + wcol * 36 + wq * 4]) = vw[i][0];
            *reinterpret_cast<uint4*>(&b0[3456 + wcol * 36 + wq * 4]) = vw[i][1];
        }
    }
    __syncthreads();
    for (int c = 0; c < 8; c++) {
        unsigned sb = smb + (unsigned)((c & 1) * 5760 * 4);
        if (c < 7) {
            int k0 = (c + 1) * 64;
            va = *reinterpret_cast<const uint4*>(Asrc + (size_t)(r0 + arow) * ldA + k0 + aq * 8);
#pragma unroll
            for (int i = 0; i < 2; i++) {
                int u = tid + i * 256, wcol = u >> 3, wq = u & 7;
                vw[i][0] = *reinterpret_cast<const uint4*>(WH + (size_t)(c0 + wcol) * 512 + k0 + wq * 8);
                vw[i][1] = *reinterpret_cast<const uint4*>(WL + (size_t)(c0 + wcol) * 512 + k0 + wq * 8);
            }
        }
#pragma unroll
        for (int ks = 0; ks < 4; ks++) {
            unsigned aH[4], aL[4], bH[2], bL[2];
            ldsm4(aH[0], aH[1], aH[2], aH[3],
                  sb + (unsigned)((a_r * 36 + ks * 8 + a_w) * 4));
            ldsm4(aL[0], aL[1], aL[2], aL[3],
                  sb + (unsigned)((576 + a_r * 36 + ks * 8 + a_w) * 4));
            ldsm4(bH[0], bH[1], bL[0], bL[1],
                  sb + (unsigned)((b_roff + b_r * 36 + ks * 8 + b_w) * 4));
            mma_bf16(acc, aH, bH);
            mma_bf16(acc, aL, bH);
            mma_bf16(acc, aH, bL);
        }
        if (c < 7) {
            unsigned* nb = SM + ((c + 1) & 1) * 5760;
            *reinterpret_cast<uint4*>(&nb[adst + arow * 36 + aq * 4]) = va;
#pragma unroll
            for (int i = 0; i < 2; i++) {
                int u = tid + i * 256, wcol = u >> 3, wq = u & 7;
                *reinterpret_cast<uint4*>(&nb[1152 + wcol * 36 + wq * 4]) = vw[i][0];
                *reinterpret_cast<uint4*>(&nb[3456 + wcol * 36 + wq * 4]) = vw[i][1];
            }
        }
        __syncthreads();
    }
}

// ---------------- persistent sequential recurrence ----------------
extern __shared__ unsigned SMd[];

__global__ __launch_bounds__(256, 1) void recur_k(
    const bf16* __restrict__ WGh, const bf16* __restrict__ WGl,
    const float* __restrict__ action, const float* __restrict__ Wih,
    const float* __restrict__ bih, const float* __restrict__ bhh,
    const bf16* __restrict__ W0hh, const bf16* __restrict__ W0hl, const float* __restrict__ PE,
    const bf16* __restrict__ W1h, const bf16* __restrict__ W1l, const float* __restrict__ b1,
    const bf16* __restrict__ W2h, const bf16* __restrict__ W2l, const float* __restrict__ b2p,
    const float* __restrict__ eps, float* __restrict__ qmu, float* __restrict__ qstd,
    bf16* __restrict__ stbf,
    bf16* __restrict__ cAH, bf16* __restrict__ cAL,
    bf16* __restrict__ cBH, bf16* __restrict__ cBL,
    const bf16* __restrict__ zcH, const bf16* __restrict__ zcL,
    bf16* __restrict__ y1H, bf16* __restrict__ y1L,
    bf16* __restrict__ y2H, bf16* __restrict__ y2L)
{
    unsigned* SM = SMd;
    int b = blockIdx.x, tid = threadIdx.x, lane = tid & 31, wid = tid >> 5;
    int g = lane >> 2, tg = lane & 3;
    unsigned smb = s2u(SM);

    for (int t = 0; t < TT; t++) {
        const bf16* cinH = (t == 0) ? zcH : ((t & 1) ? cBH : cAH);
        const bf16* cinL = (t == 0) ? zcL : ((t & 1) ? cBL : cAL);
        bf16* coutH = ((t + 1) & 1) ? cBH : cAH;
        bf16* coutL = ((t + 1) & 1) ? cBL : cAL;
        bf16* st_t = stbf + (size_t)t * BB * STATED;
        const float* a_t = action + (size_t)t * BB * ADIM;
        const float* PE_t = PE + (size_t)t * BB * FEATD;
        const float* eps_t = eps + (size_t)t * BB * STOCHD;

        // ===== GRU: [256 x 2048], K=576, 9 chunks of k64, tile 32x128 =====
        {
            int bx = b & 15, by = b >> 4;
            int r0 = by * 32, c0 = bx * 128;
            int wr = wid >> 2, wc = wid & 3;
            int a_r = wr * 16 + (lane & 7) + ((lane >> 3) & 1) * 8;
            int a_w = ((lane >> 4) & 1) * 4;
            int b_rb = (lane & 7) + ((lane >> 4) & 1) * 8;
            int b_w = ((lane >> 3) & 1) * 4;
            float acc[4][4];
#pragma unroll
            for (int nt = 0; nt < 4; nt++)
#pragma unroll
                for (int q = 0; q < 4; q++) acc[nt][q] = 0.f;

            int arow = tid >> 3, aq = tid & 7;
            uint4 vah, valo, vwh[4], vwl[4];
            vah  = *reinterpret_cast<const uint4*>(cinH + (size_t)(r0 + arow) * STATED + aq * 8);
            valo = *reinterpret_cast<const uint4*>(cinL + (size_t)(r0 + arow) * STATED + aq * 8);
#pragma unroll
            for (int i = 0; i < 4; i++) {
                int u = tid + i * 256, wcol = u >> 3, wq = u & 7;
                vwh[i] = *reinterpret_cast<const uint4*>(WGh + (size_t)(c0 + wcol) * 576 + wq * 8);
                vwl[i] = *reinterpret_cast<const uint4*>(WGl + (size_t)(c0 + wcol) * 576 + wq * 8);
            }
            {
                unsigned* b0 = SM;
                *reinterpret_cast<uint4*>(&b0[arow * 36 + aq * 4]) = vah;
                *reinterpret_cast<uint4*>(&b0[1152 + arow * 36 + aq * 4]) = valo;
#pragma unroll
                for (int i = 0; i < 4; i++) {
                    int u = tid + i * 256, wcol = u >> 3, wq = u & 7;
                    *reinterpret_cast<uint4*>(&b0[2304 + wcol * 36 + wq * 4]) = vwh[i];
                    *reinterpret_cast<uint4*>(&b0[6912 + wcol * 36 + wq * 4]) = vwl[i];
                }
            }
            __syncthreads();
            for (int c = 0; c < 9; c++) {
                unsigned sb = smb + (unsigned)((c & 1) * 11520 * 4);
                if (c < 8) {
                    int k0 = (c + 1) * 64;
                    vah  = *reinterpret_cast<const uint4*>(cinH + (size_t)(r0 + arow) * STATED + k0 + aq * 8);
                    valo = *reinterpret_cast<const uint4*>(cinL + (size_t)(r0 + arow) * STATED + k0 + aq * 8);
#pragma unroll
                    for (int i = 0; i < 4; i++) {
                        int u = tid + i * 256, wcol = u >> 3, wq = u & 7;
                        vwh[i] = *reinterpret_cast<const uint4*>(WGh + (size_t)(c0 + wcol) * 576 + k0 + wq * 8);
                        vwl[i] = *reinterpret_cast<const uint4*>(WGl + (size_t)(c0 + wcol) * 576 + k0 + wq * 8);
                    }
                }
#pragma unroll
                for (int ks = 0; ks < 4; ks++) {
                    unsigned aH[4], aL[4], bH[4][2], bL[4][2];
                    ldsm4(aH[0], aH[1], aH[2], aH[3],
                          sb + (unsigned)((a_r * 36 + ks * 8 + a_w) * 4));
                    ldsm4(aL[0], aL[1], aL[2], aL[3],
                          sb + (unsigned)((1152 + a_r * 36 + ks * 8 + a_w) * 4));
#pragma unroll
                    for (int np = 0; np < 2; np++) {
                        int row = wc * 32 + np * 16 + b_rb;
                        ldsm4(bH[np * 2][0], bH[np * 2][1], bH[np * 2 + 1][0], bH[np * 2 + 1][1],
                              sb + (unsigned)((2304 + row * 36 + ks * 8 + b_w) * 4));
                        ldsm4(bL[np * 2][0], bL[np * 2][1], bL[np * 2 + 1][0], bL[np * 2 + 1][1],
                              sb + (unsigned)((6912 + row * 36 + ks * 8 + b_w) * 4));
                    }
#pragma unroll
                    for (int nt = 0; nt < 4; nt++) {
                        mma_bf16(acc[nt], aH, bH[nt]);
                        mma_bf16(acc[nt], aL, bH[nt]);
                        mma_bf16(acc[nt], aH, bL[nt]);
                    }
                }
                if (c < 8) {
                    unsigned* nb = SM + ((c + 1) & 1) * 11520;
                    *reinterpret_cast<uint4*>(&nb[arow * 36 + aq * 4]) = vah;
                    *reinterpret_cast<uint4*>(&nb[1152 + arow * 36 + aq * 4]) = valo;
#pragma unroll
                    for (int i = 0; i < 4; i++) {
                        int u = tid + i * 256, wcol = u >> 3, wq = u & 7;
                        *reinterpret_cast<uint4*>(&nb[2304 + wcol * 36 + wq * 4]) = vwh[i];
                        *reinterpret_cast<uint4*>(&nb[6912 + wcol * 36 + wq * 4]) = vwl[i];
                    }
                }
                __syncthreads();
            }
            // stage raw gates into smem, then block-local GRU epilogue (P on-the-fly)
            float* Cst = (float*)SM;   // 32 x 132
            int wr2 = wid >> 2, wc2 = wid & 3;
#pragma unroll
            for (int nt = 0; nt < 4; nt++) {
                int cc = wc2 * 32 + nt * 8 + tg * 2;
                int rr = wr2 * 16 + g;
                Cst[rr * 132 + cc]           = acc[nt][0];
                Cst[rr * 132 + cc + 1]       = acc[nt][1];
                Cst[(rr + 8) * 132 + cc]     = acc[nt][2];
                Cst[(rr + 8) * 132 + cc + 1] = acc[nt][3];
            }
            __syncthreads();
#pragma unroll
            for (int i = 0; i < 4; i++) {
                int o = tid + i * 256;
                int row = o >> 5, jl = o & 31;
                int gr = r0 + row, j = bx * 32 + jl;
                float rv = Cst[row * 132 + jl];
                float zv = Cst[row * 132 + 32 + jl];
                float nsv = Cst[row * 132 + 64 + jl];
                float nhv = Cst[row * 132 + 96 + jl];
                float a0 = a_t[gr * ADIM], a1 = a_t[gr * ADIM + 1], a2 = a_t[gr * ADIM + 2];
                float a3 = a_t[gr * ADIM + 3], a4 = a_t[gr * ADIM + 4], a5 = a_t[gr * ADIM + 5];
                const float* wr0 = Wih + (size_t)j * 70 + 64;
                float pr = bih[j];
                pr = fmaf(a0, wr0[0], pr); pr = fmaf(a1, wr0[1], pr); pr = fmaf(a2, wr0[2], pr);
                pr = fmaf(a3, wr0[3], pr); pr = fmaf(a4, wr0[4], pr); pr = fmaf(a5, wr0[5], pr);
                pr += bhh[j];
                const float* wz0 = Wih + (size_t)(512 + j) * 70 + 64;
                float pz = bih[512 + j];
                pz = fmaf(a0, wz0[0], pz); pz = fmaf(a1, wz0[1], pz); pz = fmaf(a2, wz0[2], pz);
                pz = fmaf(a3, wz0[3], pz); pz = fmaf(a4, wz0[4], pz); pz = fmaf(a5, wz0[5], pz);
                pz += bhh[512 + j];
                const float* wn0 = Wih + (size_t)(1024 + j) * 70 + 64;
                float pn = bih[1024 + j];
                pn = fmaf(a0, wn0[0], pn); pn = fmaf(a1, wn0[1], pn); pn = fmaf(a2, wn0[2], pn);
                pn = fmaf(a3, wn0[3], pn); pn = fmaf(a4, wn0[4], pn); pn = fmaf(a5, wn0[5], pn);
                float rr_ = sigmoidf_(rv + pr);
                float zz = sigmoidf_(zv + pz);
                float nn = tanhf(nsv + pn + rr_ * (nhv + bhh[1024 + j]));
                float hp = __bfloat162float(cinH[(size_t)gr * STATED + 64 + j])
                         + __bfloat162float(cinL[(size_t)gr * STATED + 64 + j]);
                float h = (1.f - zz) * nn + zz * hp;
                bf16 hh, hl; splitw(h, hh, hl);
                coutH[(size_t)gr * STATED + 64 + j] = hh;
                coutL[(size_t)gr * STATED + 64 + j] = hl;
                st_t[(size_t)gr * STATED + j] = __float2bfloat16(h);
            }
        }
        gbar();

        // ===== L0: y1 = elu(h @ W0h^T + PE_t) =====
        {
            int by = b >> 3, bx = b & 7;
            int r0 = by * 16, c0 = bx * 64;
            float acc[4];
            gemm16v(coutH + 64, coutL + 64, STATED, W0hh, W0hl, r0, c0, acc, SM, tid, wid, g, tg);
            int cc = c0 + wid * 8 + tg * 2;
#pragma unroll
            for (int rr = 0; rr < 2; rr++) {
                int gr = r0 + g + rr * 8;
#pragma unroll
                for (int q = 0; q < 2; q++) {
                    float v = eluf(acc[rr * 2 + q] + PE_t[(size_t)gr * 512 + cc + q]);
                    bf16 vh, vl; splitw(v, vh, vl);
                    y1H[(size_t)gr * 512 + cc + q] = vh;
                    y1L[(size_t)gr * 512 + cc + q] = vl;
                }
            }
        }
        gbar();

        // ===== L1: y2 = elu(y1 @ W1^T + b1) =====
        {
            int by = b >> 3, bx = b & 7;
            int r0 = by * 16, c0 = bx * 64;
            float acc[4];
            gemm16v(y1H, y1L, 512, W1h, W1l, r0, c0, acc, SM, tid, wid, g, tg);
            int cc = c0 + wid * 8 + tg * 2;
#pragma unroll
            for (int rr = 0; rr < 2; rr++) {
                int gr = r0 + g + rr * 8;
#pragma unroll
                for (int q = 0; q < 2; q++) {
                    float v = eluf(acc[rr * 2 + q] + b1[cc + q]);
                    bf16 vh, vl; splitw(v, vh, vl);
                    y2H[(size_t)gr * 512 + cc + q] = vh;
                    y2L[(size_t)gr * 512 + cc + q] = vl;
                }
            }
        }
        gbar();

        // ===== L2 + sample =====
        if (b < 32) {
            int by = b >> 1, bx = b & 1;
            int r0 = by * 16, c0 = bx * 64;
            float acc[4];
            gemm16v(y2H, y2L, 512, W2h, W2l, r0, c0, acc, SM, tid, wid, g, tg);
            int cc = c0 + wid * 8 + tg * 2;
            int i_ = cc >> 1;
#pragma unroll
            for (int rr = 0; rr < 2; rr++) {
                int gr = r0 + g + rr * 8;
                float mu = acc[rr * 2] + b2p[cc];
                float sd = softplusf(acc[rr * 2 + 1] + b2p[cc + 1]) + 1e-4f;
                float s = fmaf(sd, eps_t[(size_t)gr * 64 + i_], mu);
                qmu[(size_t)(t * BB + gr) * 64 + i_] = mu;
                qstd[(size_t)(t * BB + gr) * 64 + i_] = sd;
                bf16 sh, sl; splitw(s, sh, sl);
                coutH[(size_t)gr * STATED + i_] = sh;
                coutL[(size_t)gr * STATED + i_] = sl;
                st_t[(size_t)gr * STATED + 512 + i_] = __float2bfloat16(s);
            }
        }
        gbar();
    }
}

// ---------------- misc ----------------
__global__ void e0_l1(const float* __restrict__ ep_b0, const float* __restrict__ ep_W1,
                      const float* __restrict__ ep_b1, float* __restrict__ l1)
{
    __shared__ float x0[512];
    for (int k = threadIdx.x; k < 512; k += 256) x0[k] = eluf(ep_b0[k]);
    __syncthreads();
    for (int o = threadIdx.x; o < 512; o += 256) {
        float v = ep_b1[o];
        for (int k = 0; k < 512; k++) v = fmaf(x0[k], ep_W1[(size_t)o * 512 + k], v);
        l1[o] = eluf(v);
    }
}

__global__ void e0_head(const float* __restrict__ l1, const float* __restrict__ ep_W2,
                        const float* __restrict__ ep_b2, float* __restrict__ e0)
{
    int o = blockIdx.x * 256 + threadIdx.x;
    float v = ep_b2[o];
    for (int k = 0; k < 512; k++) v = fmaf(l1[k], ep_W2[(size_t)o * 512 + k], v);
    e0[o] = v;
}

__global__ void build_pcat(const bf16* __restrict__ stbf, const bf16* __restrict__ Ebf,
                           const bf16* __restrict__ e0bf, bf16* __restrict__ out)
{
    int r = blockIdx.x;
    const bf16* src = (r < 256) ? e0bf : (Ebf + (size_t)(r - 256) * EMBD);
    bf16* o = out + (size_t)r * 1536;
    const bf16* st = stbf + (size_t)r * STATED;
    for (int c = threadIdx.x; c < 1536; c += 256)
        o[c] = (c < 512) ? st[c] : src[c - 512];
}

// ---------------- reductions ----------------
__global__ void zero_acc_k(double* acc) {
    if (threadIdx.x < 3) acc[threadIdx.x] = 0.0;
    if (threadIdx.x < 8) g_leaf[threadIdx.x * 32] = 0u;
    if (threadIdx.x == 0) { g_root2 = 0u; g_rel = 0u; }
}

__global__ void kl_reduce_k(const float* __restrict__ praw, const float* __restrict__ qmu,
                            const float* __restrict__ qstd, double* __restrict__ acc)
{
    __shared__ double sh[256];
    double s = 0.0;
    long total = (long)TBD * STOCHD;
    for (long idx = blockIdx.x * (long)blockDim.x + threadIdx.x; idx < total;
         idx += (long)gridDim.x * blockDim.x) {
        int r = (int)(idx >> 6), i = (int)(idx & 63);
        float pmu = praw[(size_t)r * 128 + i];
        float psd = softplusf(praw[(size_t)r * 128 + 64 + i]) + 1e-4f;
        float qm = qmu[idx], qs = qstd[idx];
        float d = qm - pmu;
        s += (double)(logf(psd / qs) + (qs * qs + d * d) / (2.f * psd * psd) - 0.5f);
    }
    sh[threadIdx.x] = s; __syncthreads();
    for (int o = 128; o > 0; o >>= 1) {
        if (threadIdx.x < o) sh[threadIdx.x] += sh[threadIdx.x + o];
        __syncthreads();
    }
    if (threadIdx.x == 0) atomicAdd(acc, sh[0]);
}

__global__ void reward_reduce_k(const bf16* __restrict__ big2, const float* __restrict__ W,
                                const float* __restrict__ bias, const float* __restrict__ reward,
                                double* __restrict__ acc)
{
    __shared__ double sh[8];
    int lane = threadIdx.x & 31, wib = threadIdx.x >> 5;
    int gwarp = (blockIdx.x * blockDim.x + threadIdx.x) >> 5;
    int nwarps = (gridDim.x * blockDim.x) >> 5;
    double local = 0.0;
    for (int r = gwarp; r < TBD; r += nwarps) {
        float sum = 0.f;
        const bf16* row = big2 + (size_t)r * FEATD;
        for (int k = lane; k < FEATD; k += 32)
            sum = fmaf(__bfloat162float(row[k]), W[k], sum);
#pragma unroll
        for (int o = 16; o > 0; o >>= 1) sum += __shfl_xor_sync(0xffffffffu, sum, o);
        if (lane == 0) {
            float d = reward[r] - (sum + bias[0]);
            local += (double)(0.5f * d * d + 0.5f * LOG2PI_F);
        }
    }
    if (lane == 0) sh[wib] = local;
    __syncthreads();
    if (threadIdx.x == 0) {
        double t = 0.0;
        for (int i = 0; i < 8; i++) t += sh[i];
        atomicAdd(acc, t);
    }
}

__global__ void finalize_k(const double* __restrict__ acc, float* __restrict__ out, int n) {
    double inv = 1.0 / (double)(TT * BB);
    double loss = (acc[0] + acc[1] + acc[2]) * inv + (double)EMBD * 0.5 * LOG2PI_D;
    float lf = (float)loss;
    for (int i = 0; i < n; i++) out[i] = lf;
}

// ---------------- host ----------------
static void* symaddr(const void* sym) {
    void* p = nullptr;
    cudaGetSymbolAddress(&p, sym);
    return p;
}

extern "C" void kernel_launch(void* const* d_in, const int* in_sizes, int n_in,
                              void* d_out, int out_size)
{
    const float* emb     = (const float*)d_in[0];
    const float* action  = (const float*)d_in[1];
    const float* reward  = (const float*)d_in[2];
    const float* eps     = (const float*)d_in[3];
    const float* gru_Wih = (const float*)d_in[4];
    const float* gru_bih = (const float*)d_in[5];
    const float* gru_Whh = (const float*)d_in[6];
    const float* gru_bhh = (const float*)d_in[7];
    const float* st_W0 = (const float*)d_in[8];  const float* st_b0 = (const float*)d_in[9];
    const float* st_W1 = (const float*)d_in[10]; const float* st_b1 = (const float*)d_in[11];
    const float* st_W2 = (const float*)d_in[12]; const float* st_b2 = (const float*)d_in[13];
    const float* ep_W0 = (const float*)d_in[14]; const float* ep_b0 = (const float*)d_in[15];
    const float* ep_W1 = (const float*)d_in[16]; const float* ep_b1 = (const float*)d_in[17];
    const float* ep_W2 = (const float*)d_in[18]; const float* ep_b2 = (const float*)d_in[19];
    const float* rp_W0 = (const float*)d_in[20]; const float* rp_b0 = (const float*)d_in[21];
    const float* rp_W1 = (const float*)d_in[22]; const float* rp_b1 = (const float*)d_in[23];
    const float* rp_W2 = (const float*)d_in[24]; const float* rp_b2 = (const float*)d_in[25];

    float* qmu    = (float*)symaddr(g_qmu);
    float* qstd   = (float*)symaddr(g_qstd);
    float* PE     = (float*)symaddr(g_PE);
    float* praw   = (float*)symaddr(g_praw);
    float* e0     = (float*)symaddr(g_e0);
    float* e0l1   = (float*)symaddr(g_e0l1);
    float* b2p    = (float*)symaddr(g_b2p);
    double* acc   = (double*)symaddr(g_acc);
    bf16* stbf   = (bf16*)symaddr(g_states_bf);
    bf16* embbf  = (bf16*)symaddr(g_emb_bf);
    bf16* Ebf    = (bf16*)symaddr(g_E_bf);
    bf16* pcatbf = (bf16*)symaddr(g_pcat_bf);
    bf16* big1bf = (bf16*)symaddr(g_big1_bf);
    bf16* big2bf = (bf16*)symaddr(g_big2_bf);
    bf16* e0bf   = (bf16*)symaddr(g_e0_bf);
    bf16* stW0b  = (bf16*)symaddr(g_stW0b);
    bf16* stW1b  = (bf16*)symaddr(g_stW1b);
    bf16* stW2b  = (bf16*)symaddr(g_stW2b);
    bf16* epW0b  = (bf16*)symaddr(g_epW0b);
    bf16* epW1b  = (bf16*)symaddr(g_epW1b);
    bf16* epW2b  = (bf16*)symaddr(g_epW2b);
    bf16* rpW0b  = (bf16*)symaddr(g_rpW0b);
    bf16* rpW1b  = (bf16*)symaddr(g_rpW1b);
    bf16* WGh  = (bf16*)symaddr(g_WGh);   bf16* WGl  = (bf16*)symaddr(g_WGl);
    bf16* W0hh = (bf16*)symaddr(g_W0hh);  bf16* W0hl = (bf16*)symaddr(g_W0hl);
    bf16* W1h  = (bf16*)symaddr(g_W1h);   bf16* W1l  = (bf16*)symaddr(g_W1l);
    bf16* W2h  = (bf16*)symaddr(g_W2h);   bf16* W2l  = (bf16*)symaddr(g_W2l);
    bf16* cAH = (bf16*)symaddr(g_cAH);    bf16* cAL = (bf16*)symaddr(g_cAL);
    bf16* cBH = (bf16*)symaddr(g_cBH);    bf16* cBL = (bf16*)symaddr(g_cBL);
    bf16* zcH = (bf16*)symaddr(g_zcH);    bf16* zcL = (bf16*)symaddr(g_zcL);
    bf16* y1H = (bf16*)symaddr(g_y1H);    bf16* y1L = (bf16*)symaddr(g_y1L);
    bf16* y2H = (bf16*)symaddr(g_y2H);    bf16* y2L = (bf16*)symaddr(g_y2L);

    static bool attr_set = false;
    if (!attr_set) {
        cudaFuncSetAttribute(recur_k, cudaFuncAttributeMaxDynamicSharedMemorySize, 96 * 1024);
        attr_set = true;
    }

    // launch order chosen so recur_k is the 6th launch (ncu -s 5 -c 1 captures it)
    zero_acc_k<<<1, 32>>>(acc);                                           // 1
    cvt_bf_k<<<2048, 256>>>(emb, embbf, (long)TBD * EMBD);                // 2
    cvt_bf_k<<<512, 256>>>(st_W0, stW0b, 512L * 1536);                    // 3
    prep_all<<<1024, 256>>>(gru_Wih, gru_Whh, WGh, WGl,
                            st_W0, W0hh, W0hl, st_W1, W1h, W1l,
                            st_W2, st_b2, W2h, W2l, b2p);                 // 4
    mma_gemm<0, true, true, false, false><<<dim3(4, 128), 256>>>(         // 5: PE
        embbf, EMBD, stW0b + 512, 1536, st_b0, PE, nullptr, FEATD, EMBD, nullptr, nullptr);
    recur_k<<<NBLK, 256, 92160>>>(WGh, WGl, action, gru_Wih, gru_bih, gru_bhh,   // 6
                                  W0hh, W0hl, PE,
                                  W1h, W1l, st_b1, W2h, W2l, b2p,
                                  eps, qmu, qstd, stbf,
                                  cAH, cAL, cBH, cBL, zcH, zcL,
                                  y1H, y1L, y2H, y2L);

    // remaining weight conversions + e0 chain
    cvt_bf_k<<<256, 256>>>(ep_W0, epW0b, 512L * 576);
    cvt_bf_k<<<256, 256>>>(ep_W1, epW1b, 512L * 512);
    cvt_bf_k<<<512, 256>>>(ep_W2, epW2b, 1024L * 512);
    cvt_bf_k<<<256, 256>>>(rp_W0, rpW0b, 512L * 576);
    cvt_bf_k<<<256, 256>>>(rp_W1, rpW1b, 512L * 512);
    cvt_bf_k<<<256, 256>>>(st_W1, stW1b, 512L * 512);
    cvt_bf_k<<<64,  256>>>(st_W2, stW2b, 128L * 512);
    e0_l1<<<1, 256>>>(ep_b0, ep_W1, ep_b1, e0l1);
    e0_head<<<4, 256>>>(e0l1, ep_W2, ep_b2, e0);
    cvt_bf_k<<<4, 256>>>(e0, e0bf, EMBD);

    // shared ep-MLP: E = ep_mlp(states); head epilogue fuses emb loss (acc[1])
    mma_gemm<1, false, false, true, false><<<dim3(4, 128), 256>>>(
        stbf, STATED, epW0b, STATED, ep_b0, nullptr, big1bf, FEATD, STATED, nullptr, nullptr);
    mma_gemm<1, false, false, true, false><<<dim3(4, 128), 256>>>(
        big1bf, FEATD, epW1b, FEATD, ep_b1, nullptr, big2bf, FEATD, FEATD, nullptr, nullptr);
    mma_gemm<0, false, false, true, true><<<dim3(8, 128), 256>>>(
        big2bf, FEATD, epW2b, FEATD, ep_b2, nullptr, Ebf, EMBD, FEATD, emb, acc + 1);

    // prior path
    build_pcat<<<TBD, 256>>>(stbf, Ebf, e0bf, pcatbf);
    mma_gemm<1, false, false, true, false><<<dim3(4, 128), 256>>>(
        pcatbf, 1536, stW0b, 1536, st_b0, nullptr, big1bf, FEATD, 1536, nullptr, nullptr);
    mma_gemm<1, false, false, true, false><<<dim3(4, 128), 256>>>(
        big1bf, FEATD, stW1b, FEATD, st_b1, nullptr, big2bf, FEATD, FEATD, nullptr, nullptr);
    mma_gemm<0, false, true, false, false><<<dim3(1, 128), 256>>>(
        big2bf, FEATD, stW2b, FEATD, st_b2, praw, nullptr, 128, FEATD, nullptr, nullptr);
    kl_reduce_k<<<1024, 256>>>(praw, qmu, qstd, acc + 0);

    // reward loss
    mma_gemm<1, false, false, true, false><<<dim3(4, 128), 256>>>(
        stbf, STATED, rpW0b, STATED, rp_b0, nullptr, big1bf, FEATD, STATED, nullptr, nullptr);
    mma_gemm<1, false, false, true, false><<<dim3(4, 128), 256>>>(
        big1bf, FEATD, rpW1b, FEATD, rp_b1, nullptr, big2bf, FEATD, FEATD, nullptr, nullptr);
    reward_reduce_k<<<512, 256>>>(big2bf, rp_W2, rp_b2, reward, acc + 2);

    finalize_k<<<1, 1>>>(acc, (float*)d_out, out_size);
}

// round 12
// speedup vs baseline: 1.4733x; 1.0303x over previous
#include <cuda_runtime.h>
#include <cuda_bf16.h>
#include <math.h>

#define TT 64
#define BB 256
#define EMBD 1024
#define ADIM 6
#define STOCHD 64
#define HIDD 512
#define FEATD 512
#define STATED 576
#define TBD (TT*BB)
#define NBLK 128
#define LOG2PI_F 1.837877066409345483560659472811f
#define LOG2PI_D 1.837877066409345483560659472811

typedef __nv_bfloat16 bf16;

// ---------------- scratch ----------------
__device__ float g_qmu[TBD*STOCHD];
__device__ float g_qstd[TBD*STOCHD];
__device__ float g_PE[TBD*FEATD];
__device__ float g_e0[EMBD];
__device__ float g_e0l1[FEATD];
__device__ float g_b2p[128];
__device__ double g_acc[3];
// tree barrier state
__device__ unsigned g_leaf[8*32];
__device__ unsigned g_root2 = 0;
__device__ volatile unsigned g_rel = 0;

// hi/lo carry + intermediates (bf16 pairs)
__device__ bf16 g_cAH[BB*STATED];
__device__ bf16 g_cAL[BB*STATED];
__device__ bf16 g_cBH[BB*STATED];
__device__ bf16 g_cBL[BB*STATED];
__device__ bf16 g_zcH[BB*STATED];   // zero, never written
__device__ bf16 g_zcL[BB*STATED];   // zero, never written
__device__ bf16 g_y1H[BB*FEATD];
__device__ bf16 g_y1L[BB*FEATD];
__device__ bf16 g_y2H[BB*FEATD];
__device__ bf16 g_y2L[BB*FEATD];

__device__ bf16 g_states_bf[TBD*STATED];
__device__ bf16 g_emb_bf[TBD*EMBD];
__device__ bf16 g_E_bf[TBD*EMBD];
__device__ bf16 g_big1_bf[TBD*FEATD];
__device__ bf16 g_big2_bf[TBD*FEATD];
__device__ bf16 g_e0_bf[EMBD];
__device__ bf16 g_stW0b[512*1536];
__device__ bf16 g_epW0b[512*576];
__device__ bf16 g_epW1b[512*512];
__device__ bf16 g_epW2b[1024*512];
__device__ bf16 g_rpW0b[512*576];
__device__ bf16 g_rpW1b[512*512];
// split hi/lo weights for the sequential path
__device__ bf16 g_WGh[2048*576];
__device__ bf16 g_WGl[2048*576];
__device__ bf16 g_W0hh[512*512];
__device__ bf16 g_W0hl[512*512];
__device__ bf16 g_W1h[512*512];
__device__ bf16 g_W1l[512*512];
__device__ bf16 g_W2h[128*512];
__device__ bf16 g_W2l[128*512];

// ---------------- math ----------------
__device__ __forceinline__ float softplusf(float x) {
    return fmaxf(x, 0.f) + log1pf(expf(-fabsf(x)));
}
__device__ __forceinline__ float sigmoidf_(float x) { return 1.f / (1.f + expf(-x)); }
__device__ __forceinline__ float eluf(float x) { return x > 0.f ? x : expm1f(x); }
template<int ACT> __device__ __forceinline__ float actf(float v) {
    if (ACT == 1) return eluf(v);
    return v;
}

__device__ __forceinline__ void mma_bf16(float* c, const unsigned* a, const unsigned* b) {
    asm volatile(
        "mma.sync.aligned.m16n8k16.row.col.f32.bf16.bf16.f32 "
        "{%0,%1,%2,%3},{%4,%5,%6,%7},{%8,%9},{%0,%1,%2,%3};"
        : "+f"(c[0]), "+f"(c[1]), "+f"(c[2]), "+f"(c[3])
        : "r"(a[0]), "r"(a[1]), "r"(a[2]), "r"(a[3]), "r"(b[0]), "r"(b[1]));
}

__device__ __forceinline__ void splitw(float v, bf16& h, bf16& l) {
    h = __float2bfloat16(v);
    l = __float2bfloat16(v - __bfloat162float(h));
}

__device__ __forceinline__ unsigned s2u(const void* p) {
    return (unsigned)__cvta_generic_to_shared(p);
}
__device__ __forceinline__ void ldsm4(unsigned& r0, unsigned& r1, unsigned& r2, unsigned& r3,
                                      unsigned a) {
    asm volatile("ldmatrix.sync.aligned.m8n8.x4.shared.b16 {%0,%1,%2,%3}, [%4];"
                 : "=r"(r0), "=r"(r1), "=r"(r2), "=r"(r3) : "r"(a));
}

// ---------------- two-level tree grid barrier ----------------
__device__ __forceinline__ void gbar() {
    __syncthreads();
    if (threadIdx.x == 0) {
        unsigned gen = g_rel;
        __threadfence();
        int grp = (blockIdx.x >> 4) * 32;
        if (atomicAdd(&g_leaf[grp], 1u) == 15u) {
            if (atomicAdd(&g_root2, 1u) == 7u) {
#pragma unroll
                for (int i = 0; i < 8; i++) g_leaf[i * 32] = 0u;
                g_root2 = 0u;
                __threadfence();
                g_rel = gen + 1u;
            }
        }
        while (g_rel == gen) { __nanosleep(32); }
        __threadfence();
    }
    __syncthreads();
}

// ---------------- bf16 tensor-core GEMM (batched; ldmatrix fragments) ----------------
// RED: 0 none, 1 emb-SSE vs Ef, 2 KL vs (Ef=qmu, Qs=qstd). PCAT: A = [states | E-shifted/e0].
template<int ACT, bool ROWSHIFT, bool WF32, bool WBF, int RED, bool PCAT>
__global__ __launch_bounds__(256, 2) void mma_gemm(
    const bf16* __restrict__ A, int ldA,
    const bf16* __restrict__ W, int ldW,
    const float* __restrict__ bias,
    float* __restrict__ Cf, bf16* __restrict__ Cb, int ldC, int K,
    const float* __restrict__ Ef, const float* __restrict__ Qs, double* __restrict__ racc,
    const bf16* __restrict__ A2, const bf16* __restrict__ Ae0)
{
    __shared__ __align__(16) unsigned As[2][128 * 20];
    __shared__ __align__(16) unsigned Ws[2][128 * 20];
    __shared__ double redsm[256];
    int tid = threadIdx.x, lane = tid & 31, wid = tid >> 5;
    int g = lane >> 2, tg = lane & 3;
    int wr = wid >> 2, wc = wid & 3;
    int row0 = blockIdx.y * 128, col0 = blockIdx.x * 128;

    float acc[4][4][4];
#pragma unroll
    for (int mt = 0; mt < 4; mt++)
#pragma unroll
        for (int nt = 0; nt < 4; nt++)
#pragma unroll
            for (int q = 0; q < 4; q++) acc[mt][nt][q] = 0.f;

    int a_r = (lane & 7) + ((lane >> 3) & 1) * 8;
    int a_w = ((lane >> 4) & 1) * 4;
    int b_r = (lane & 7) + ((lane >> 4) & 1) * 8;
    int b_w = ((lane >> 3) & 1) * 4;

    const int nc = K / 32;
    uint4 pa[2], pb[2];

    auto loadA = [&](int grow, int k) -> uint4 {
        if (PCAT) {
            if (k < 512)
                return *reinterpret_cast<const uint4*>(A + (size_t)grow * STATED + k);
            if (grow < 256)
                return *reinterpret_cast<const uint4*>(Ae0 + (k - 512));
            return *reinterpret_cast<const uint4*>(A2 + (size_t)(grow - 256) * EMBD + (k - 512));
        } else {
            if (ROWSHIFT && grow >= 256) grow -= 256;
            return *reinterpret_cast<const uint4*>(A + (size_t)grow * ldA + k);
        }
    };

#pragma unroll
    for (int i = 0; i < 2; i++) {
        int u = tid + i * 256, row = u >> 2, q = u & 3;
        pa[i] = loadA(row0 + row, q * 8);
        pb[i] = *reinterpret_cast<const uint4*>(W + (size_t)(col0 + row) * ldW + q * 8);
    }
#pragma unroll
    for (int i = 0; i < 2; i++) {
        int u = tid + i * 256, row = u >> 2, q = u & 3;
        *reinterpret_cast<uint4*>(&As[0][row * 20 + q * 4]) = pa[i];
        *reinterpret_cast<uint4*>(&Ws[0][row * 20 + q * 4]) = pb[i];
    }
    __syncthreads();

    int buf = 0;
    for (int c = 0; c < nc; c++) {
        bool nxt = (c + 1 < nc);
        if (nxt) {
            int k0 = (c + 1) * 32;
#pragma unroll
            for (int i = 0; i < 2; i++) {
                int u = tid + i * 256, row = u >> 2, q = u & 3;
                pa[i] = loadA(row0 + row, k0 + q * 8);
                pb[i] = *reinterpret_cast<const uint4*>(W + (size_t)(col0 + row) * ldW + k0 + q * 8);
            }
        }
        unsigned asb = s2u(&As[buf][0]);
        unsigned wsb = s2u(&Ws[buf][0]);
#pragma unroll
        for (int ks = 0; ks < 2; ks++) {
            unsigned af[4][4], bfr[4][2];
#pragma unroll
            for (int mt = 0; mt < 4; mt++) {
                int row = wr * 64 + mt * 16 + a_r;
                ldsm4(af[mt][0], af[mt][1], af[mt][2], af[mt][3],
                      asb + (unsigned)((row * 20 + ks * 8 + a_w) * 4));
            }
#pragma unroll
            for (int np = 0; np < 2; np++) {
                int row = wc * 32 + np * 16 + b_r;
                ldsm4(bfr[np * 2][0], bfr[np * 2][1], bfr[np * 2 + 1][0], bfr[np * 2 + 1][1],
                      wsb + (unsigned)((row * 20 + ks * 8 + b_w) * 4));
            }
#pragma unroll
            for (int mt = 0; mt < 4; mt++)
#pragma unroll
                for (int nt = 0; nt < 4; nt++)
                    mma_bf16(acc[mt][nt], af[mt], bfr[nt]);
        }
        if (nxt) {
            int nb = buf ^ 1;
#pragma unroll
            for (int i = 0; i < 2; i++) {
                int u = tid + i * 256, row = u >> 2, q = u & 3;
                *reinterpret_cast<uint4*>(&As[nb][row * 20 + q * 4]) = pa[i];
                *reinterpret_cast<uint4*>(&Ws[nb][row * 20 + q * 4]) = pb[i];
            }
        }
        __syncthreads();
        buf ^= 1;
    }

    double rsum = 0.0;
#pragma unroll
    for (int mt = 0; mt < 4; mt++) {
        int r = row0 + wr * 64 + mt * 16 + g;
#pragma unroll
        for (int nt = 0; nt < 4; nt++) {
            int cc = col0 + wc * 32 + nt * 8 + tg * 2;
            float b0v = bias[cc], b1v = bias[cc + 1];
            float v00 = actf<ACT>(acc[mt][nt][0] + b0v);
            float v01 = actf<ACT>(acc[mt][nt][1] + b1v);
            float v10 = actf<ACT>(acc[mt][nt][2] + b0v);
            float v11 = actf<ACT>(acc[mt][nt][3] + b1v);
            if (WF32) {
                Cf[(size_t)r * ldC + cc]           = v00;
                Cf[(size_t)r * ldC + cc + 1]       = v01;
                Cf[(size_t)(r + 8) * ldC + cc]     = v10;
                Cf[(size_t)(r + 8) * ldC + cc + 1] = v11;
            }
            if (WBF) {
                Cb[(size_t)r * ldC + cc]           = __float2bfloat16(v00);
                Cb[(size_t)r * ldC + cc + 1]       = __float2bfloat16(v01);
                Cb[(size_t)(r + 8) * ldC + cc]     = __float2bfloat16(v10);
                Cb[(size_t)(r + 8) * ldC + cc + 1] = __float2bfloat16(v11);
            }
            if (RED == 1) {
                float d0 = Ef[(size_t)r * ldC + cc]           - v00;
                float d1 = Ef[(size_t)r * ldC + cc + 1]       - v01;
                float d2 = Ef[(size_t)(r + 8) * ldC + cc]     - v10;
                float d3 = Ef[(size_t)(r + 8) * ldC + cc + 1] - v11;
                rsum += (double)(0.5f * d0 * d0) + (double)(0.5f * d1 * d1)
                      + (double)(0.5f * d2 * d2) + (double)(0.5f * d3 * d3);
            }
            if (RED == 2) {
                // interleaved (mu_i, std_i): cc even, i = cc>>1
                int i0 = cc >> 1;
                {
                    float psd = softplusf(v01) + 1e-4f;
                    float qm = Ef[(size_t)r * 64 + i0], qs = Qs[(size_t)r * 64 + i0];
                    float d = qm - v00;
                    rsum += (double)(logf(psd / qs) + (qs * qs + d * d) / (2.f * psd * psd) - 0.5f);
                }
                {
                    float psd = softplusf(v11) + 1e-4f;
                    float qm = Ef[(size_t)(r + 8) * 64 + i0], qs = Qs[(size_t)(r + 8) * 64 + i0];
                    float d = qm - v10;
                    rsum += (double)(logf(psd / qs) + (qs * qs + d * d) / (2.f * psd * psd) - 0.5f);
                }
            }
        }
    }
    if (RED != 0) {
        redsm[tid] = rsum;
        __syncthreads();
        for (int o = 128; o > 0; o >>= 1) {
            if (tid < o) redsm[tid] += redsm[tid + o];
            __syncthreads();
        }
        if (tid == 0) atomicAdd(racc, redsm[0]);
    }
}

// ---------------- prep ----------------
__global__ void cvt_bf_k(const float* __restrict__ s, bf16* __restrict__ d, long n) {
    for (long i = blockIdx.x * (long)blockDim.x + threadIdx.x; i < n;
         i += (long)gridDim.x * blockDim.x)
        d[i] = __float2bfloat16(s[i]);
}

// fused conversion of the 5 head weights
__global__ void cvt_multi(const float* __restrict__ s0, bf16* __restrict__ d0, long n0,
                          const float* __restrict__ s1, bf16* __restrict__ d1, long n1,
                          const float* __restrict__ s2, bf16* __restrict__ d2, long n2,
                          const float* __restrict__ s3, bf16* __restrict__ d3, long n3,
                          const float* __restrict__ s4, bf16* __restrict__ d4, long n4)
{
    long t0 = n0, t1 = t0 + n1, t2 = t1 + n2, t3 = t2 + n3, total = t3 + n4;
    for (long idx = blockIdx.x * (long)blockDim.x + threadIdx.x; idx < total;
         idx += (long)gridDim.x * blockDim.x) {
        if (idx < t0)       d0[idx]      = __float2bfloat16(s0[idx]);
        else if (idx < t1)  d1[idx - t0] = __float2bfloat16(s1[idx - t0]);
        else if (idx < t2)  d2[idx - t1] = __float2bfloat16(s2[idx - t1]);
        else if (idx < t3)  d3[idx - t2] = __float2bfloat16(s3[idx - t2]);
        else                d4[idx - t3] = __float2bfloat16(s4[idx - t3]);
    }
}

// fused prep for everything recur_k needs: WG split, W0/W1 splits, W2p
__global__ void prep_all(const float* __restrict__ Wih, const float* __restrict__ Whh,
                         bf16* __restrict__ WGh, bf16* __restrict__ WGl,
                         const float* __restrict__ st_W0, bf16* __restrict__ W0hh, bf16* __restrict__ W0hl,
                         const float* __restrict__ st_W1, bf16* __restrict__ W1h, bf16* __restrict__ W1l,
                         const float* __restrict__ W2, const float* __restrict__ b2,
                         bf16* __restrict__ W2h, bf16* __restrict__ W2l, float* __restrict__ b2p)
{
    const long nWG = 2048L * 576;
    const long nW0 = 512L * 512;
    const long nW1 = 512L * 512;
    const long nW2 = 128L * 512;
    const long total = nWG + nW0 + nW1 + nW2;
    for (long idx = blockIdx.x * (long)blockDim.x + threadIdx.x; idx < total;
         idx += (long)gridDim.x * blockDim.x) {
        if (idx < nWG) {
            int c = (int)(idx / 576), k = (int)(idx % 576);
            int jb = c >> 7, gs = (c >> 5) & 3, jl = c & 31, j = jb * 32 + jl;
            float v = 0.f;
            if (gs == 0)      v = (k < 64) ? Wih[j * 70 + k] : Whh[(size_t)j * 512 + k - 64];
            else if (gs == 1) v = (k < 64) ? Wih[(512 + j) * 70 + k] : Whh[(size_t)(512 + j) * 512 + k - 64];
            else if (gs == 2) v = (k < 64) ? Wih[(1024 + j) * 70 + k] : 0.f;
            else              v = (k < 64) ? 0.f : Whh[(size_t)(1024 + j) * 512 + k - 64];
            bf16 h, l; splitw(v, h, l);
            WGh[idx] = h; WGl[idx] = l;
        } else if (idx < nWG + nW0) {
            long i2 = idx - nWG;
            int row = (int)(i2 / 512), k = (int)(i2 % 512);
            float v = st_W0[(size_t)row * 1536 + k];
            bf16 h, l; splitw(v, h, l);
            W0hh[i2] = h; W0hl[i2] = l;
        } else if (idx < nWG + nW0 + nW1) {
            long i2 = idx - nWG - nW0;
            float v = st_W1[i2];
            bf16 h, l; splitw(v, h, l);
            W1h[i2] = h; W1l[i2] = l;
        } else {
            long i2 = idx - nWG - nW0 - nW1;
            int c = (int)(i2 / 512), k = (int)(i2 % 512);
            int sr = (c & 1) ? (64 + (c >> 1)) : (c >> 1);
            float v = W2[(size_t)sr * 512 + k];
            bf16 h, l; splitw(v, h, l);
            W2h[i2] = h; W2l[i2] = l;
            if (k == 0) b2p[c] = b2[sr];
        }
    }
}

// ---------------- 16x64-tile split-bf16 MMA, K=512, k64 chunks, ldmatrix ----------------
__device__ __forceinline__ void gemm16v(
    const bf16* __restrict__ AH, const bf16* __restrict__ AL, int ldA,
    const bf16* __restrict__ WH, const bf16* __restrict__ WL,
    int r0, int c0, float* acc, unsigned* SM,
    int tid, int wid, int g, int tg)
{
    int lane = tid & 31;
    acc[0] = acc[1] = acc[2] = acc[3] = 0.f;
    int arow = (tid & 127) >> 3, aq = tid & 7;
    const bf16* Asrc = (tid < 128) ? AH : AL;
    int adst = (tid < 128) ? 0 : 576;
    int a_r = (lane & 7) + ((lane >> 3) & 1) * 8;
    int a_w = ((lane >> 4) & 1) * 4;
    int b_r = wid * 8 + (lane & 7);
    int b_w = ((lane >> 3) & 1) * 4;
    unsigned b_roff = (lane < 16) ? 1152u : 3456u;
    unsigned smb = s2u(SM);

    uint4 va, vw[2][2];
    va = *reinterpret_cast<const uint4*>(Asrc + (size_t)(r0 + arow) * ldA + aq * 8);
#pragma unroll
    for (int i = 0; i < 2; i++) {
        int u = tid + i * 256, wcol = u >> 3, wq = u & 7;
        vw[i][0] = *reinterpret_cast<const uint4*>(WH + (size_t)(c0 + wcol) * 512 + wq * 8);
        vw[i][1] = *reinterpret_cast<const uint4*>(WL + (size_t)(c0 + wcol) * 512 + wq * 8);
    }
    {
        unsigned* b0 = SM;
        *reinterpret_cast<uint4*>(&b0[adst + arow * 36 + aq * 4]) = va;
#pragma unroll
        for (int i = 0; i < 2; i++) {
            int u = tid + i * 256, wcol = u >> 3, wq = u & 7;
            *reinterpret_cast<uint4*>(&b0[1152 + wcol * 36 + wq * 4]) = vw[i][0];
            *reinterpret_cast<uint4*>(&b0[3456 + wcol * 36 + wq * 4]) = vw[i][1];
        }
    }
    __syncthreads();
    for (int c = 0; c < 8; c++) {
        unsigned sb = smb + (unsigned)((c & 1) * 5760 * 4);
        if (c < 7) {
            int k0 = (c + 1) * 64;
            va = *reinterpret_cast<const uint4*>(Asrc + (size_t)(r0 + arow) * ldA + k0 + aq * 8);
#pragma unroll
            for (int i = 0; i < 2; i++) {
                int u = tid + i * 256, wcol = u >> 3, wq = u & 7;
                vw[i][0] = *reinterpret_cast<const uint4*>(WH + (size_t)(c0 + wcol) * 512 + k0 + wq * 8);
                vw[i][1] = *reinterpret_cast<const uint4*>(WL + (size_t)(c0 + wcol) * 512 + k0 + wq * 8);
            }
        }
#pragma unroll
        for (int ks = 0; ks < 4; ks++) {
            unsigned aH[4], aL[4], bH[2], bL[2];
            ldsm4(aH[0], aH[1], aH[2], aH[3],
                  sb + (unsigned)((a_r * 36 + ks * 8 + a_w) * 4));
            ldsm4(aL[0], aL[1], aL[2], aL[3],
                  sb + (unsigned)((576 + a_r * 36 + ks * 8 + a_w) * 4));
            ldsm4(bH[0], bH[1], bL[0], bL[1],
                  sb + (unsigned)((b_roff + b_r * 36 + ks * 8 + b_w) * 4));
            mma_bf16(acc, aH, bH);
            mma_bf16(acc, aL, bH);
            mma_bf16(acc, aH, bL);
        }
        if (c < 7) {
            unsigned* nb = SM + ((c + 1) & 1) * 5760;
            *reinterpret_cast<uint4*>(&nb[adst + arow * 36 + aq * 4]) = va;
#pragma unroll
            for (int i = 0; i < 2; i++) {
                int u = tid + i * 256, wcol = u >> 3, wq = u & 7;
                *reinterpret_cast<uint4*>(&nb[1152 + wcol * 36 + wq * 4]) = vw[i][0];
                *reinterpret_cast<uint4*>(&nb[3456 + wcol * 36 + wq * 4]) = vw[i][1];
            }
        }
        __syncthreads();
    }
}

// ---------------- persistent sequential recurrence ----------------
extern __shared__ unsigned SMd[];

__global__ __launch_bounds__(256, 1) void recur_k(
    const bf16* __restrict__ WGh, const bf16* __restrict__ WGl,
    const float* __restrict__ action, const float* __restrict__ Wih,
    const float* __restrict__ bih, const float* __restrict__ bhh,
    const bf16* __restrict__ W0hh, const bf16* __restrict__ W0hl, const float* __restrict__ PE,
    const bf16* __restrict__ W1h, const bf16* __restrict__ W1l, const float* __restrict__ b1,
    const bf16* __restrict__ W2h, const bf16* __restrict__ W2l, const float* __restrict__ b2p,
    const float* __restrict__ eps, float* __restrict__ qmu, float* __restrict__ qstd,
    bf16* __restrict__ stbf,
    bf16* __restrict__ cAH, bf16* __restrict__ cAL,
    bf16* __restrict__ cBH, bf16* __restrict__ cBL,
    const bf16* __restrict__ zcH, const bf16* __restrict__ zcL,
    bf16* __restrict__ y1H, bf16* __restrict__ y1L,
    bf16* __restrict__ y2H, bf16* __restrict__ y2L)
{
    unsigned* SM = SMd;
    int b = blockIdx.x, tid = threadIdx.x, lane = tid & 31, wid = tid >> 5;
    int g = lane >> 2, tg = lane & 3;
    unsigned smb = s2u(SM);

    for (int t = 0; t < TT; t++) {
        const bf16* cinH = (t == 0) ? zcH : ((t & 1) ? cBH : cAH);
        const bf16* cinL = (t == 0) ? zcL : ((t & 1) ? cBL : cAL);
        bf16* coutH = ((t + 1) & 1) ? cBH : cAH;
        bf16* coutL = ((t + 1) & 1) ? cBL : cAL;
        bf16* st_t = stbf + (size_t)t * BB * STATED;
        const float* a_t = action + (size_t)t * BB * ADIM;
        const float* PE_t = PE + (size_t)t * BB * FEATD;
        const float* eps_t = eps + (size_t)t * BB * STOCHD;

        // ===== GRU: [256 x 2048], K=576, 9 chunks of k64, tile 32x128 =====
        {
            int bx = b & 15, by = b >> 4;
            int r0 = by * 32, c0 = bx * 128;
            int wr = wid >> 2, wc = wid & 3;
            int a_r = wr * 16 + (lane & 7) + ((lane >> 3) & 1) * 8;
            int a_w = ((lane >> 4) & 1) * 4;
            int b_rb = (lane & 7) + ((lane >> 4) & 1) * 8;
            int b_w = ((lane >> 3) & 1) * 4;
            float acc[4][4];
#pragma unroll
            for (int nt = 0; nt < 4; nt++)
#pragma unroll
                for (int q = 0; q < 4; q++) acc[nt][q] = 0.f;

            int arow = tid >> 3, aq = tid & 7;
            uint4 vah, valo, vwh[4], vwl[4];
            vah  = *reinterpret_cast<const uint4*>(cinH + (size_t)(r0 + arow) * STATED + aq * 8);
            valo = *reinterpret_cast<const uint4*>(cinL + (size_t)(r0 + arow) * STATED + aq * 8);
#pragma unroll
            for (int i = 0; i < 4; i++) {
                int u = tid + i * 256, wcol = u >> 3, wq = u & 7;
                vwh[i] = *reinterpret_cast<const uint4*>(WGh + (size_t)(c0 + wcol) * 576 + wq * 8);
                vwl[i] = *reinterpret_cast<const uint4*>(WGl + (size_t)(c0 + wcol) * 576 + wq * 8);
            }
            {
                unsigned* b0 = SM;
                *reinterpret_cast<uint4*>(&b0[arow * 36 + aq * 4]) = vah;
                *reinterpret_cast<uint4*>(&b0[1152 + arow * 36 + aq * 4]) = valo;
#pragma unroll
                for (int i = 0; i < 4; i++) {
                    int u = tid + i * 256, wcol = u >> 3, wq = u & 7;
                    *reinterpret_cast<uint4*>(&b0[2304 + wcol * 36 + wq * 4]) = vwh[i];
                    *reinterpret_cast<uint4*>(&b0[6912 + wcol * 36 + wq * 4]) = vwl[i];
                }
            }
            __syncthreads();
            for (int c = 0; c < 9; c++) {
                unsigned sb = smb + (unsigned)((c & 1) * 11520 * 4);
                if (c < 8) {
                    int k0 = (c + 1) * 64;
                    vah  = *reinterpret_cast<const uint4*>(cinH + (size_t)(r0 + arow) * STATED + k0 + aq * 8);
                    valo = *reinterpret_cast<const uint4*>(cinL + (size_t)(r0 + arow) * STATED + k0 + aq * 8);
#pragma unroll
                    for (int i = 0; i < 4; i++) {
                        int u = tid + i * 256, wcol = u >> 3, wq = u & 7;
                        vwh[i] = *reinterpret_cast<const uint4*>(WGh + (size_t)(c0 + wcol) * 576 + k0 + wq * 8);
                        vwl[i] = *reinterpret_cast<const uint4*>(WGl + (size_t)(c0 + wcol) * 576 + k0 + wq * 8);
                    }
                }
#pragma unroll
                for (int ks = 0; ks < 4; ks++) {
                    unsigned aH[4], aL[4], bH[4][2], bL[4][2];
                    ldsm4(aH[0], aH[1], aH[2], aH[3],
                          sb + (unsigned)((a_r * 36 + ks * 8 + a_w) * 4));
                    ldsm4(aL[0], aL[1], aL[2], aL[3],
                          sb + (unsigned)((1152 + a_r * 36 + ks * 8 + a_w) * 4));
#pragma unroll
                    for (int np = 0; np < 2; np++) {
                        int row = wc * 32 + np * 16 + b_rb;
                        ldsm4(bH[np * 2][0], bH[np * 2][1], bH[np * 2 + 1][0], bH[np * 2 + 1][1],
                              sb + (unsigned)((2304 + row * 36 + ks * 8 + b_w) * 4));
                        ldsm4(bL[np * 2][0], bL[np * 2][1], bL[np * 2 + 1][0], bL[np * 2 + 1][1],
                              sb + (unsigned)((6912 + row * 36 + ks * 8 + b_w) * 4));
                    }
#pragma unroll
                    for (int nt = 0; nt < 4; nt++) {
                        mma_bf16(acc[nt], aH, bH[nt]);
                        mma_bf16(acc[nt], aL, bH[nt]);
                        mma_bf16(acc[nt], aH, bL[nt]);
                    }
                }
                if (c < 8) {
                    unsigned* nb = SM + ((c + 1) & 1) * 11520;
                    *reinterpret_cast<uint4*>(&nb[arow * 36 + aq * 4]) = vah;
                    *reinterpret_cast<uint4*>(&nb[1152 + arow * 36 + aq * 4]) = valo;
#pragma unroll
                    for (int i = 0; i < 4; i++) {
                        int u = tid + i * 256, wcol = u >> 3, wq = u & 7;
                        *reinterpret_cast<uint4*>(&nb[2304 + wcol * 36 + wq * 4]) = vwh[i];
                        *reinterpret_cast<uint4*>(&nb[6912 + wcol * 36 + wq * 4]) = vwl[i];
                    }
                }
                __syncthreads();
            }
            float* Cst = (float*)SM;
            int wr2 = wid >> 2, wc2 = wid & 3;
#pragma unroll
            for (int nt = 0; nt < 4; nt++) {
                int cc = wc2 * 32 + nt * 8 + tg * 2;
                int rr = wr2 * 16 + g;
                Cst[rr * 132 + cc]           = acc[nt][0];
                Cst[rr * 132 + cc + 1]       = acc[nt][1];
                Cst[(rr + 8) * 132 + cc]     = acc[nt][2];
                Cst[(rr + 8) * 132 + cc + 1] = acc[nt][3];
            }
            __syncthreads();
#pragma unroll
            for (int i = 0; i < 4; i++) {
                int o = tid + i * 256;
                int row = o >> 5, jl = o & 31;
                int gr = r0 + row, j = bx * 32 + jl;
                float rv = Cst[row * 132 + jl];
                float zv = Cst[row * 132 + 32 + jl];
                float nsv = Cst[row * 132 + 64 + jl];
                float nhv = Cst[row * 132 + 96 + jl];
                float a0 = a_t[gr * ADIM], a1 = a_t[gr * ADIM + 1], a2 = a_t[gr * ADIM + 2];
                float a3 = a_t[gr * ADIM + 3], a4 = a_t[gr * ADIM + 4], a5 = a_t[gr * ADIM + 5];
                const float* wr0 = Wih + (size_t)j * 70 + 64;
                float pr = bih[j];
                pr = fmaf(a0, wr0[0], pr); pr = fmaf(a1, wr0[1], pr); pr = fmaf(a2, wr0[2], pr);
                pr = fmaf(a3, wr0[3], pr); pr = fmaf(a4, wr0[4], pr); pr = fmaf(a5, wr0[5], pr);
                pr += bhh[j];
                const float* wz0 = Wih + (size_t)(512 + j) * 70 + 64;
                float pz = bih[512 + j];
                pz = fmaf(a0, wz0[0], pz); pz = fmaf(a1, wz0[1], pz); pz = fmaf(a2, wz0[2], pz);
                pz = fmaf(a3, wz0[3], pz); pz = fmaf(a4, wz0[4], pz); pz = fmaf(a5, wz0[5], pz);
                pz += bhh[512 + j];
                const float* wn0 = Wih + (size_t)(1024 + j) * 70 + 64;
                float pn = bih[1024 + j];
                pn = fmaf(a0, wn0[0], pn); pn = fmaf(a1, wn0[1], pn); pn = fmaf(a2, wn0[2], pn);
                pn = fmaf(a3, wn0[3], pn); pn = fmaf(a4, wn0[4], pn); pn = fmaf(a5, wn0[5], pn);
                float rr_ = sigmoidf_(rv + pr);
                float zz = sigmoidf_(zv + pz);
                float nn = tanhf(nsv + pn + rr_ * (nhv + bhh[1024 + j]));
                float hp = __bfloat162float(cinH[(size_t)gr * STATED + 64 + j])
                         + __bfloat162float(cinL[(size_t)gr * STATED + 64 + j]);
                float h = (1.f - zz) * nn + zz * hp;
                bf16 hh, hl; splitw(h, hh, hl);
                coutH[(size_t)gr * STATED + 64 + j] = hh;
                coutL[(size_t)gr * STATED + 64 + j] = hl;
                st_t[(size_t)gr * STATED + j] = __float2bfloat16(h);
            }
        }
        gbar();

        // ===== L0 =====
        {
            int by = b >> 3, bx = b & 7;
            int r0 = by * 16, c0 = bx * 64;
            float acc[4];
            gemm16v(coutH + 64, coutL + 64, STATED, W0hh, W0hl, r0, c0, acc, SM, tid, wid, g, tg);
            int cc = c0 + wid * 8 + tg * 2;
#pragma unroll
            for (int rr = 0; rr < 2; rr++) {
                int gr = r0 + g + rr * 8;
#pragma unroll
                for (int q = 0; q < 2; q++) {
                    float v = eluf(acc[rr * 2 + q] + PE_t[(size_t)gr * 512 + cc + q]);
                    bf16 vh, vl; splitw(v, vh, vl);
                    y1H[(size_t)gr * 512 + cc + q] = vh;
                    y1L[(size_t)gr * 512 + cc + q] = vl;
                }
            }
        }
        gbar();

        // ===== L1 =====
        {
            int by = b >> 3, bx = b & 7;
            int r0 = by * 16, c0 = bx * 64;
            float acc[4];
            gemm16v(y1H, y1L, 512, W1h, W1l, r0, c0, acc, SM, tid, wid, g, tg);
            int cc = c0 + wid * 8 + tg * 2;
#pragma unroll
            for (int rr = 0; rr < 2; rr++) {
                int gr = r0 + g + rr * 8;
#pragma unroll
                for (int q = 0; q < 2; q++) {
                    float v = eluf(acc[rr * 2 + q] + b1[cc + q]);
                    bf16 vh, vl; splitw(v, vh, vl);
                    y2H[(size_t)gr * 512 + cc + q] = vh;
                    y2L[(size_t)gr * 512 + cc + q] = vl;
                }
            }
        }
        gbar();

        // ===== L2 + sample =====
        if (b < 32) {
            int by = b >> 1, bx = b & 1;
            int r0 = by * 16, c0 = bx * 64;
            float acc[4];
            gemm16v(y2H, y2L, 512, W2h, W2l, r0, c0, acc, SM, tid, wid, g, tg);
            int cc = c0 + wid * 8 + tg * 2;
            int i_ = cc >> 1;
#pragma unroll
            for (int rr = 0; rr < 2; rr++) {
                int gr = r0 + g + rr * 8;
                float mu = acc[rr * 2] + b2p[cc];
                float sd = softplusf(acc[rr * 2 + 1] + b2p[cc + 1]) + 1e-4f;
                float s = fmaf(sd, eps_t[(size_t)gr * 64 + i_], mu);
                qmu[(size_t)(t * BB + gr) * 64 + i_] = mu;
                qstd[(size_t)(t * BB + gr) * 64 + i_] = sd;
                bf16 sh, sl; splitw(s, sh, sl);
                coutH[(size_t)gr * STATED + i_] = sh;
                coutL[(size_t)gr * STATED + i_] = sl;
                st_t[(size_t)gr * STATED + 512 + i_] = __float2bfloat16(s);
            }
        }
        gbar();
    }
}

// ---------------- misc ----------------
__global__ void e0_l1(const float* __restrict__ ep_b0, const float* __restrict__ ep_W1,
                      const float* __restrict__ ep_b1, float* __restrict__ l1)
{
    __shared__ float x0[512];
    for (int k = threadIdx.x; k < 512; k += 256) x0[k] = eluf(ep_b0[k]);
    __syncthreads();
    for (int o = threadIdx.x; o < 512; o += 256) {
        float v = ep_b1[o];
        for (int k = 0; k < 512; k++) v = fmaf(x0[k], ep_W1[(size_t)o * 512 + k], v);
        l1[o] = eluf(v);
    }
}

__global__ void e0_head(const float* __restrict__ l1, const float* __restrict__ ep_W2,
                        const float* __restrict__ ep_b2, float* __restrict__ e0)
{
    int o = blockIdx.x * 256 + threadIdx.x;
    float v = ep_b2[o];
    for (int k = 0; k < 512; k++) v = fmaf(l1[k], ep_W2[(size_t)o * 512 + k], v);
    e0[o] = v;
}

// ---------------- reductions ----------------
__global__ void zero_acc_k(double* acc) {
    if (threadIdx.x < 3) acc[threadIdx.x] = 0.0;
    if (threadIdx.x < 8) g_leaf[threadIdx.x * 32] = 0u;
    if (threadIdx.x == 0) { g_root2 = 0u; g_rel = 0u; }
}

__global__ void reward_reduce_k(const bf16* __restrict__ big2, const float* __restrict__ W,
                                const float* __restrict__ bias, const float* __restrict__ reward,
                                double* __restrict__ acc)
{
    __shared__ double sh[8];
    int lane = threadIdx.x & 31, wib = threadIdx.x >> 5;
    int gwarp = (blockIdx.x * blockDim.x + threadIdx.x) >> 5;
    int nwarps = (gridDim.x * blockDim.x) >> 5;
    double local = 0.0;
    for (int r = gwarp; r < TBD; r += nwarps) {
        float sum = 0.f;
        const bf16* row = big2 + (size_t)r * FEATD;
        for (int k = lane; k < FEATD; k += 32)
            sum = fmaf(__bfloat162float(row[k]), W[k], sum);
#pragma unroll
        for (int o = 16; o > 0; o >>= 1) sum += __shfl_xor_sync(0xffffffffu, sum, o);
        if (lane == 0) {
            float d = reward[r] - (sum + bias[0]);
            local += (double)(0.5f * d * d + 0.5f * LOG2PI_F);
        }
    }
    if (lane == 0) sh[wib] = local;
    __syncthreads();
    if (threadIdx.x == 0) {
        double t = 0.0;
        for (int i = 0; i < 8; i++) t += sh[i];
        atomicAdd(acc, t);
    }
}

__global__ void finalize_k(const double* __restrict__ acc, float* __restrict__ out, int n) {
    double inv = 1.0 / (double)(TT * BB);
    double loss = (acc[0] + acc[1] + acc[2]) * inv + (double)EMBD * 0.5 * LOG2PI_D;
    float lf = (float)loss;
    for (int i = 0; i < n; i++) out[i] = lf;
}

// ---------------- host ----------------
static void* symaddr(const void* sym) {
    void* p = nullptr;
    cudaGetSymbolAddress(&p, sym);
    return p;
}

extern "C" void kernel_launch(void* const* d_in, const int* in_sizes, int n_in,
                              void* d_out, int out_size)
{
    const float* emb     = (const float*)d_in[0];
    const float* action  = (const float*)d_in[1];
    const float* reward  = (const float*)d_in[2];
    const float* eps     = (const float*)d_in[3];
    const float* gru_Wih = (const float*)d_in[4];
    const float* gru_bih = (const float*)d_in[5];
    const float* gru_Whh = (const float*)d_in[6];
    const float* gru_bhh = (const float*)d_in[7];
    const float* st_W0 = (const float*)d_in[8];  const float* st_b0 = (const float*)d_in[9];
    const float* st_W1 = (const float*)d_in[10]; const float* st_b1 = (const float*)d_in[11];
    const float* st_W2 = (const float*)d_in[12]; const float* st_b2 = (const float*)d_in[13];
    const float* ep_W0 = (const float*)d_in[14]; const float* ep_b0 = (const float*)d_in[15];
    const float* ep_W1 = (const float*)d_in[16]; const float* ep_b1 = (const float*)d_in[17];
    const float* ep_W2 = (const float*)d_in[18]; const float* ep_b2 = (const float*)d_in[19];
    const float* rp_W0 = (const float*)d_in[20]; const float* rp_b0 = (const float*)d_in[21];
    const float* rp_W1 = (const float*)d_in[22]; const float* rp_b1 = (const float*)d_in[23];
    const float* rp_W2 = (const float*)d_in[24]; const float* rp_b2 = (const float*)d_in[25];

    float* qmu    = (float*)symaddr(g_qmu);
    float* qstd   = (float*)symaddr(g_qstd);
    float* PE     = (float*)symaddr(g_PE);
    float* e0     = (float*)symaddr(g_e0);
    float* e0l1   = (float*)symaddr(g_e0l1);
    float* b2p    = (float*)symaddr(g_b2p);
    double* acc   = (double*)symaddr(g_acc);
    bf16* stbf   = (bf16*)symaddr(g_states_bf);
    bf16* embbf  = (bf16*)symaddr(g_emb_bf);
    bf16* Ebf    = (bf16*)symaddr(g_E_bf);
    bf16* big1bf = (bf16*)symaddr(g_big1_bf);
    bf16* big2bf = (bf16*)symaddr(g_big2_bf);
    bf16* e0bf   = (bf16*)symaddr(g_e0_bf);
    bf16* stW0b  = (bf16*)symaddr(g_stW0b);
    bf16* epW0b  = (bf16*)symaddr(g_epW0b);
    bf16* epW1b  = (bf16*)symaddr(g_epW1b);
    bf16* epW2b  = (bf16*)symaddr(g_epW2b);
    bf16* rpW0b  = (bf16*)symaddr(g_rpW0b);
    bf16* rpW1b  = (bf16*)symaddr(g_rpW1b);
    bf16* WGh  = (bf16*)symaddr(g_WGh);   bf16* WGl  = (bf16*)symaddr(g_WGl);
    bf16* W0hh = (bf16*)symaddr(g_W0hh);  bf16* W0hl = (bf16*)symaddr(g_W0hl);
    bf16* W1h  = (bf16*)symaddr(g_W1h);   bf16* W1l  = (bf16*)symaddr(g_W1l);
    bf16* W2h  = (bf16*)symaddr(g_W2h);   bf16* W2l  = (bf16*)symaddr(g_W2l);
    bf16* cAH = (bf16*)symaddr(g_cAH);    bf16* cAL = (bf16*)symaddr(g_cAL);
    bf16* cBH = (bf16*)symaddr(g_cBH);    bf16* cBL = (bf16*)symaddr(g_cBL);
    bf16* zcH = (bf16*)symaddr(g_zcH);    bf16* zcL = (bf16*)symaddr(g_zcL);
    bf16* y1H = (bf16*)symaddr(g_y1H);    bf16* y1L = (bf16*)symaddr(g_y1L);
    bf16* y2H = (bf16*)symaddr(g_y2H);    bf16* y2L = (bf16*)symaddr(g_y2L);

    static bool attr_set = false;
    if (!attr_set) {
        cudaFuncSetAttribute(recur_k, cudaFuncAttributeMaxDynamicSharedMemorySize, 96 * 1024);
        attr_set = true;
    }

    // launch order: recur_k is the 6th launch
    zero_acc_k<<<1, 32>>>(acc);                                           // 1
    cvt_bf_k<<<2048, 256>>>(emb, embbf, (long)TBD * EMBD);                // 2
    cvt_bf_k<<<512, 256>>>(st_W0, stW0b, 512L * 1536);                    // 3
    prep_all<<<1024, 256>>>(gru_Wih, gru_Whh, WGh, WGl,
                            st_W0, W0hh, W0hl, st_W1, W1h, W1l,
                            st_W2, st_b2, W2h, W2l, b2p);                 // 4
    mma_gemm<0, true, true, false, 0, false><<<dim3(4, 128), 256>>>(      // 5: PE
        embbf, EMBD, stW0b + 512, 1536, st_b0, PE, nullptr, FEATD, EMBD,
        nullptr, nullptr, nullptr, nullptr, nullptr);
    recur_k<<<NBLK, 256, 92160>>>(WGh, WGl, action, gru_Wih, gru_bih, gru_bhh,   // 6
                                  W0hh, W0hl, PE,
                                  W1h, W1l, st_b1, W2h, W2l, b2p,
                                  eps, qmu, qstd, stbf,
                                  cAH, cAL, cBH, cBL, zcH, zcL,
                                  y1H, y1L, y2H, y2L);

    // remaining head-weight conversions (one launch) + e0 chain
    cvt_multi<<<512, 256>>>(ep_W0, epW0b, 512L * 576,
                            ep_W1, epW1b, 512L * 512,
                            ep_W2, epW2b, 1024L * 512,
                            rp_W0, rpW0b, 512L * 576,
                            rp_W1, rpW1b, 512L * 512);
    e0_l1<<<1, 256>>>(ep_b0, ep_W1, ep_b1, e0l1);
    e0_head<<<4, 256>>>(e0l1, ep_W2, ep_b2, e0);
    cvt_bf_k<<<4, 256>>>(e0, e0bf, EMBD);

    // shared ep-MLP: E = ep_mlp(states); head epilogue fuses emb loss (acc[1])
    mma_gemm<1, false, false, true, 0, false><<<dim3(4, 128), 256>>>(
        stbf, STATED, epW0b, STATED, ep_b0, nullptr, big1bf, FEATD, STATED,
        nullptr, nullptr, nullptr, nullptr, nullptr);
    mma_gemm<1, false, false, true, 0, false><<<dim3(4, 128), 256>>>(
        big1bf, FEATD, epW1b, FEATD, ep_b1, nullptr, big2bf, FEATD, FEATD,
        nullptr, nullptr, nullptr, nullptr, nullptr);
    mma_gemm<0, false, false, true, 1, false><<<dim3(8, 128), 256>>>(
        big2bf, FEATD, epW2b, FEATD, ep_b2, nullptr, Ebf, EMBD, FEATD,
        emb, nullptr, acc + 1, nullptr, nullptr);

    // prior path: L0 reads [states | E-shifted/e0] directly (no pcat materialization)
    mma_gemm<1, false, false, true, 0, true><<<dim3(4, 128), 256>>>(
        stbf, 1536, stW0b, 1536, st_b0, nullptr, big1bf, FEATD, 1536,
        nullptr, nullptr, nullptr, Ebf, e0bf);
    mma_gemm<1, false, false, true, 0, false><<<dim3(4, 128), 256>>>(
        big1bf, FEATD, W1h, FEATD, st_b1, nullptr, big2bf, FEATD, FEATD,
        nullptr, nullptr, nullptr, nullptr, nullptr);
    // prior L2: interleaved W2h/b2p, KL fused into epilogue (acc[0])
    mma_gemm<0, false, false, false, 2, false><<<dim3(1, 128), 256>>>(
        big2bf, FEATD, W2h, FEATD, b2p, nullptr, nullptr, 128, FEATD,
        qmu, qstd, acc + 0, nullptr, nullptr);

    // reward loss
    mma_gemm<1, false, false, true, 0, false><<<dim3(4, 128), 256>>>(
        stbf, STATED, rpW0b, STATED, rp_b0, nullptr, big1bf, FEATD, STATED,
        nullptr, nullptr, nullptr, nullptr, nullptr);
    mma_gemm<1, false, false, true, 0, false><<<dim3(4, 128), 256>>>(
        big1bf, FEATD, rpW1b, FEATD, rp_b1, nullptr, big2bf, FEATD, FEATD,
        nullptr, nullptr, nullptr, nullptr, nullptr);
    reward_reduce_k<<<512, 256>>>(big2bf, rp_W2, rp_b2, reward, acc + 2);

    finalize_k<<<1, 1>>>(acc, (float*)d_out, out_size);
}